// round 1
// baseline (speedup 1.0000x reference)
#include <cuda_runtime.h>
#include <cstdint>
#include <cstddef>

// Problem dims
#define DIMV   1024
#define HIDV   4096
#define SEQ    2048
#define NHEAD  16
#define HDIMV  64
#define NTOK   8192          // B * S

// ---------------- static scratch (no allocation allowed) ----------------
__device__ float g_h  [(size_t)NTOK * DIMV];   // ln1(x)
__device__ float g_q  [(size_t)NTOK * DIMV];
__device__ float g_kk [(size_t)NTOK * DIMV];
__device__ float g_v  [(size_t)NTOK * DIMV];
__device__ float g_o  [(size_t)NTOK * DIMV];   // attention out, concat-head layout
__device__ float g_x2 [(size_t)NTOK * DIMV];   // x + attn
__device__ float g_h2 [(size_t)NTOK * DIMV];   // double-LN out
__device__ float g_mid[(size_t)NTOK * HIDV];   // MLP hidden
__device__ float g_wp [(size_t)3 * DIMV * DIMV]; // repacked Wq/Wk/Wv

__device__ __forceinline__ float gelu_exact(float x) {
    return 0.5f * x * (1.0f + erff(x * 0.70710678118654752f));
}

// ---------------- repack [NH,D,HD] -> [D, NH*HD] ----------------
__global__ void repack_w_kernel(const float* __restrict__ Wq, const float* __restrict__ Wk,
                                const float* __restrict__ Wv, float* __restrict__ Wp)
{
    int w = blockIdx.y;
    const float* src = (w == 0) ? Wq : (w == 1) ? Wk : Wv;
    int idx = blockIdx.x * 256 + threadIdx.x;       // 0 .. D*D-1
    int d = idx >> 10;
    int c = idx & 1023;
    int h = c >> 6;
    int k = c & 63;
    Wp[(size_t)w * DIMV * DIMV + idx] = src[(size_t)h * DIMV * HDIMV + (size_t)d * HDIMV + k];
}

// ---------------- LayerNorm over rows of 1024 ----------------
__global__ void ln_kernel(const float* __restrict__ x, const float* __restrict__ g,
                          const float* __restrict__ b, float* __restrict__ y)
{
    __shared__ float s_a[8], s_b[8];
    __shared__ float s_mu, s_rs;
    size_t row = blockIdx.x;
    int tid = threadIdx.x;
    float4 v = ((const float4*)(x + row * DIMV))[tid];
    float sum = v.x + v.y + v.z + v.w;
    float sq  = v.x*v.x + v.y*v.y + v.z*v.z + v.w*v.w;
    #pragma unroll
    for (int o = 16; o; o >>= 1) {
        sum += __shfl_xor_sync(0xffffffffu, sum, o);
        sq  += __shfl_xor_sync(0xffffffffu, sq,  o);
    }
    if ((tid & 31) == 0) { s_a[tid >> 5] = sum; s_b[tid >> 5] = sq; }
    __syncthreads();
    if (tid == 0) {
        float ts = 0.f, tq = 0.f;
        #pragma unroll
        for (int i = 0; i < 8; i++) { ts += s_a[i]; tq += s_b[i]; }
        float mu  = ts * (1.0f / DIMV);
        float var = tq * (1.0f / DIMV) - mu * mu;
        s_mu = mu;
        s_rs = rsqrtf(var + 1e-5f);
    }
    __syncthreads();
    float mu = s_mu, rs = s_rs;
    float4 gv = ((const float4*)g)[tid];
    float4 bv = ((const float4*)b)[tid];
    float4 o;
    o.x = (v.x - mu) * rs * gv.x + bv.x;
    o.y = (v.y - mu) * rs * gv.y + bv.y;
    o.z = (v.z - mu) * rs * gv.z + bv.z;
    o.w = (v.w - mu) * rs * gv.w + bv.w;
    ((float4*)(y + row * DIMV))[tid] = o;
}

// ---------------- residual add + LN(ln2) + LN(fcln) fused ----------------
__global__ void add_dln_kernel(const float* __restrict__ x, const float* __restrict__ oatt,
                               const float* __restrict__ g2, const float* __restrict__ b2,
                               const float* __restrict__ gf, const float* __restrict__ bf,
                               float* __restrict__ x2, float* __restrict__ h2)
{
    __shared__ float s_a[8], s_b[8];
    __shared__ float s_mu, s_rs;
    size_t row = blockIdx.x;
    int tid = threadIdx.x;
    float4 v  = ((const float4*)(x    + row * DIMV))[tid];
    float4 ov = ((const float4*)(oatt + row * DIMV))[tid];
    v.x += ov.x; v.y += ov.y; v.z += ov.z; v.w += ov.w;
    ((float4*)(x2 + row * DIMV))[tid] = v;

    // LN pass 1
    float sum = v.x + v.y + v.z + v.w;
    float sq  = v.x*v.x + v.y*v.y + v.z*v.z + v.w*v.w;
    #pragma unroll
    for (int o = 16; o; o >>= 1) {
        sum += __shfl_xor_sync(0xffffffffu, sum, o);
        sq  += __shfl_xor_sync(0xffffffffu, sq,  o);
    }
    if ((tid & 31) == 0) { s_a[tid >> 5] = sum; s_b[tid >> 5] = sq; }
    __syncthreads();
    if (tid == 0) {
        float ts = 0.f, tq = 0.f;
        #pragma unroll
        for (int i = 0; i < 8; i++) { ts += s_a[i]; tq += s_b[i]; }
        float mu  = ts * (1.0f / DIMV);
        float var = tq * (1.0f / DIMV) - mu * mu;
        s_mu = mu;
        s_rs = rsqrtf(var + 1e-5f);
    }
    __syncthreads();
    float mu1 = s_mu, rs1 = s_rs;
    float4 g2v = ((const float4*)g2)[tid];
    float4 b2v = ((const float4*)b2)[tid];
    float4 t;
    t.x = (v.x - mu1) * rs1 * g2v.x + b2v.x;
    t.y = (v.y - mu1) * rs1 * g2v.y + b2v.y;
    t.z = (v.z - mu1) * rs1 * g2v.z + b2v.z;
    t.w = (v.w - mu1) * rs1 * g2v.w + b2v.w;

    // LN pass 2
    float sum2 = t.x + t.y + t.z + t.w;
    float sq2  = t.x*t.x + t.y*t.y + t.z*t.z + t.w*t.w;
    #pragma unroll
    for (int o = 16; o; o >>= 1) {
        sum2 += __shfl_xor_sync(0xffffffffu, sum2, o);
        sq2  += __shfl_xor_sync(0xffffffffu, sq2,  o);
    }
    if ((tid & 31) == 0) { s_a[tid >> 5] = sum2; s_b[tid >> 5] = sq2; }
    __syncthreads();
    if (tid == 0) {
        float ts = 0.f, tq = 0.f;
        #pragma unroll
        for (int i = 0; i < 8; i++) { ts += s_a[i]; tq += s_b[i]; }
        float mu  = ts * (1.0f / DIMV);
        float var = tq * (1.0f / DIMV) - mu * mu;
        s_mu = mu;
        s_rs = rsqrtf(var + 1e-5f);
    }
    __syncthreads();
    float mu2 = s_mu, rs2 = s_rs;
    float4 gfv = ((const float4*)gf)[tid];
    float4 bfv = ((const float4*)bf)[tid];
    float4 o;
    o.x = (t.x - mu2) * rs2 * gfv.x + bfv.x;
    o.y = (t.y - mu2) * rs2 * gfv.y + bfv.y;
    o.z = (t.z - mu2) * rs2 * gfv.z + bfv.z;
    o.w = (t.w - mu2) * rs2 * gfv.w + bfv.w;
    ((float4*)(h2 + row * DIMV))[tid] = o;
}

// ---------------- tiled SGEMM: C = act(A[M,K] @ W[K,N] + bias) (+ res) ----------------
// block tile 128x64, K-step 16, 256 threads, 8x4 per thread
template<int ACT, int RES>
__global__ void __launch_bounds__(256) gemm_kernel(
    const float* __restrict__ A, const float* __restrict__ W,
    const float* __restrict__ bias, const float* __restrict__ resid,
    float* __restrict__ C, int M, int N, int K)
{
    __shared__ float AsT[16][128];
    __shared__ float Bs[16][64];
    const int tid = threadIdx.x;
    const int m0 = blockIdx.y * 128;
    const int n0 = blockIdx.x * 64;
    const int r0 = (tid & 15) * 8;
    const int c0 = (tid >> 4) * 4;
    const int lm = tid >> 1;
    const int lk = (tid & 1) * 8;
    float acc[8][4] = {};
    const float* Ap  = A + (size_t)(m0 + lm) * K + lk;
    const float* Wp2 = W + (size_t)(tid >> 4) * N + n0 + (tid & 15) * 4;

    for (int k0 = 0; k0 < K; k0 += 16) {
        float4 a0 = *(const float4*)(Ap + k0);
        float4 a1 = *(const float4*)(Ap + k0 + 4);
        float4 w0 = *(const float4*)(Wp2 + (size_t)k0 * N);
        AsT[lk + 0][lm] = a0.x; AsT[lk + 1][lm] = a0.y;
        AsT[lk + 2][lm] = a0.z; AsT[lk + 3][lm] = a0.w;
        AsT[lk + 4][lm] = a1.x; AsT[lk + 5][lm] = a1.y;
        AsT[lk + 6][lm] = a1.z; AsT[lk + 7][lm] = a1.w;
        *(float4*)&Bs[tid >> 4][(tid & 15) * 4] = w0;
        __syncthreads();
        #pragma unroll
        for (int k = 0; k < 16; k++) {
            float4 aA = *(float4*)&AsT[k][r0];
            float4 aB = *(float4*)&AsT[k][r0 + 4];
            float4 bv = *(float4*)&Bs[k][c0];
            float av[8] = {aA.x, aA.y, aA.z, aA.w, aB.x, aB.y, aB.z, aB.w};
            float bw[4] = {bv.x, bv.y, bv.z, bv.w};
            #pragma unroll
            for (int i = 0; i < 8; i++)
                #pragma unroll
                for (int j = 0; j < 4; j++)
                    acc[i][j] += av[i] * bw[j];
        }
        __syncthreads();
    }

    float4 bi = *(const float4*)(bias + n0 + c0);
    float bb[4] = {bi.x, bi.y, bi.z, bi.w};
    #pragma unroll
    for (int i = 0; i < 8; i++) {
        size_t row = (size_t)(m0 + r0 + i);
        float v[4];
        #pragma unroll
        for (int j = 0; j < 4; j++) {
            float t = acc[i][j] + bb[j];
            if (ACT == 1) t = gelu_exact(t);
            v[j] = t;
        }
        if (RES) {
            float4 rv = *(const float4*)(resid + row * N + n0 + c0);
            v[0] += rv.x; v[1] += rv.y; v[2] += rv.z; v[3] += rv.w;
        }
        float4 o; o.x = v[0]; o.y = v[1]; o.z = v[2]; o.w = v[3];
        *(float4*)(C + row * N + n0 + c0) = o;
    }
}

// ---------------- flash-style causal attention ----------------
// grid (32 q-tiles, 64 b*h), 256 threads; tiles 64x64, HD=64
__global__ void __launch_bounds__(256) attn_kernel(
    const float* __restrict__ Q, const float* __restrict__ K,
    const float* __restrict__ V, float* __restrict__ O)
{
    extern __shared__ float sm[];
    float* QsT  = sm;              // [c][r]  4096
    float* KsT  = sm + 4096;       // [c][t]  4096
    float* Vs   = sm + 8192;       // [t][d]  4096
    float* Ps   = sm + 12288;      // [t][r]  4096
    float* rowM = sm + 16384;      // 64
    float* rowL = rowM + 64;       // 64
    float* rowA = rowL + 64;       // 64

    const int qt = blockIdx.x;
    const int bh = blockIdx.y;
    const int b  = bh >> 4;
    const int h  = bh & 15;
    const int tid = threadIdx.x;
    const size_t base = (size_t)b * SEQ * DIMV + (size_t)h * HDIMV;
    const float* Qb = Q + base;
    const float* Kb = K + base;
    const float* Vb = V + base;

    const int lr = tid >> 4;   // 0..15
    const int lc = tid & 15;   // 0..15

    // load Q tile transposed + pre-scaled by 1/sqrt(HD)
    #pragma unroll
    for (int i = 0; i < 4; i++) {
        int r = lr + i * 16;
        float4 qv = *(const float4*)(Qb + (size_t)(qt * 64 + r) * DIMV + lc * 4);
        QsT[(lc * 4 + 0) * 64 + r] = qv.x * 0.125f;
        QsT[(lc * 4 + 1) * 64 + r] = qv.y * 0.125f;
        QsT[(lc * 4 + 2) * 64 + r] = qv.z * 0.125f;
        QsT[(lc * 4 + 3) * 64 + r] = qv.w * 0.125f;
    }
    if (tid < 64) { rowM[tid] = -3e38f; rowL[tid] = 0.f; }

    const int r0 = (tid & 15) * 4;
    const int c0 = (tid >> 4) * 4;
    float acc[4][4] = {};
    __syncthreads();

    for (int kt = 0; kt <= qt; kt++) {
        // load K (transposed) and V (natural) tiles
        #pragma unroll
        for (int i = 0; i < 4; i++) {
            int r = lr + i * 16;
            float4 kv = *(const float4*)(Kb + (size_t)(kt * 64 + r) * DIMV + lc * 4);
            KsT[(lc * 4 + 0) * 64 + r] = kv.x;
            KsT[(lc * 4 + 1) * 64 + r] = kv.y;
            KsT[(lc * 4 + 2) * 64 + r] = kv.z;
            KsT[(lc * 4 + 3) * 64 + r] = kv.w;
            float4 vv = *(const float4*)(Vb + (size_t)(kt * 64 + r) * DIMV + lc * 4);
            *(float4*)&Vs[r * 64 + lc * 4] = vv;
        }
        __syncthreads();

        // S = Q @ K^T (this thread: rows r0..r0+3, cols c0..c0+3)
        float s[4][4] = {};
        #pragma unroll
        for (int c = 0; c < 64; c++) {
            float4 qv = *(float4*)&QsT[c * 64 + r0];
            float4 kv = *(float4*)&KsT[c * 64 + c0];
            float qa[4] = {qv.x, qv.y, qv.z, qv.w};
            float kb2[4] = {kv.x, kv.y, kv.z, kv.w};
            #pragma unroll
            for (int i = 0; i < 4; i++)
                #pragma unroll
                for (int j = 0; j < 4; j++)
                    s[i][j] += qa[i] * kb2[j];
        }
        if (kt == qt) {
            #pragma unroll
            for (int i = 0; i < 4; i++)
                #pragma unroll
                for (int j = 0; j < 4; j++)
                    if (c0 + j > r0 + i) s[i][j] = -3e38f;
        }
        #pragma unroll
        for (int i = 0; i < 4; i++)
            #pragma unroll
            for (int j = 0; j < 4; j++)
                Ps[(c0 + j) * 64 + (r0 + i)] = s[i][j];
        __syncthreads();

        // online softmax: 4 threads per row
        {
            int r  = tid >> 2;
            int cg = tid & 3;
            float pv[16];
            float mloc = -3e38f;
            #pragma unroll
            for (int j = 0; j < 16; j++) {
                pv[j] = Ps[(cg * 16 + j) * 64 + r];
                mloc = fmaxf(mloc, pv[j]);
            }
            mloc = fmaxf(mloc, __shfl_xor_sync(0xffffffffu, mloc, 1));
            mloc = fmaxf(mloc, __shfl_xor_sync(0xffffffffu, mloc, 2));
            float mprev = rowM[r];
            float mnew  = fmaxf(mprev, mloc);
            float alpha = __expf(mprev - mnew);
            float suml = 0.f;
            #pragma unroll
            for (int j = 0; j < 16; j++) {
                float p = __expf(pv[j] - mnew);
                Ps[(cg * 16 + j) * 64 + r] = p;
                suml += p;
            }
            suml += __shfl_xor_sync(0xffffffffu, suml, 1);
            suml += __shfl_xor_sync(0xffffffffu, suml, 2);
            if (cg == 0) {
                rowM[r] = mnew;
                rowL[r] = rowL[r] * alpha + suml;
                rowA[r] = alpha;
            }
        }
        __syncthreads();

        // O = O * alpha + P @ V
        float al[4];
        #pragma unroll
        for (int i = 0; i < 4; i++) al[i] = rowA[r0 + i];
        #pragma unroll
        for (int i = 0; i < 4; i++)
            #pragma unroll
            for (int j = 0; j < 4; j++)
                acc[i][j] *= al[i];
        #pragma unroll
        for (int t = 0; t < 64; t++) {
            float4 pv4 = *(float4*)&Ps[t * 64 + r0];
            float4 vv4 = *(float4*)&Vs[t * 64 + c0];
            float pa[4] = {pv4.x, pv4.y, pv4.z, pv4.w};
            float vb[4] = {vv4.x, vv4.y, vv4.z, vv4.w};
            #pragma unroll
            for (int i = 0; i < 4; i++)
                #pragma unroll
                for (int j = 0; j < 4; j++)
                    acc[i][j] += pa[i] * vb[j];
        }
        __syncthreads();
    }

    // normalize and write O in concat-head layout [b, s, h*64 + d]
    #pragma unroll
    for (int i = 0; i < 4; i++) {
        float linv = 1.0f / rowL[r0 + i];
        size_t row = (size_t)b * SEQ + (size_t)(qt * 64 + r0 + i);
        float4 o;
        o.x = acc[i][0] * linv;
        o.y = acc[i][1] * linv;
        o.z = acc[i][2] * linv;
        o.w = acc[i][3] * linv;
        *(float4*)(O + row * DIMV + h * HDIMV + c0) = o;
    }
}

static const size_t ATTN_SMEM = (16384 + 192) * sizeof(float);  // 66304 B

extern "C" void kernel_launch(void* const* d_in, const int* in_sizes, int n_in,
                              void* d_out, int out_size)
{
    const float* x    = (const float*)d_in[0];
    const float* ln1g = (const float*)d_in[1];
    const float* ln1b = (const float*)d_in[2];
    const float* Wq   = (const float*)d_in[3];
    const float* bq   = (const float*)d_in[4];
    const float* Wk   = (const float*)d_in[5];
    const float* bk   = (const float*)d_in[6];
    const float* Wv   = (const float*)d_in[7];
    const float* bv   = (const float*)d_in[8];
    const float* ln2g = (const float*)d_in[9];
    const float* ln2b = (const float*)d_in[10];
    const float* fclg = (const float*)d_in[11];
    const float* fclb = (const float*)d_in[12];
    const float* W1   = (const float*)d_in[13];
    const float* b1   = (const float*)d_in[14];
    const float* W2   = (const float*)d_in[15];
    const float* b2   = (const float*)d_in[16];
    float* out = (float*)d_out;

    float *p_h, *p_q, *p_k, *p_v, *p_o, *p_x2, *p_h2, *p_mid, *p_wp;
    cudaGetSymbolAddress((void**)&p_h,   g_h);
    cudaGetSymbolAddress((void**)&p_q,   g_q);
    cudaGetSymbolAddress((void**)&p_k,   g_kk);
    cudaGetSymbolAddress((void**)&p_v,   g_v);
    cudaGetSymbolAddress((void**)&p_o,   g_o);
    cudaGetSymbolAddress((void**)&p_x2,  g_x2);
    cudaGetSymbolAddress((void**)&p_h2,  g_h2);
    cudaGetSymbolAddress((void**)&p_mid, g_mid);
    cudaGetSymbolAddress((void**)&p_wp,  g_wp);

    cudaFuncSetAttribute(attn_kernel, cudaFuncAttributeMaxDynamicSharedMemorySize,
                         (int)ATTN_SMEM);

    // 1. repack QKV weights to [D, NH*HD]
    repack_w_kernel<<<dim3(4096, 3), 256>>>(Wq, Wk, Wv, p_wp);
    // 2. ln1
    ln_kernel<<<NTOK, 256>>>(x, ln1g, ln1b, p_h);
    // 3. QKV projections (bias layouts [NH,HD] are already contiguous over columns)
    gemm_kernel<0, 0><<<dim3(16, 64), 256>>>(p_h, p_wp,               bq, nullptr, p_q, NTOK, DIMV, DIMV);
    gemm_kernel<0, 0><<<dim3(16, 64), 256>>>(p_h, p_wp + 1048576,     bk, nullptr, p_k, NTOK, DIMV, DIMV);
    gemm_kernel<0, 0><<<dim3(16, 64), 256>>>(p_h, p_wp + 2097152,     bv, nullptr, p_v, NTOK, DIMV, DIMV);
    // 4. causal attention (writes concat-head layout directly)
    attn_kernel<<<dim3(32, 64), 256, ATTN_SMEM>>>(p_q, p_k, p_v, p_o);
    // 5. residual add + ln2 + fcln fused
    add_dln_kernel<<<NTOK, 256>>>(x, p_o, ln2g, ln2b, fclg, fclb, p_x2, p_h2);
    // 6. MLP up + GELU
    gemm_kernel<1, 0><<<dim3(64, 64), 256>>>(p_h2, W1, b1, nullptr, p_mid, NTOK, HIDV, DIMV);
    // 7. MLP down + GELU + residual -> out
    gemm_kernel<1, 1><<<dim3(16, 64), 256>>>(p_mid, W2, b2, p_x2, out, NTOK, DIMV, HIDV);
}

// round 4
// speedup vs baseline: 3.1029x; 3.1029x over previous
#include <cuda_runtime.h>
#include <cstdint>
#include <cstddef>

// Problem dims
#define DIMV   1024
#define HIDV   4096
#define SEQ    2048
#define NHEAD  16
#define HDIMV  64
#define NTOK   8192          // B * S
#define QKV_LD 3072          // fused QKV row stride

// GEMM tiling (mma.sync tf32)
#define BM 128
#define BN 128
#define BKS 16               // K per stage
#define TILE_F 2560          // 128 rows * 20 padded floats
#define STAGE_F 5120         // A tile + B tile
#define GEMM_SMEM_BYTES (3 * STAGE_F * 4)   // 61440

// ---------------- static scratch (no allocation allowed) ----------------
__device__ float g_h   [(size_t)NTOK * DIMV];    // ln1(x), tf32-rounded
__device__ float g_qkv [(size_t)NTOK * QKV_LD];  // fused Q|K|V
__device__ float g_o   [(size_t)NTOK * DIMV];    // attention out (concat heads)
__device__ float g_x2  [(size_t)NTOK * DIMV];    // x + attn
__device__ float g_h2  [(size_t)NTOK * DIMV];    // double-LN out, tf32-rounded
__device__ float g_mid [(size_t)NTOK * HIDV];    // MLP hidden, tf32-rounded
__device__ float g_wt  [(size_t)QKV_LD * DIMV];  // QKV weights [3072 n][1024 k]
__device__ float g_w1t [(size_t)HIDV * DIMV];    // W1^T  [4096 n][1024 k]
__device__ float g_w2t [(size_t)DIMV * HIDV];    // W2^T  [1024 n][4096 k]
__device__ float g_bqkv[QKV_LD];

// ---------------- helpers ----------------
__device__ __forceinline__ uint32_t smem_u32(const void* p) {
    uint32_t a;
    asm("{ .reg .u64 t; cvta.to.shared.u64 t, %1; cvt.u32.u64 %0, t; }" : "=r"(a) : "l"(p));
    return a;
}

__device__ __forceinline__ float to_tf32(float x) {
    uint32_t r;
    asm("cvt.rna.tf32.f32 %0, %1;" : "=r"(r) : "f"(x));
    return __uint_as_float(r);
}

__device__ __forceinline__ float gelu_exact(float x) {
    return 0.5f * x * (1.0f + erff(x * 0.70710678118654752f));
}

__device__ __forceinline__ void cp_async16(uint32_t dst, const float* src) {
    asm volatile("cp.async.cg.shared.global [%0], [%1], 16;" :: "r"(dst), "l"(src));
}
#define CP_COMMIT() asm volatile("cp.async.commit_group;" ::: "memory")
#define CP_WAIT1()  asm volatile("cp.async.wait_group 1;" ::: "memory")

__device__ __forceinline__ void mma_tf32(float* c, const uint32_t* a, const uint32_t* b) {
    asm volatile(
        "mma.sync.aligned.m16n8k8.row.col.f32.tf32.tf32.f32 "
        "{%0,%1,%2,%3}, {%4,%5,%6,%7}, {%8,%9}, {%0,%1,%2,%3};"
        : "+f"(c[0]), "+f"(c[1]), "+f"(c[2]), "+f"(c[3])
        : "r"(a[0]), "r"(a[1]), "r"(a[2]), "r"(a[3]), "r"(b[0]), "r"(b[1]));
}

// ---------------- weight transpose (tiled, with tf32 rounding) ----------------
__global__ void transpose_kernel(const float* __restrict__ src, float* __restrict__ dst,
                                 int R, int C)
{
    __shared__ float t[32][33];
    int c0 = blockIdx.x * 32, r0 = blockIdx.y * 32;
    int tx = threadIdx.x, ty = threadIdx.y;
    #pragma unroll
    for (int i = 0; i < 32; i += 8)
        t[ty + i][tx] = src[(size_t)(r0 + ty + i) * C + c0 + tx];
    __syncthreads();
    #pragma unroll
    for (int i = 0; i < 32; i += 8)
        dst[(size_t)(c0 + ty + i) * R + r0 + tx] = to_tf32(t[tx][ty + i]);
}

// QKV: [NH,D,HD] x3 -> [3072 n][1024 k], n = w*1024 + h*64 + j
__global__ void transpose_qkv_kernel(const float* __restrict__ Wq, const float* __restrict__ Wk,
                                     const float* __restrict__ Wv, float* __restrict__ dst)
{
    __shared__ float t[32][33];
    int s = blockIdx.z, w = s >> 4, h = s & 15;
    const float* W = ((w == 0) ? Wq : (w == 1) ? Wk : Wv) + (size_t)h * DIMV * HDIMV;
    float* D = dst + (size_t)(w * 1024 + h * 64) * DIMV;
    int c0 = blockIdx.x * 32, r0 = blockIdx.y * 32;
    int tx = threadIdx.x, ty = threadIdx.y;
    #pragma unroll
    for (int i = 0; i < 32; i += 8)
        t[ty + i][tx] = W[(size_t)(r0 + ty + i) * HDIMV + c0 + tx];
    __syncthreads();
    #pragma unroll
    for (int i = 0; i < 32; i += 8)
        D[(size_t)(c0 + ty + i) * DIMV + r0 + tx] = to_tf32(t[tx][ty + i]);
}

__global__ void pack_bias_kernel(const float* __restrict__ bq, const float* __restrict__ bk,
                                 const float* __restrict__ bv, float* __restrict__ dst)
{
    int i = blockIdx.x * 256 + threadIdx.x;
    float v = (i < 1024) ? bq[i] : (i < 2048) ? bk[i - 1024] : bv[i - 2048];
    dst[i] = v;
}

// ---------------- LayerNorm (tf32-rounded output) ----------------
__global__ void ln_kernel(const float* __restrict__ x, const float* __restrict__ g,
                          const float* __restrict__ b, float* __restrict__ y)
{
    __shared__ float s_a[8], s_b[8];
    __shared__ float s_mu, s_rs;
    size_t row = blockIdx.x;
    int tid = threadIdx.x;
    float4 v = ((const float4*)(x + row * DIMV))[tid];
    float sum = v.x + v.y + v.z + v.w;
    float sq  = v.x*v.x + v.y*v.y + v.z*v.z + v.w*v.w;
    #pragma unroll
    for (int o = 16; o; o >>= 1) {
        sum += __shfl_xor_sync(0xffffffffu, sum, o);
        sq  += __shfl_xor_sync(0xffffffffu, sq,  o);
    }
    if ((tid & 31) == 0) { s_a[tid >> 5] = sum; s_b[tid >> 5] = sq; }
    __syncthreads();
    if (tid == 0) {
        float ts = 0.f, tq = 0.f;
        #pragma unroll
        for (int i = 0; i < 8; i++) { ts += s_a[i]; tq += s_b[i]; }
        float mu  = ts * (1.0f / DIMV);
        float var = tq * (1.0f / DIMV) - mu * mu;
        s_mu = mu; s_rs = rsqrtf(var + 1e-5f);
    }
    __syncthreads();
    float mu = s_mu, rs = s_rs;
    float4 gv = ((const float4*)g)[tid];
    float4 bv = ((const float4*)b)[tid];
    float4 o;
    o.x = to_tf32((v.x - mu) * rs * gv.x + bv.x);
    o.y = to_tf32((v.y - mu) * rs * gv.y + bv.y);
    o.z = to_tf32((v.z - mu) * rs * gv.z + bv.z);
    o.w = to_tf32((v.w - mu) * rs * gv.w + bv.w);
    ((float4*)(y + row * DIMV))[tid] = o;
}

// ---------------- residual add + LN(ln2) + LN(fcln) fused ----------------
__global__ void add_dln_kernel(const float* __restrict__ x, const float* __restrict__ oatt,
                               const float* __restrict__ g2, const float* __restrict__ b2,
                               const float* __restrict__ gf, const float* __restrict__ bf,
                               float* __restrict__ x2, float* __restrict__ h2)
{
    __shared__ float s_a[8], s_b[8];
    __shared__ float s_mu, s_rs;
    size_t row = blockIdx.x;
    int tid = threadIdx.x;
    float4 v  = ((const float4*)(x    + row * DIMV))[tid];
    float4 ov = ((const float4*)(oatt + row * DIMV))[tid];
    v.x += ov.x; v.y += ov.y; v.z += ov.z; v.w += ov.w;
    ((float4*)(x2 + row * DIMV))[tid] = v;

    float sum = v.x + v.y + v.z + v.w;
    float sq  = v.x*v.x + v.y*v.y + v.z*v.z + v.w*v.w;
    #pragma unroll
    for (int o = 16; o; o >>= 1) {
        sum += __shfl_xor_sync(0xffffffffu, sum, o);
        sq  += __shfl_xor_sync(0xffffffffu, sq,  o);
    }
    if ((tid & 31) == 0) { s_a[tid >> 5] = sum; s_b[tid >> 5] = sq; }
    __syncthreads();
    if (tid == 0) {
        float ts = 0.f, tq = 0.f;
        #pragma unroll
        for (int i = 0; i < 8; i++) { ts += s_a[i]; tq += s_b[i]; }
        float mu  = ts * (1.0f / DIMV);
        float var = tq * (1.0f / DIMV) - mu * mu;
        s_mu = mu; s_rs = rsqrtf(var + 1e-5f);
    }
    __syncthreads();
    float mu1 = s_mu, rs1 = s_rs;
    float4 g2v = ((const float4*)g2)[tid];
    float4 b2v = ((const float4*)b2)[tid];
    float4 t;
    t.x = (v.x - mu1) * rs1 * g2v.x + b2v.x;
    t.y = (v.y - mu1) * rs1 * g2v.y + b2v.y;
    t.z = (v.z - mu1) * rs1 * g2v.z + b2v.z;
    t.w = (v.w - mu1) * rs1 * g2v.w + b2v.w;

    float sum2 = t.x + t.y + t.z + t.w;
    float sq2  = t.x*t.x + t.y*t.y + t.z*t.z + t.w*t.w;
    #pragma unroll
    for (int o = 16; o; o >>= 1) {
        sum2 += __shfl_xor_sync(0xffffffffu, sum2, o);
        sq2  += __shfl_xor_sync(0xffffffffu, sq2,  o);
    }
    if ((tid & 31) == 0) { s_a[tid >> 5] = sum2; s_b[tid >> 5] = sq2; }
    __syncthreads();
    if (tid == 0) {
        float ts = 0.f, tq = 0.f;
        #pragma unroll
        for (int i = 0; i < 8; i++) { ts += s_a[i]; tq += s_b[i]; }
        float mu  = ts * (1.0f / DIMV);
        float var = tq * (1.0f / DIMV) - mu * mu;
        s_mu = mu; s_rs = rsqrtf(var + 1e-5f);
    }
    __syncthreads();
    float mu2 = s_mu, rs2 = s_rs;
    float4 gfv = ((const float4*)gf)[tid];
    float4 bfv = ((const float4*)bf)[tid];
    float4 o;
    o.x = to_tf32((t.x - mu2) * rs2 * gfv.x + bfv.x);
    o.y = to_tf32((t.y - mu2) * rs2 * gfv.y + bfv.y);
    o.z = to_tf32((t.z - mu2) * rs2 * gfv.z + bfv.z);
    o.w = to_tf32((t.w - mu2) * rs2 * gfv.w + bfv.w);
    ((float4*)(h2 + row * DIMV))[tid] = o;
}

// ---------------- mma.sync tf32 GEMM: C = act(A[M,K] @ Bt^T + bias) (+res) ----------------
// A [M,K] row-major fp32 (tf32-rounded values); Bt [N,K] row-major (tf32-rounded).
// CTA tile 128x128, 256 threads, 8 warps (2m x 4n), warp tile 64x32, 3-stage cp.async.
template<int ACT, int RES, int RND>
__global__ void __launch_bounds__(256) gemm_mma(
    const float* __restrict__ A, const float* __restrict__ Bt,
    const float* __restrict__ bias, const float* __restrict__ resid,
    float* __restrict__ C, int N, int K)
{
    extern __shared__ float sm[];
    const int tid  = threadIdx.x;
    const int lane = tid & 31;
    const int warp = tid >> 5;
    const int wm = warp >> 2;       // 0..1
    const int wn = warp & 3;        // 0..3
    const int m0 = blockIdx.y * BM;
    const int n0 = blockIdx.x * BN;
    const int KT = K / BKS;

    const int lrow = tid >> 2;          // 0..63
    const int lkc  = (tid & 3) * 4;     // 0,4,8,12

    const float* Asrc0 = A  + (size_t)(m0 + lrow)      * K + lkc;
    const float* Asrc1 = A  + (size_t)(m0 + lrow + 64) * K + lkc;
    const float* Bsrc0 = Bt + (size_t)(n0 + lrow)      * K + lkc;
    const float* Bsrc1 = Bt + (size_t)(n0 + lrow + 64) * K + lkc;

    const uint32_t smb = smem_u32(sm);
    const uint32_t dA0 = smb + ((lrow)      * 20 + lkc) * 4;
    const uint32_t dA1 = smb + ((lrow + 64) * 20 + lkc) * 4;
    const uint32_t dB0 = dA0 + TILE_F * 4;
    const uint32_t dB1 = dA1 + TILE_F * 4;

    // prologue: stages 0,1
    #pragma unroll
    for (int s = 0; s < 2; s++) {
        uint32_t off = s * STAGE_F * 4;
        int k0 = s * BKS;
        cp_async16(dA0 + off, Asrc0 + k0);
        cp_async16(dA1 + off, Asrc1 + k0);
        cp_async16(dB0 + off, Bsrc0 + k0);
        cp_async16(dB1 + off, Bsrc1 + k0);
        CP_COMMIT();
    }

    float acc[4][4][4] = {};
    const int gr = lane >> 2;   // 0..7
    const int tg = lane & 3;    // 0..3

    for (int kt = 0; kt < KT; kt++) {
        CP_WAIT1();
        __syncthreads();
        const float* As = sm + (kt % 3) * STAGE_F;
        const float* Bs = As + TILE_F;

        #pragma unroll
        for (int ks = 0; ks < 16; ks += 8) {
            uint32_t af[4][4], bf[4][2];
            #pragma unroll
            for (int mb = 0; mb < 4; mb++) {
                int r = wm * 64 + mb * 16 + gr;
                af[mb][0] = __float_as_uint(As[(r)     * 20 + ks + tg]);
                af[mb][1] = __float_as_uint(As[(r + 8) * 20 + ks + tg]);
                af[mb][2] = __float_as_uint(As[(r)     * 20 + ks + 4 + tg]);
                af[mb][3] = __float_as_uint(As[(r + 8) * 20 + ks + 4 + tg]);
            }
            #pragma unroll
            for (int nb = 0; nb < 4; nb++) {
                int c = wn * 32 + nb * 8 + gr;
                bf[nb][0] = __float_as_uint(Bs[c * 20 + ks + tg]);
                bf[nb][1] = __float_as_uint(Bs[c * 20 + ks + 4 + tg]);
            }
            #pragma unroll
            for (int mb = 0; mb < 4; mb++)
                #pragma unroll
                for (int nb = 0; nb < 4; nb++)
                    mma_tf32(acc[mb][nb], af[mb], bf[nb]);
        }

        if (kt + 2 < KT) {
            uint32_t off = ((kt + 2) % 3) * STAGE_F * 4;
            int k0 = (kt + 2) * BKS;
            cp_async16(dA0 + off, Asrc0 + k0);
            cp_async16(dA1 + off, Asrc1 + k0);
            cp_async16(dB0 + off, Bsrc0 + k0);
            cp_async16(dB1 + off, Bsrc1 + k0);
        }
        CP_COMMIT();
        __syncthreads();
    }

    // epilogue
    #pragma unroll
    for (int mb = 0; mb < 4; mb++) {
        int rlo = m0 + wm * 64 + mb * 16 + gr;
        #pragma unroll
        for (int nb = 0; nb < 4; nb++) {
            int col = n0 + wn * 32 + nb * 8 + tg * 2;
            float2 bi = *(const float2*)(bias + col);
            #pragma unroll
            for (int half = 0; half < 2; half++) {
                int row = rlo + half * 8;
                float v0 = acc[mb][nb][half * 2 + 0] + bi.x;
                float v1 = acc[mb][nb][half * 2 + 1] + bi.y;
                if (ACT) { v0 = gelu_exact(v0); v1 = gelu_exact(v1); }
                if (RND) { v0 = to_tf32(v0);    v1 = to_tf32(v1); }
                if (RES) {
                    float2 rv = *(const float2*)(resid + (size_t)row * N + col);
                    v0 += rv.x; v1 += rv.y;
                }
                float2 o2; o2.x = v0; o2.y = v1;
                *(float2*)(C + (size_t)row * N + col) = o2;
            }
        }
    }
}

// ---------------- flash-style causal attention (fp32, fused-QKV input) ----------------
__global__ void __launch_bounds__(256) attn_kernel(
    const float* __restrict__ QKV, float* __restrict__ O)
{
    extern __shared__ float sma[];
    float* QsT  = sma;
    float* KsT  = sma + 4096;
    float* Vs   = sma + 8192;
    float* Ps   = sma + 12288;
    float* rowM = sma + 16384;
    float* rowL = rowM + 64;
    float* rowA = rowL + 64;

    const int qt = blockIdx.x;
    const int bh = blockIdx.y;
    const int b  = bh >> 4;
    const int h  = bh & 15;
    const int tid = threadIdx.x;
    const float* Qb = QKV + (size_t)b * SEQ * QKV_LD + h * HDIMV;
    const float* Kb = Qb + 1024;
    const float* Vb = Qb + 2048;

    const int lr = tid >> 4;
    const int lc = tid & 15;

    #pragma unroll
    for (int i = 0; i < 4; i++) {
        int r = lr + i * 16;
        float4 qv = *(const float4*)(Qb + (size_t)(qt * 64 + r) * QKV_LD + lc * 4);
        QsT[(lc * 4 + 0) * 64 + r] = qv.x * 0.125f;
        QsT[(lc * 4 + 1) * 64 + r] = qv.y * 0.125f;
        QsT[(lc * 4 + 2) * 64 + r] = qv.z * 0.125f;
        QsT[(lc * 4 + 3) * 64 + r] = qv.w * 0.125f;
    }
    if (tid < 64) { rowM[tid] = -3e38f; rowL[tid] = 0.f; }

    const int r0 = (tid & 15) * 4;
    const int c0 = (tid >> 4) * 4;
    float acc[4][4] = {};
    __syncthreads();

    for (int kt = 0; kt <= qt; kt++) {
        #pragma unroll
        for (int i = 0; i < 4; i++) {
            int r = lr + i * 16;
            float4 kv = *(const float4*)(Kb + (size_t)(kt * 64 + r) * QKV_LD + lc * 4);
            KsT[(lc * 4 + 0) * 64 + r] = kv.x;
            KsT[(lc * 4 + 1) * 64 + r] = kv.y;
            KsT[(lc * 4 + 2) * 64 + r] = kv.z;
            KsT[(lc * 4 + 3) * 64 + r] = kv.w;
            float4 vv = *(const float4*)(Vb + (size_t)(kt * 64 + r) * QKV_LD + lc * 4);
            *(float4*)&Vs[r * 64 + lc * 4] = vv;
        }
        __syncthreads();

        float s[4][4] = {};
        #pragma unroll
        for (int c = 0; c < 64; c++) {
            float4 qv = *(float4*)&QsT[c * 64 + r0];
            float4 kv = *(float4*)&KsT[c * 64 + c0];
            float qa[4] = {qv.x, qv.y, qv.z, qv.w};
            float kb2[4] = {kv.x, kv.y, kv.z, kv.w};
            #pragma unroll
            for (int i = 0; i < 4; i++)
                #pragma unroll
                for (int j = 0; j < 4; j++)
                    s[i][j] += qa[i] * kb2[j];
        }
        if (kt == qt) {
            #pragma unroll
            for (int i = 0; i < 4; i++)
                #pragma unroll
                for (int j = 0; j < 4; j++)
                    if (c0 + j > r0 + i) s[i][j] = -3e38f;
        }
        #pragma unroll
        for (int i = 0; i < 4; i++)
            #pragma unroll
            for (int j = 0; j < 4; j++)
                Ps[(c0 + j) * 64 + (r0 + i)] = s[i][j];
        __syncthreads();

        {
            int r  = tid >> 2;
            int cg = tid & 3;
            float pv[16];
            float mloc = -3e38f;
            #pragma unroll
            for (int j = 0; j < 16; j++) {
                pv[j] = Ps[(cg * 16 + j) * 64 + r];
                mloc = fmaxf(mloc, pv[j]);
            }
            mloc = fmaxf(mloc, __shfl_xor_sync(0xffffffffu, mloc, 1));
            mloc = fmaxf(mloc, __shfl_xor_sync(0xffffffffu, mloc, 2));
            float mprev = rowM[r];
            float mnew  = fmaxf(mprev, mloc);
            float alpha = __expf(mprev - mnew);
            float suml = 0.f;
            #pragma unroll
            for (int j = 0; j < 16; j++) {
                float p = __expf(pv[j] - mnew);
                Ps[(cg * 16 + j) * 64 + r] = p;
                suml += p;
            }
            suml += __shfl_xor_sync(0xffffffffu, suml, 1);
            suml += __shfl_xor_sync(0xffffffffu, suml, 2);
            if (cg == 0) {
                rowM[r] = mnew;
                rowL[r] = rowL[r] * alpha + suml;
                rowA[r] = alpha;
            }
        }
        __syncthreads();

        float al[4];
        #pragma unroll
        for (int i = 0; i < 4; i++) al[i] = rowA[r0 + i];
        #pragma unroll
        for (int i = 0; i < 4; i++)
            #pragma unroll
            for (int j = 0; j < 4; j++)
                acc[i][j] *= al[i];
        #pragma unroll
        for (int t = 0; t < 64; t++) {
            float4 pv4 = *(float4*)&Ps[t * 64 + r0];
            float4 vv4 = *(float4*)&Vs[t * 64 + c0];
            float pa[4] = {pv4.x, pv4.y, pv4.z, pv4.w};
            float vb[4] = {vv4.x, vv4.y, vv4.z, vv4.w};
            #pragma unroll
            for (int i = 0; i < 4; i++)
                #pragma unroll
                for (int j = 0; j < 4; j++)
                    acc[i][j] += pa[i] * vb[j];
        }
        __syncthreads();
    }

    #pragma unroll
    for (int i = 0; i < 4; i++) {
        float linv = 1.0f / rowL[r0 + i];
        size_t row = (size_t)b * SEQ + (size_t)(qt * 64 + r0 + i);
        float4 o;
        o.x = acc[i][0] * linv;
        o.y = acc[i][1] * linv;
        o.z = acc[i][2] * linv;
        o.w = acc[i][3] * linv;
        *(float4*)(O + row * DIMV + h * HDIMV + c0) = o;
    }
}

static const size_t ATTN_SMEM = (16384 + 192) * sizeof(float);

extern "C" void kernel_launch(void* const* d_in, const int* in_sizes, int n_in,
                              void* d_out, int out_size)
{
    const float* x    = (const float*)d_in[0];
    const float* ln1g = (const float*)d_in[1];
    const float* ln1b = (const float*)d_in[2];
    const float* Wq   = (const float*)d_in[3];
    const float* bq   = (const float*)d_in[4];
    const float* Wk   = (const float*)d_in[5];
    const float* bk   = (const float*)d_in[6];
    const float* Wv   = (const float*)d_in[7];
    const float* bv   = (const float*)d_in[8];
    const float* ln2g = (const float*)d_in[9];
    const float* ln2b = (const float*)d_in[10];
    const float* fclg = (const float*)d_in[11];
    const float* fclb = (const float*)d_in[12];
    const float* W1   = (const float*)d_in[13];
    const float* b1   = (const float*)d_in[14];
    const float* W2   = (const float*)d_in[15];
    const float* b2   = (const float*)d_in[16];
    float* out = (float*)d_out;

    float *p_h, *p_qkv, *p_o, *p_x2, *p_h2, *p_mid, *p_wt, *p_w1t, *p_w2t, *p_bqkv;
    cudaGetSymbolAddress((void**)&p_h,    g_h);
    cudaGetSymbolAddress((void**)&p_qkv,  g_qkv);
    cudaGetSymbolAddress((void**)&p_o,    g_o);
    cudaGetSymbolAddress((void**)&p_x2,   g_x2);
    cudaGetSymbolAddress((void**)&p_h2,   g_h2);
    cudaGetSymbolAddress((void**)&p_mid,  g_mid);
    cudaGetSymbolAddress((void**)&p_wt,   g_wt);
    cudaGetSymbolAddress((void**)&p_w1t,  g_w1t);
    cudaGetSymbolAddress((void**)&p_w2t,  g_w2t);
    cudaGetSymbolAddress((void**)&p_bqkv, g_bqkv);

    cudaFuncSetAttribute(attn_kernel, cudaFuncAttributeMaxDynamicSharedMemorySize, (int)ATTN_SMEM);
    cudaFuncSetAttribute(gemm_mma<0,0,0>, cudaFuncAttributeMaxDynamicSharedMemorySize, GEMM_SMEM_BYTES);
    cudaFuncSetAttribute(gemm_mma<1,0,1>, cudaFuncAttributeMaxDynamicSharedMemorySize, GEMM_SMEM_BYTES);
    cudaFuncSetAttribute(gemm_mma<1,1,0>, cudaFuncAttributeMaxDynamicSharedMemorySize, GEMM_SMEM_BYTES);

    // 1. weight prep (transpose + tf32 rounding) and bias pack
    transpose_qkv_kernel<<<dim3(2, 32, 48), dim3(32, 8)>>>(Wq, Wk, Wv, p_wt);
    transpose_kernel<<<dim3(HIDV / 32, DIMV / 32), dim3(32, 8)>>>(W1, p_w1t, DIMV, HIDV);
    transpose_kernel<<<dim3(DIMV / 32, HIDV / 32), dim3(32, 8)>>>(W2, p_w2t, HIDV, DIMV);
    pack_bias_kernel<<<QKV_LD / 256, 256>>>(bq, bk, bv, p_bqkv);
    // 2. ln1 (tf32-rounded)
    ln_kernel<<<NTOK, 256>>>(x, ln1g, ln1b, p_h);
    // 3. fused QKV projection: [8192,1024] @ [1024,3072]
    gemm_mma<0,0,0><<<dim3(QKV_LD / BN, NTOK / BM), 256, GEMM_SMEM_BYTES>>>(
        p_h, p_wt, p_bqkv, nullptr, p_qkv, QKV_LD, DIMV);
    // 4. causal attention
    attn_kernel<<<dim3(SEQ / 64, 64), 256, ATTN_SMEM>>>(p_qkv, p_o);
    // 5. residual + ln2 + fcln
    add_dln_kernel<<<NTOK, 256>>>(x, p_o, ln2g, ln2b, fclg, fclb, p_x2, p_h2);
    // 6. MLP up + GELU (tf32-rounded out)
    gemm_mma<1,0,1><<<dim3(HIDV / BN, NTOK / BM), 256, GEMM_SMEM_BYTES>>>(
        p_h2, p_w1t, b1, nullptr, p_mid, HIDV, DIMV);
    // 7. MLP down + GELU + residual -> out
    gemm_mma<1,1,0><<<dim3(DIMV / BN, NTOK / BM), 256, GEMM_SMEM_BYTES>>>(
        p_mid, p_w2t, b2, p_x2, out, DIMV, HIDV);
}

// round 5
// speedup vs baseline: 4.8567x; 1.5652x over previous
#include <cuda_runtime.h>
#include <cstdint>
#include <cstddef>

// Problem dims
#define DIMV   1024
#define HIDV   4096
#define SEQ    2048
#define NHEAD  16
#define HDIMV  64
#define NTOK   8192          // B * S
#define QKV_LD 3072          // fused QKV row stride

// GEMM tiling (mma.sync tf32)
#define BM 128
#define BN 128
#define BKS 16               // K per stage
#define TILE_F 2560          // 128 rows * 20 padded floats
#define STAGE_F 5120         // A tile + B tile
#define GEMM_SMEM_BYTES (3 * STAGE_F * 4)   // 61440

// attention smem
#define AT_PAD 68
#define AT_TILE (64 * AT_PAD)                  // floats per K/V/P tile
#define ATTN_SMEM_B ((4 * AT_TILE + AT_TILE) * 4)  // K[2]+V[2]+P = 87040 B

// ---------------- static scratch (no allocation allowed) ----------------
__device__ float g_h   [(size_t)NTOK * DIMV];
__device__ float g_qkv [(size_t)NTOK * QKV_LD];
__device__ float g_o   [(size_t)NTOK * DIMV];
__device__ float g_x2  [(size_t)NTOK * DIMV];
__device__ float g_h2  [(size_t)NTOK * DIMV];
__device__ float g_mid [(size_t)NTOK * HIDV];
__device__ float g_wt  [(size_t)QKV_LD * DIMV];
__device__ float g_w1t [(size_t)HIDV * DIMV];
__device__ float g_w2t [(size_t)DIMV * HIDV];
__device__ float g_bqkv[QKV_LD];

// ---------------- helpers ----------------
__device__ __forceinline__ uint32_t smem_u32(const void* p) {
    uint32_t a;
    asm("{ .reg .u64 t; cvta.to.shared.u64 t, %1; cvt.u32.u64 %0, t; }" : "=r"(a) : "l"(p));
    return a;
}

__device__ __forceinline__ float to_tf32(float x) {
    uint32_t r;
    asm("cvt.rna.tf32.f32 %0, %1;" : "=r"(r) : "f"(x));
    return __uint_as_float(r);
}

__device__ __forceinline__ uint32_t to_tf32_u(float x) {
    uint32_t r;
    asm("cvt.rna.tf32.f32 %0, %1;" : "=r"(r) : "f"(x));
    return r;
}

__device__ __forceinline__ float gelu_exact(float x) {
    return 0.5f * x * (1.0f + erff(x * 0.70710678118654752f));
}

__device__ __forceinline__ void cp_async16(uint32_t dst, const float* src) {
    asm volatile("cp.async.cg.shared.global [%0], [%1], 16;" :: "r"(dst), "l"(src));
}
#define CP_COMMIT() asm volatile("cp.async.commit_group;" ::: "memory")
#define CP_WAIT1()  asm volatile("cp.async.wait_group 1;" ::: "memory")
#define CP_WAIT0()  asm volatile("cp.async.wait_group 0;" ::: "memory")

__device__ __forceinline__ void mma_tf32(float* c, const uint32_t* a, const uint32_t* b) {
    asm volatile(
        "mma.sync.aligned.m16n8k8.row.col.f32.tf32.tf32.f32 "
        "{%0,%1,%2,%3}, {%4,%5,%6,%7}, {%8,%9}, {%0,%1,%2,%3};"
        : "+f"(c[0]), "+f"(c[1]), "+f"(c[2]), "+f"(c[3])
        : "r"(a[0]), "r"(a[1]), "r"(a[2]), "r"(a[3]), "r"(b[0]), "r"(b[1]));
}

// ---------------- weight transpose (tiled, with tf32 rounding) ----------------
__global__ void transpose_kernel(const float* __restrict__ src, float* __restrict__ dst,
                                 int R, int C)
{
    __shared__ float t[32][33];
    int c0 = blockIdx.x * 32, r0 = blockIdx.y * 32;
    int tx = threadIdx.x, ty = threadIdx.y;
    #pragma unroll
    for (int i = 0; i < 32; i += 8)
        t[ty + i][tx] = src[(size_t)(r0 + ty + i) * C + c0 + tx];
    __syncthreads();
    #pragma unroll
    for (int i = 0; i < 32; i += 8)
        dst[(size_t)(c0 + ty + i) * R + r0 + tx] = to_tf32(t[tx][ty + i]);
}

__global__ void transpose_qkv_kernel(const float* __restrict__ Wq, const float* __restrict__ Wk,
                                     const float* __restrict__ Wv, float* __restrict__ dst)
{
    __shared__ float t[32][33];
    int s = blockIdx.z, w = s >> 4, h = s & 15;
    const float* W = ((w == 0) ? Wq : (w == 1) ? Wk : Wv) + (size_t)h * DIMV * HDIMV;
    float* D = dst + (size_t)(w * 1024 + h * 64) * DIMV;
    int c0 = blockIdx.x * 32, r0 = blockIdx.y * 32;
    int tx = threadIdx.x, ty = threadIdx.y;
    #pragma unroll
    for (int i = 0; i < 32; i += 8)
        t[ty + i][tx] = W[(size_t)(r0 + ty + i) * HDIMV + c0 + tx];
    __syncthreads();
    #pragma unroll
    for (int i = 0; i < 32; i += 8)
        D[(size_t)(c0 + ty + i) * DIMV + r0 + tx] = to_tf32(t[tx][ty + i]);
}

__global__ void pack_bias_kernel(const float* __restrict__ bq, const float* __restrict__ bk,
                                 const float* __restrict__ bv, float* __restrict__ dst)
{
    int i = blockIdx.x * 256 + threadIdx.x;
    float v = (i < 1024) ? bq[i] : (i < 2048) ? bk[i - 1024] : bv[i - 2048];
    dst[i] = v;
}

// ---------------- LayerNorm (tf32-rounded output) ----------------
__global__ void ln_kernel(const float* __restrict__ x, const float* __restrict__ g,
                          const float* __restrict__ b, float* __restrict__ y)
{
    __shared__ float s_a[8], s_b[8];
    __shared__ float s_mu, s_rs;
    size_t row = blockIdx.x;
    int tid = threadIdx.x;
    float4 v = ((const float4*)(x + row * DIMV))[tid];
    float sum = v.x + v.y + v.z + v.w;
    float sq  = v.x*v.x + v.y*v.y + v.z*v.z + v.w*v.w;
    #pragma unroll
    for (int o = 16; o; o >>= 1) {
        sum += __shfl_xor_sync(0xffffffffu, sum, o);
        sq  += __shfl_xor_sync(0xffffffffu, sq,  o);
    }
    if ((tid & 31) == 0) { s_a[tid >> 5] = sum; s_b[tid >> 5] = sq; }
    __syncthreads();
    if (tid == 0) {
        float ts = 0.f, tq = 0.f;
        #pragma unroll
        for (int i = 0; i < 8; i++) { ts += s_a[i]; tq += s_b[i]; }
        float mu  = ts * (1.0f / DIMV);
        float var = tq * (1.0f / DIMV) - mu * mu;
        s_mu = mu; s_rs = rsqrtf(var + 1e-5f);
    }
    __syncthreads();
    float mu = s_mu, rs = s_rs;
    float4 gv = ((const float4*)g)[tid];
    float4 bv = ((const float4*)b)[tid];
    float4 o;
    o.x = to_tf32((v.x - mu) * rs * gv.x + bv.x);
    o.y = to_tf32((v.y - mu) * rs * gv.y + bv.y);
    o.z = to_tf32((v.z - mu) * rs * gv.z + bv.z);
    o.w = to_tf32((v.w - mu) * rs * gv.w + bv.w);
    ((float4*)(y + row * DIMV))[tid] = o;
}

// ---------------- residual add + LN(ln2) + LN(fcln) fused ----------------
__global__ void add_dln_kernel(const float* __restrict__ x, const float* __restrict__ oatt,
                               const float* __restrict__ g2, const float* __restrict__ b2,
                               const float* __restrict__ gf, const float* __restrict__ bf,
                               float* __restrict__ x2, float* __restrict__ h2)
{
    __shared__ float s_a[8], s_b[8];
    __shared__ float s_mu, s_rs;
    size_t row = blockIdx.x;
    int tid = threadIdx.x;
    float4 v  = ((const float4*)(x    + row * DIMV))[tid];
    float4 ov = ((const float4*)(oatt + row * DIMV))[tid];
    v.x += ov.x; v.y += ov.y; v.z += ov.z; v.w += ov.w;
    ((float4*)(x2 + row * DIMV))[tid] = v;

    float sum = v.x + v.y + v.z + v.w;
    float sq  = v.x*v.x + v.y*v.y + v.z*v.z + v.w*v.w;
    #pragma unroll
    for (int o = 16; o; o >>= 1) {
        sum += __shfl_xor_sync(0xffffffffu, sum, o);
        sq  += __shfl_xor_sync(0xffffffffu, sq,  o);
    }
    if ((tid & 31) == 0) { s_a[tid >> 5] = sum; s_b[tid >> 5] = sq; }
    __syncthreads();
    if (tid == 0) {
        float ts = 0.f, tq = 0.f;
        #pragma unroll
        for (int i = 0; i < 8; i++) { ts += s_a[i]; tq += s_b[i]; }
        float mu  = ts * (1.0f / DIMV);
        float var = tq * (1.0f / DIMV) - mu * mu;
        s_mu = mu; s_rs = rsqrtf(var + 1e-5f);
    }
    __syncthreads();
    float mu1 = s_mu, rs1 = s_rs;
    float4 g2v = ((const float4*)g2)[tid];
    float4 b2v = ((const float4*)b2)[tid];
    float4 t;
    t.x = (v.x - mu1) * rs1 * g2v.x + b2v.x;
    t.y = (v.y - mu1) * rs1 * g2v.y + b2v.y;
    t.z = (v.z - mu1) * rs1 * g2v.z + b2v.z;
    t.w = (v.w - mu1) * rs1 * g2v.w + b2v.w;

    float sum2 = t.x + t.y + t.z + t.w;
    float sq2  = t.x*t.x + t.y*t.y + t.z*t.z + t.w*t.w;
    #pragma unroll
    for (int o = 16; o; o >>= 1) {
        sum2 += __shfl_xor_sync(0xffffffffu, sum2, o);
        sq2  += __shfl_xor_sync(0xffffffffu, sq2,  o);
    }
    if ((tid & 31) == 0) { s_a[tid >> 5] = sum2; s_b[tid >> 5] = sq2; }
    __syncthreads();
    if (tid == 0) {
        float ts = 0.f, tq = 0.f;
        #pragma unroll
        for (int i = 0; i < 8; i++) { ts += s_a[i]; tq += s_b[i]; }
        float mu  = ts * (1.0f / DIMV);
        float var = tq * (1.0f / DIMV) - mu * mu;
        s_mu = mu; s_rs = rsqrtf(var + 1e-5f);
    }
    __syncthreads();
    float mu2 = s_mu, rs2 = s_rs;
    float4 gfv = ((const float4*)gf)[tid];
    float4 bfv = ((const float4*)bf)[tid];
    float4 o;
    o.x = to_tf32((t.x - mu2) * rs2 * gfv.x + bfv.x);
    o.y = to_tf32((t.y - mu2) * rs2 * gfv.y + bfv.y);
    o.z = to_tf32((t.z - mu2) * rs2 * gfv.z + bfv.z);
    o.w = to_tf32((t.w - mu2) * rs2 * gfv.w + bfv.w);
    ((float4*)(h2 + row * DIMV))[tid] = o;
}

// ---------------- mma.sync tf32 GEMM (unchanged from R4) ----------------
template<int ACT, int RES, int RND>
__global__ void __launch_bounds__(256) gemm_mma(
    const float* __restrict__ A, const float* __restrict__ Bt,
    const float* __restrict__ bias, const float* __restrict__ resid,
    float* __restrict__ C, int N, int K)
{
    extern __shared__ float sm[];
    const int tid  = threadIdx.x;
    const int lane = tid & 31;
    const int warp = tid >> 5;
    const int wm = warp >> 2;
    const int wn = warp & 3;
    const int m0 = blockIdx.y * BM;
    const int n0 = blockIdx.x * BN;
    const int KT = K / BKS;

    const int lrow = tid >> 2;
    const int lkc  = (tid & 3) * 4;

    const float* Asrc0 = A  + (size_t)(m0 + lrow)      * K + lkc;
    const float* Asrc1 = A  + (size_t)(m0 + lrow + 64) * K + lkc;
    const float* Bsrc0 = Bt + (size_t)(n0 + lrow)      * K + lkc;
    const float* Bsrc1 = Bt + (size_t)(n0 + lrow + 64) * K + lkc;

    const uint32_t smb = smem_u32(sm);
    const uint32_t dA0 = smb + ((lrow)      * 20 + lkc) * 4;
    const uint32_t dA1 = smb + ((lrow + 64) * 20 + lkc) * 4;
    const uint32_t dB0 = dA0 + TILE_F * 4;
    const uint32_t dB1 = dA1 + TILE_F * 4;

    #pragma unroll
    for (int s = 0; s < 2; s++) {
        uint32_t off = s * STAGE_F * 4;
        int k0 = s * BKS;
        cp_async16(dA0 + off, Asrc0 + k0);
        cp_async16(dA1 + off, Asrc1 + k0);
        cp_async16(dB0 + off, Bsrc0 + k0);
        cp_async16(dB1 + off, Bsrc1 + k0);
        CP_COMMIT();
    }

    float acc[4][4][4] = {};
    const int gr = lane >> 2;
    const int tg = lane & 3;

    for (int kt = 0; kt < KT; kt++) {
        CP_WAIT1();
        __syncthreads();
        const float* As = sm + (kt % 3) * STAGE_F;
        const float* Bs = As + TILE_F;

        #pragma unroll
        for (int ks = 0; ks < 16; ks += 8) {
            uint32_t af[4][4], bf[4][2];
            #pragma unroll
            for (int mb = 0; mb < 4; mb++) {
                int r = wm * 64 + mb * 16 + gr;
                af[mb][0] = __float_as_uint(As[(r)     * 20 + ks + tg]);
                af[mb][1] = __float_as_uint(As[(r + 8) * 20 + ks + tg]);
                af[mb][2] = __float_as_uint(As[(r)     * 20 + ks + 4 + tg]);
                af[mb][3] = __float_as_uint(As[(r + 8) * 20 + ks + 4 + tg]);
            }
            #pragma unroll
            for (int nb = 0; nb < 4; nb++) {
                int c = wn * 32 + nb * 8 + gr;
                bf[nb][0] = __float_as_uint(Bs[c * 20 + ks + tg]);
                bf[nb][1] = __float_as_uint(Bs[c * 20 + ks + 4 + tg]);
            }
            #pragma unroll
            for (int mb = 0; mb < 4; mb++)
                #pragma unroll
                for (int nb = 0; nb < 4; nb++)
                    mma_tf32(acc[mb][nb], af[mb], bf[nb]);
        }

        if (kt + 2 < KT) {
            uint32_t off = ((kt + 2) % 3) * STAGE_F * 4;
            int k0 = (kt + 2) * BKS;
            cp_async16(dA0 + off, Asrc0 + k0);
            cp_async16(dA1 + off, Asrc1 + k0);
            cp_async16(dB0 + off, Bsrc0 + k0);
            cp_async16(dB1 + off, Bsrc1 + k0);
        }
        CP_COMMIT();
        __syncthreads();
    }

    #pragma unroll
    for (int mb = 0; mb < 4; mb++) {
        int rlo = m0 + wm * 64 + mb * 16 + gr;
        #pragma unroll
        for (int nb = 0; nb < 4; nb++) {
            int col = n0 + wn * 32 + nb * 8 + tg * 2;
            float2 bi = *(const float2*)(bias + col);
            #pragma unroll
            for (int half = 0; half < 2; half++) {
                int row = rlo + half * 8;
                float v0 = acc[mb][nb][half * 2 + 0] + bi.x;
                float v1 = acc[mb][nb][half * 2 + 1] + bi.y;
                if (ACT) { v0 = gelu_exact(v0); v1 = gelu_exact(v1); }
                if (RND) { v0 = to_tf32(v0);    v1 = to_tf32(v1); }
                if (RES) {
                    float2 rv = *(const float2*)(resid + (size_t)row * N + col);
                    v0 += rv.x; v1 += rv.y;
                }
                float2 o2; o2.x = v0; o2.y = v1;
                *(float2*)(C + (size_t)row * N + col) = o2;
            }
        }
    }
}

// ---------------- tensor-core flash attention ----------------
// block: 128 threads (4 warps), 64 q-rows per block, one (b,h).
// warp w owns q-rows [w*16, w*16+16). K/V tiles 64x64 double-buffered cp.async.
__global__ void __launch_bounds__(128) attn_kernel(
    const float* __restrict__ QKV, float* __restrict__ O)
{
    extern __shared__ float sma[];
    float* Ks = sma;                    // [2][64][AT_PAD]
    float* Vs = sma + 2 * AT_TILE;      // [2][64][AT_PAD]
    float* Ps = sma + 4 * AT_TILE;      // [64][AT_PAD]

    const int qt = blockIdx.x;
    const int bh = blockIdx.y;
    const int b  = bh >> 4;
    const int h  = bh & 15;
    const int tid  = threadIdx.x;
    const int lane = tid & 31;
    const int w    = tid >> 5;
    const int gr   = lane >> 2;
    const int tg   = lane & 3;

    const float* Qb = QKV + (size_t)b * SEQ * QKV_LD + h * HDIMV;
    const float* Kb = Qb + 1024;
    const float* Vb = Qb + 2048;

    const uint32_t smb  = smem_u32(sma);
    const uint32_t KsB  = smb;
    const uint32_t VsB  = smb + 2 * AT_TILE * 4;

    // ---- stage Q tile into Ps (scaled + tf32), then to registers ----
    #pragma unroll
    for (int j = 0; j < 8; j++) {
        int idx = j * 128 + tid;          // 0..1023 float4 chunks
        int r  = idx >> 4;
        int c4 = (idx & 15) * 4;
        float4 qv = *(const float4*)(Qb + (size_t)(qt * 64 + r) * QKV_LD + c4);
        Ps[r * AT_PAD + c4 + 0] = to_tf32(qv.x * 0.125f);
        Ps[r * AT_PAD + c4 + 1] = to_tf32(qv.y * 0.125f);
        Ps[r * AT_PAD + c4 + 2] = to_tf32(qv.z * 0.125f);
        Ps[r * AT_PAD + c4 + 3] = to_tf32(qv.w * 0.125f);
    }
    __syncthreads();
    uint32_t qf[8][4];
    {
        const int r = w * 16 + gr;
        #pragma unroll
        for (int kb = 0; kb < 8; kb++) {
            qf[kb][0] = __float_as_uint(Ps[(r)     * AT_PAD + kb * 8 + tg]);
            qf[kb][1] = __float_as_uint(Ps[(r + 8) * AT_PAD + kb * 8 + tg]);
            qf[kb][2] = __float_as_uint(Ps[(r)     * AT_PAD + kb * 8 + 4 + tg]);
            qf[kb][3] = __float_as_uint(Ps[(r + 8) * AT_PAD + kb * 8 + 4 + tg]);
        }
    }
    __syncthreads();

    // ---- prologue: load K/V tile 0 ----
    #pragma unroll
    for (int j = 0; j < 8; j++) {
        int idx = j * 128 + tid;
        int r  = idx >> 4;
        int c4 = (idx & 15) * 4;
        uint32_t doff = (r * AT_PAD + c4) * 4;
        cp_async16(KsB + doff, Kb + (size_t)r * QKV_LD + c4);
        cp_async16(VsB + doff, Vb + (size_t)r * QKV_LD + c4);
    }
    CP_COMMIT();

    float oacc[8][4] = {};
    float rm[2] = { -3e38f, -3e38f };
    float rl[2] = { 0.f, 0.f };

    for (int kt = 0; kt <= qt; kt++) {
        const int buf = kt & 1;
        if (kt < qt) {
            const int nbuf = (kt + 1) & 1;
            const size_t krow0 = (size_t)(kt + 1) * 64;
            #pragma unroll
            for (int j = 0; j < 8; j++) {
                int idx = j * 128 + tid;
                int r  = idx >> 4;
                int c4 = (idx & 15) * 4;
                uint32_t doff = (nbuf * AT_TILE + r * AT_PAD + c4) * 4;
                cp_async16(KsB + doff, Kb + (krow0 + r) * QKV_LD + c4);
                cp_async16(VsB + doff, Vb + (krow0 + r) * QKV_LD + c4);
            }
            CP_COMMIT();
            CP_WAIT1();
        } else {
            CP_WAIT0();
        }
        __syncthreads();

        const float* Kt = Ks + buf * AT_TILE;
        const float* Vt = Vs + buf * AT_TILE;

        // ---- S = Q @ K^T ----
        float s[8][4] = {};
        #pragma unroll
        for (int kb = 0; kb < 8; kb++) {
            uint32_t bf[8][2];
            #pragma unroll
            for (int nb = 0; nb < 8; nb++) {
                int t = nb * 8 + gr;
                bf[nb][0] = to_tf32_u(Kt[t * AT_PAD + kb * 8 + tg]);
                bf[nb][1] = to_tf32_u(Kt[t * AT_PAD + kb * 8 + 4 + tg]);
            }
            #pragma unroll
            for (int nb = 0; nb < 8; nb++)
                mma_tf32(s[nb], qf[kb], bf[nb]);
        }

        // ---- causal mask on diagonal tile ----
        if (kt == qt) {
            #pragma unroll
            for (int nb = 0; nb < 8; nb++)
                #pragma unroll
                for (int e = 0; e < 4; e++) {
                    int row = w * 16 + gr + (e >> 1) * 8;
                    int col = nb * 8 + tg * 2 + (e & 1);
                    if (col > row) s[nb][e] = -3e38f;
                }
        }

        // ---- online softmax (register row stats, quad shuffle) ----
        float alpha[2];
        #pragma unroll
        for (int hh = 0; hh < 2; hh++) {
            float mloc = -3e38f;
            #pragma unroll
            for (int nb = 0; nb < 8; nb++) {
                mloc = fmaxf(mloc, s[nb][hh * 2 + 0]);
                mloc = fmaxf(mloc, s[nb][hh * 2 + 1]);
            }
            mloc = fmaxf(mloc, __shfl_xor_sync(0xffffffffu, mloc, 1));
            mloc = fmaxf(mloc, __shfl_xor_sync(0xffffffffu, mloc, 2));
            float mnew = fmaxf(rm[hh], mloc);
            alpha[hh] = __expf(rm[hh] - mnew);
            float suml = 0.f;
            #pragma unroll
            for (int nb = 0; nb < 8; nb++) {
                float p0 = __expf(s[nb][hh * 2 + 0] - mnew);
                float p1 = __expf(s[nb][hh * 2 + 1] - mnew);
                s[nb][hh * 2 + 0] = p0;
                s[nb][hh * 2 + 1] = p1;
                suml += p0 + p1;
            }
            suml += __shfl_xor_sync(0xffffffffu, suml, 1);
            suml += __shfl_xor_sync(0xffffffffu, suml, 2);
            rl[hh] = rl[hh] * alpha[hh] + suml;
            rm[hh] = mnew;
        }

        // rescale O accumulator
        #pragma unroll
        for (int nb = 0; nb < 8; nb++) {
            oacc[nb][0] *= alpha[0]; oacc[nb][1] *= alpha[0];
            oacc[nb][2] *= alpha[1]; oacc[nb][3] *= alpha[1];
        }

        // ---- write P strip (tf32) to smem, reload as A fragments ----
        {
            int r0s = w * 16 + gr;
            #pragma unroll
            for (int nb = 0; nb < 8; nb++) {
                Ps[(r0s)     * AT_PAD + nb * 8 + tg * 2 + 0] = to_tf32(s[nb][0]);
                Ps[(r0s)     * AT_PAD + nb * 8 + tg * 2 + 1] = to_tf32(s[nb][1]);
                Ps[(r0s + 8) * AT_PAD + nb * 8 + tg * 2 + 0] = to_tf32(s[nb][2]);
                Ps[(r0s + 8) * AT_PAD + nb * 8 + tg * 2 + 1] = to_tf32(s[nb][3]);
            }
        }
        __syncwarp();

        // ---- O += P @ V ----
        {
            const int r = w * 16 + gr;
            #pragma unroll
            for (int kb = 0; kb < 8; kb++) {
                uint32_t af[4];
                af[0] = __float_as_uint(Ps[(r)     * AT_PAD + kb * 8 + tg]);
                af[1] = __float_as_uint(Ps[(r + 8) * AT_PAD + kb * 8 + tg]);
                af[2] = __float_as_uint(Ps[(r)     * AT_PAD + kb * 8 + 4 + tg]);
                af[3] = __float_as_uint(Ps[(r + 8) * AT_PAD + kb * 8 + 4 + tg]);
                uint32_t bf[8][2];
                #pragma unroll
                for (int nb = 0; nb < 8; nb++) {
                    int d = nb * 8 + gr;
                    bf[nb][0] = to_tf32_u(Vt[(kb * 8 + tg)     * AT_PAD + d]);
                    bf[nb][1] = to_tf32_u(Vt[(kb * 8 + 4 + tg) * AT_PAD + d]);
                }
                #pragma unroll
                for (int nb = 0; nb < 8; nb++)
                    mma_tf32(oacc[nb], af, bf[nb]);
            }
        }
        __syncthreads();   // protect K/V/P buffers before next iteration's loads
    }

    // ---- normalize + write (concat-head layout) ----
    float linv0 = 1.0f / rl[0];
    float linv1 = 1.0f / rl[1];
    #pragma unroll
    for (int hh = 0; hh < 2; hh++) {
        size_t row = (size_t)b * SEQ + (size_t)(qt * 64 + w * 16 + gr + hh * 8);
        float linv = hh ? linv1 : linv0;
        #pragma unroll
        for (int nb = 0; nb < 8; nb++) {
            float2 o2;
            o2.x = oacc[nb][hh * 2 + 0] * linv;
            o2.y = oacc[nb][hh * 2 + 1] * linv;
            *(float2*)(O + row * DIMV + h * HDIMV + nb * 8 + tg * 2) = o2;
        }
    }
}

extern "C" void kernel_launch(void* const* d_in, const int* in_sizes, int n_in,
                              void* d_out, int out_size)
{
    const float* x    = (const float*)d_in[0];
    const float* ln1g = (const float*)d_in[1];
    const float* ln1b = (const float*)d_in[2];
    const float* Wq   = (const float*)d_in[3];
    const float* bq   = (const float*)d_in[4];
    const float* Wk   = (const float*)d_in[5];
    const float* bk   = (const float*)d_in[6];
    const float* Wv   = (const float*)d_in[7];
    const float* bv   = (const float*)d_in[8];
    const float* ln2g = (const float*)d_in[9];
    const float* ln2b = (const float*)d_in[10];
    const float* fclg = (const float*)d_in[11];
    const float* fclb = (const float*)d_in[12];
    const float* W1   = (const float*)d_in[13];
    const float* b1   = (const float*)d_in[14];
    const float* W2   = (const float*)d_in[15];
    const float* b2   = (const float*)d_in[16];
    float* out = (float*)d_out;

    float *p_h, *p_qkv, *p_o, *p_x2, *p_h2, *p_mid, *p_wt, *p_w1t, *p_w2t, *p_bqkv;
    cudaGetSymbolAddress((void**)&p_h,    g_h);
    cudaGetSymbolAddress((void**)&p_qkv,  g_qkv);
    cudaGetSymbolAddress((void**)&p_o,    g_o);
    cudaGetSymbolAddress((void**)&p_x2,   g_x2);
    cudaGetSymbolAddress((void**)&p_h2,   g_h2);
    cudaGetSymbolAddress((void**)&p_mid,  g_mid);
    cudaGetSymbolAddress((void**)&p_wt,   g_wt);
    cudaGetSymbolAddress((void**)&p_w1t,  g_w1t);
    cudaGetSymbolAddress((void**)&p_w2t,  g_w2t);
    cudaGetSymbolAddress((void**)&p_bqkv, g_bqkv);

    cudaFuncSetAttribute(attn_kernel, cudaFuncAttributeMaxDynamicSharedMemorySize, ATTN_SMEM_B);
    cudaFuncSetAttribute(gemm_mma<0,0,0>, cudaFuncAttributeMaxDynamicSharedMemorySize, GEMM_SMEM_BYTES);
    cudaFuncSetAttribute(gemm_mma<1,0,1>, cudaFuncAttributeMaxDynamicSharedMemorySize, GEMM_SMEM_BYTES);
    cudaFuncSetAttribute(gemm_mma<1,1,0>, cudaFuncAttributeMaxDynamicSharedMemorySize, GEMM_SMEM_BYTES);

    transpose_qkv_kernel<<<dim3(2, 32, 48), dim3(32, 8)>>>(Wq, Wk, Wv, p_wt);
    transpose_kernel<<<dim3(HIDV / 32, DIMV / 32), dim3(32, 8)>>>(W1, p_w1t, DIMV, HIDV);
    transpose_kernel<<<dim3(DIMV / 32, HIDV / 32), dim3(32, 8)>>>(W2, p_w2t, HIDV, DIMV);
    pack_bias_kernel<<<QKV_LD / 256, 256>>>(bq, bk, bv, p_bqkv);
    ln_kernel<<<NTOK, 256>>>(x, ln1g, ln1b, p_h);
    gemm_mma<0,0,0><<<dim3(QKV_LD / BN, NTOK / BM), 256, GEMM_SMEM_BYTES>>>(
        p_h, p_wt, p_bqkv, nullptr, p_qkv, QKV_LD, DIMV);
    attn_kernel<<<dim3(SEQ / 64, 64), 128, ATTN_SMEM_B>>>(p_qkv, p_o);
    add_dln_kernel<<<NTOK, 256>>>(x, p_o, ln2g, ln2b, fclg, fclb, p_x2, p_h2);
    gemm_mma<1,0,1><<<dim3(HIDV / BN, NTOK / BM), 256, GEMM_SMEM_BYTES>>>(
        p_h2, p_w1t, b1, nullptr, p_mid, HIDV, DIMV);
    gemm_mma<1,1,0><<<dim3(DIMV / BN, NTOK / BM), 256, GEMM_SMEM_BYTES>>>(
        p_mid, p_w2t, b2, p_x2, out, DIMV, HIDV);
}

// round 6
// speedup vs baseline: 6.5363x; 1.3458x over previous
#include <cuda_runtime.h>
#include <cuda_bf16.h>
#include <cstdint>
#include <cstddef>

// Problem dims
#define DIMV   1024
#define HIDV   4096
#define SEQ    2048
#define NHEAD  16
#define HDIMV  64
#define NTOK   8192          // B * S
#define QKV_LD 3072          // fused QKV row stride

// tf32 GEMM tiling (QKV projection)
#define BM 128
#define BN 128
#define BKS 16
#define TILE_F 2560          // 128 rows * 20 padded floats
#define STAGE_F 5120
#define GEMM_SMEM_BYTES (3 * STAGE_F * 4)   // 61440

// bf16 GEMM tiling (MLP): 128x128 tile, 32 K per stage, same b32 footprint
#define BKS16 32
#define TILE_H 2560          // 128 rows * 20 b32 (40 bf16 padded)
#define STAGE_H 5120

// attention smem
#define AT_PAD 68
#define AT_TILE (64 * AT_PAD)
#define ATTN_SMEM_B ((4 * AT_TILE + AT_TILE) * 4)  // 87040 B

// ---------------- static scratch ----------------
__device__ float g_h   [(size_t)NTOK * DIMV];
__device__ float g_qkv [(size_t)NTOK * QKV_LD];
__device__ float g_o   [(size_t)NTOK * DIMV];
__device__ float g_x2  [(size_t)NTOK * DIMV];
__device__ __nv_bfloat16 g_h2 [(size_t)NTOK * DIMV];
__device__ __nv_bfloat16 g_mid[(size_t)NTOK * HIDV];
__device__ float g_wt  [(size_t)QKV_LD * DIMV];
__device__ __nv_bfloat16 g_w1t[(size_t)HIDV * DIMV];
__device__ __nv_bfloat16 g_w2t[(size_t)DIMV * HIDV];
__device__ float g_bqkv[QKV_LD];

// ---------------- helpers ----------------
__device__ __forceinline__ uint32_t smem_u32(const void* p) {
    uint32_t a;
    asm("{ .reg .u64 t; cvta.to.shared.u64 t, %1; cvt.u32.u64 %0, t; }" : "=r"(a) : "l"(p));
    return a;
}

__device__ __forceinline__ float to_tf32(float x) {
    uint32_t r;
    asm("cvt.rna.tf32.f32 %0, %1;" : "=r"(r) : "f"(x));
    return __uint_as_float(r);
}

__device__ __forceinline__ uint32_t to_tf32_u(float x) {
    uint32_t r;
    asm("cvt.rna.tf32.f32 %0, %1;" : "=r"(r) : "f"(x));
    return r;
}

__device__ __forceinline__ float gelu_exact(float x) {
    return 0.5f * x * (1.0f + erff(x * 0.70710678118654752f));
}

__device__ __forceinline__ void cp_async16(uint32_t dst, const void* src) {
    asm volatile("cp.async.cg.shared.global [%0], [%1], 16;" :: "r"(dst), "l"(src));
}
#define CP_COMMIT() asm volatile("cp.async.commit_group;" ::: "memory")
#define CP_WAIT1()  asm volatile("cp.async.wait_group 1;" ::: "memory")
#define CP_WAIT0()  asm volatile("cp.async.wait_group 0;" ::: "memory")

__device__ __forceinline__ void mma_tf32(float* c, const uint32_t* a, const uint32_t* b) {
    asm volatile(
        "mma.sync.aligned.m16n8k8.row.col.f32.tf32.tf32.f32 "
        "{%0,%1,%2,%3}, {%4,%5,%6,%7}, {%8,%9}, {%0,%1,%2,%3};"
        : "+f"(c[0]), "+f"(c[1]), "+f"(c[2]), "+f"(c[3])
        : "r"(a[0]), "r"(a[1]), "r"(a[2]), "r"(a[3]), "r"(b[0]), "r"(b[1]));
}

__device__ __forceinline__ void mma_bf16(float* c, const uint32_t* a, const uint32_t* b) {
    asm volatile(
        "mma.sync.aligned.m16n8k16.row.col.f32.bf16.bf16.f32 "
        "{%0,%1,%2,%3}, {%4,%5,%6,%7}, {%8,%9}, {%0,%1,%2,%3};"
        : "+f"(c[0]), "+f"(c[1]), "+f"(c[2]), "+f"(c[3])
        : "r"(a[0]), "r"(a[1]), "r"(a[2]), "r"(a[3]), "r"(b[0]), "r"(b[1]));
}

// ---------------- weight transposes ----------------
__global__ void transpose_kernel_b16(const float* __restrict__ src, __nv_bfloat16* __restrict__ dst,
                                     int R, int C)
{
    __shared__ float t[32][33];
    int c0 = blockIdx.x * 32, r0 = blockIdx.y * 32;
    int tx = threadIdx.x, ty = threadIdx.y;
    #pragma unroll
    for (int i = 0; i < 32; i += 8)
        t[ty + i][tx] = src[(size_t)(r0 + ty + i) * C + c0 + tx];
    __syncthreads();
    #pragma unroll
    for (int i = 0; i < 32; i += 8)
        dst[(size_t)(c0 + ty + i) * R + r0 + tx] = __float2bfloat16_rn(t[tx][ty + i]);
}

__global__ void transpose_qkv_kernel(const float* __restrict__ Wq, const float* __restrict__ Wk,
                                     const float* __restrict__ Wv, float* __restrict__ dst)
{
    __shared__ float t[32][33];
    int s = blockIdx.z, w = s >> 4, h = s & 15;
    const float* W = ((w == 0) ? Wq : (w == 1) ? Wk : Wv) + (size_t)h * DIMV * HDIMV;
    float* D = dst + (size_t)(w * 1024 + h * 64) * DIMV;
    int c0 = blockIdx.x * 32, r0 = blockIdx.y * 32;
    int tx = threadIdx.x, ty = threadIdx.y;
    #pragma unroll
    for (int i = 0; i < 32; i += 8)
        t[ty + i][tx] = W[(size_t)(r0 + ty + i) * HDIMV + c0 + tx];
    __syncthreads();
    #pragma unroll
    for (int i = 0; i < 32; i += 8)
        D[(size_t)(c0 + ty + i) * DIMV + r0 + tx] = to_tf32(t[tx][ty + i]);
}

__global__ void pack_bias_kernel(const float* __restrict__ bq, const float* __restrict__ bk,
                                 const float* __restrict__ bv, float* __restrict__ dst)
{
    int i = blockIdx.x * 256 + threadIdx.x;
    float v = (i < 1024) ? bq[i] : (i < 2048) ? bk[i - 1024] : bv[i - 2048];
    dst[i] = v;
}

// ---------------- LayerNorm (tf32-rounded output) ----------------
__global__ void ln_kernel(const float* __restrict__ x, const float* __restrict__ g,
                          const float* __restrict__ b, float* __restrict__ y)
{
    __shared__ float s_a[8], s_b[8];
    __shared__ float s_mu, s_rs;
    size_t row = blockIdx.x;
    int tid = threadIdx.x;
    float4 v = ((const float4*)(x + row * DIMV))[tid];
    float sum = v.x + v.y + v.z + v.w;
    float sq  = v.x*v.x + v.y*v.y + v.z*v.z + v.w*v.w;
    #pragma unroll
    for (int o = 16; o; o >>= 1) {
        sum += __shfl_xor_sync(0xffffffffu, sum, o);
        sq  += __shfl_xor_sync(0xffffffffu, sq,  o);
    }
    if ((tid & 31) == 0) { s_a[tid >> 5] = sum; s_b[tid >> 5] = sq; }
    __syncthreads();
    if (tid == 0) {
        float ts = 0.f, tq = 0.f;
        #pragma unroll
        for (int i = 0; i < 8; i++) { ts += s_a[i]; tq += s_b[i]; }
        float mu  = ts * (1.0f / DIMV);
        float var = tq * (1.0f / DIMV) - mu * mu;
        s_mu = mu; s_rs = rsqrtf(var + 1e-5f);
    }
    __syncthreads();
    float mu = s_mu, rs = s_rs;
    float4 gv = ((const float4*)g)[tid];
    float4 bv = ((const float4*)b)[tid];
    float4 o;
    o.x = to_tf32((v.x - mu) * rs * gv.x + bv.x);
    o.y = to_tf32((v.y - mu) * rs * gv.y + bv.y);
    o.z = to_tf32((v.z - mu) * rs * gv.z + bv.z);
    o.w = to_tf32((v.w - mu) * rs * gv.w + bv.w);
    ((float4*)(y + row * DIMV))[tid] = o;
}

// ---------------- residual add + LN(ln2) + LN(fcln), h2 out bf16 ----------------
__global__ void add_dln_kernel(const float* __restrict__ x, const float* __restrict__ oatt,
                               const float* __restrict__ g2, const float* __restrict__ b2,
                               const float* __restrict__ gf, const float* __restrict__ bf,
                               float* __restrict__ x2, __nv_bfloat16* __restrict__ h2)
{
    __shared__ float s_a[8], s_b[8];
    __shared__ float s_mu, s_rs;
    size_t row = blockIdx.x;
    int tid = threadIdx.x;
    float4 v  = ((const float4*)(x    + row * DIMV))[tid];
    float4 ov = ((const float4*)(oatt + row * DIMV))[tid];
    v.x += ov.x; v.y += ov.y; v.z += ov.z; v.w += ov.w;
    ((float4*)(x2 + row * DIMV))[tid] = v;

    float sum = v.x + v.y + v.z + v.w;
    float sq  = v.x*v.x + v.y*v.y + v.z*v.z + v.w*v.w;
    #pragma unroll
    for (int o = 16; o; o >>= 1) {
        sum += __shfl_xor_sync(0xffffffffu, sum, o);
        sq  += __shfl_xor_sync(0xffffffffu, sq,  o);
    }
    if ((tid & 31) == 0) { s_a[tid >> 5] = sum; s_b[tid >> 5] = sq; }
    __syncthreads();
    if (tid == 0) {
        float ts = 0.f, tq = 0.f;
        #pragma unroll
        for (int i = 0; i < 8; i++) { ts += s_a[i]; tq += s_b[i]; }
        float mu  = ts * (1.0f / DIMV);
        float var = tq * (1.0f / DIMV) - mu * mu;
        s_mu = mu; s_rs = rsqrtf(var + 1e-5f);
    }
    __syncthreads();
    float mu1 = s_mu, rs1 = s_rs;
    float4 g2v = ((const float4*)g2)[tid];
    float4 b2v = ((const float4*)b2)[tid];
    float4 t;
    t.x = (v.x - mu1) * rs1 * g2v.x + b2v.x;
    t.y = (v.y - mu1) * rs1 * g2v.y + b2v.y;
    t.z = (v.z - mu1) * rs1 * g2v.z + b2v.z;
    t.w = (v.w - mu1) * rs1 * g2v.w + b2v.w;

    float sum2 = t.x + t.y + t.z + t.w;
    float sq2  = t.x*t.x + t.y*t.y + t.z*t.z + t.w*t.w;
    #pragma unroll
    for (int o = 16; o; o >>= 1) {
        sum2 += __shfl_xor_sync(0xffffffffu, sum2, o);
        sq2  += __shfl_xor_sync(0xffffffffu, sq2,  o);
    }
    if ((tid & 31) == 0) { s_a[tid >> 5] = sum2; s_b[tid >> 5] = sq2; }
    __syncthreads();
    if (tid == 0) {
        float ts = 0.f, tq = 0.f;
        #pragma unroll
        for (int i = 0; i < 8; i++) { ts += s_a[i]; tq += s_b[i]; }
        float mu  = ts * (1.0f / DIMV);
        float var = tq * (1.0f / DIMV) - mu * mu;
        s_mu = mu; s_rs = rsqrtf(var + 1e-5f);
    }
    __syncthreads();
    float mu2 = s_mu, rs2 = s_rs;
    float4 gfv = ((const float4*)gf)[tid];
    float4 bfv = ((const float4*)bf)[tid];
    __nv_bfloat162 h0, h1;
    h0.x = __float2bfloat16_rn((t.x - mu2) * rs2 * gfv.x + bfv.x);
    h0.y = __float2bfloat16_rn((t.y - mu2) * rs2 * gfv.y + bfv.y);
    h1.x = __float2bfloat16_rn((t.z - mu2) * rs2 * gfv.z + bfv.z);
    h1.y = __float2bfloat16_rn((t.w - mu2) * rs2 * gfv.w + bfv.w);
    ((__nv_bfloat162*)(h2 + row * DIMV))[tid * 2 + 0] = h0;
    ((__nv_bfloat162*)(h2 + row * DIMV))[tid * 2 + 1] = h1;
}

// ---------------- tf32 GEMM (QKV projection) ----------------
template<int ACT, int RES, int RND>
__global__ void __launch_bounds__(256) gemm_mma(
    const float* __restrict__ A, const float* __restrict__ Bt,
    const float* __restrict__ bias, const float* __restrict__ resid,
    float* __restrict__ C, int N, int K)
{
    extern __shared__ float sm[];
    const int tid  = threadIdx.x;
    const int lane = tid & 31;
    const int warp = tid >> 5;
    const int wm = warp >> 2;
    const int wn = warp & 3;
    const int m0 = blockIdx.y * BM;
    const int n0 = blockIdx.x * BN;
    const int KT = K / BKS;

    const int lrow = tid >> 2;
    const int lkc  = (tid & 3) * 4;

    const float* Asrc0 = A  + (size_t)(m0 + lrow)      * K + lkc;
    const float* Asrc1 = A  + (size_t)(m0 + lrow + 64) * K + lkc;
    const float* Bsrc0 = Bt + (size_t)(n0 + lrow)      * K + lkc;
    const float* Bsrc1 = Bt + (size_t)(n0 + lrow + 64) * K + lkc;

    const uint32_t smb = smem_u32(sm);
    const uint32_t dA0 = smb + ((lrow)      * 20 + lkc) * 4;
    const uint32_t dA1 = smb + ((lrow + 64) * 20 + lkc) * 4;
    const uint32_t dB0 = dA0 + TILE_F * 4;
    const uint32_t dB1 = dA1 + TILE_F * 4;

    #pragma unroll
    for (int s = 0; s < 2; s++) {
        uint32_t off = s * STAGE_F * 4;
        int k0 = s * BKS;
        cp_async16(dA0 + off, Asrc0 + k0);
        cp_async16(dA1 + off, Asrc1 + k0);
        cp_async16(dB0 + off, Bsrc0 + k0);
        cp_async16(dB1 + off, Bsrc1 + k0);
        CP_COMMIT();
    }

    float acc[4][4][4] = {};
    const int gr = lane >> 2;
    const int tg = lane & 3;

    for (int kt = 0; kt < KT; kt++) {
        CP_WAIT1();
        __syncthreads();
        const float* As = sm + (kt % 3) * STAGE_F;
        const float* Bs = As + TILE_F;

        #pragma unroll
        for (int ks = 0; ks < 16; ks += 8) {
            uint32_t af[4][4], bf[4][2];
            #pragma unroll
            for (int mb = 0; mb < 4; mb++) {
                int r = wm * 64 + mb * 16 + gr;
                af[mb][0] = __float_as_uint(As[(r)     * 20 + ks + tg]);
                af[mb][1] = __float_as_uint(As[(r + 8) * 20 + ks + tg]);
                af[mb][2] = __float_as_uint(As[(r)     * 20 + ks + 4 + tg]);
                af[mb][3] = __float_as_uint(As[(r + 8) * 20 + ks + 4 + tg]);
            }
            #pragma unroll
            for (int nb = 0; nb < 4; nb++) {
                int c = wn * 32 + nb * 8 + gr;
                bf[nb][0] = __float_as_uint(Bs[c * 20 + ks + tg]);
                bf[nb][1] = __float_as_uint(Bs[c * 20 + ks + 4 + tg]);
            }
            #pragma unroll
            for (int mb = 0; mb < 4; mb++)
                #pragma unroll
                for (int nb = 0; nb < 4; nb++)
                    mma_tf32(acc[mb][nb], af[mb], bf[nb]);
        }

        if (kt + 2 < KT) {
            uint32_t off = ((kt + 2) % 3) * STAGE_F * 4;
            int k0 = (kt + 2) * BKS;
            cp_async16(dA0 + off, Asrc0 + k0);
            cp_async16(dA1 + off, Asrc1 + k0);
            cp_async16(dB0 + off, Bsrc0 + k0);
            cp_async16(dB1 + off, Bsrc1 + k0);
        }
        CP_COMMIT();
        __syncthreads();
    }

    #pragma unroll
    for (int mb = 0; mb < 4; mb++) {
        int rlo = m0 + wm * 64 + mb * 16 + gr;
        #pragma unroll
        for (int nb = 0; nb < 4; nb++) {
            int col = n0 + wn * 32 + nb * 8 + tg * 2;
            float2 bi = *(const float2*)(bias + col);
            #pragma unroll
            for (int half = 0; half < 2; half++) {
                int row = rlo + half * 8;
                float v0 = acc[mb][nb][half * 2 + 0] + bi.x;
                float v1 = acc[mb][nb][half * 2 + 1] + bi.y;
                if (ACT) { v0 = gelu_exact(v0); v1 = gelu_exact(v1); }
                if (RND) { v0 = to_tf32(v0);    v1 = to_tf32(v1); }
                if (RES) {
                    float2 rv = *(const float2*)(resid + (size_t)row * N + col);
                    v0 += rv.x; v1 += rv.y;
                }
                float2 o2; o2.x = v0; o2.y = v1;
                *(float2*)(C + (size_t)row * N + col) = o2;
            }
        }
    }
}

// ---------------- bf16 GEMM (MLP): C = act(A @ Bt^T + bias) (+res) ----------------
// A [M,K] bf16, Bt [N,K] bf16. 128x128 tile, 32 K per stage, 3-stage cp.async.
// OUT_BF16: write __nv_bfloat16, else fp32.
template<int ACT, int RES, int OUT_BF16>
__global__ void __launch_bounds__(256) gemm_bf16(
    const __nv_bfloat16* __restrict__ A, const __nv_bfloat16* __restrict__ Bt,
    const float* __restrict__ bias, const float* __restrict__ resid,
    void* __restrict__ Cout, int N, int K)
{
    extern __shared__ float sm[];
    uint32_t* smu = (uint32_t*)sm;
    const int tid  = threadIdx.x;
    const int lane = tid & 31;
    const int warp = tid >> 5;
    const int wm = warp >> 2;
    const int wn = warp & 3;
    const int m0 = blockIdx.y * BM;
    const int n0 = blockIdx.x * BN;
    const int KT = K / BKS16;

    const int lrow = tid >> 2;          // 0..63
    const int lk8  = (tid & 3) * 8;     // bf16 element offset 0,8,16,24
    const int lk4  = (tid & 3) * 4;     // b32 offset

    const __nv_bfloat16* Asrc0 = A  + (size_t)(m0 + lrow)      * K + lk8;
    const __nv_bfloat16* Asrc1 = A  + (size_t)(m0 + lrow + 64) * K + lk8;
    const __nv_bfloat16* Bsrc0 = Bt + (size_t)(n0 + lrow)      * K + lk8;
    const __nv_bfloat16* Bsrc1 = Bt + (size_t)(n0 + lrow + 64) * K + lk8;

    const uint32_t smb = smem_u32(sm);
    const uint32_t dA0 = smb + ((lrow)      * 20 + lk4) * 4;
    const uint32_t dA1 = smb + ((lrow + 64) * 20 + lk4) * 4;
    const uint32_t dB0 = dA0 + TILE_H * 4;
    const uint32_t dB1 = dA1 + TILE_H * 4;

    #pragma unroll
    for (int s = 0; s < 2; s++) {
        uint32_t off = s * STAGE_H * 4;
        int k0 = s * BKS16;
        cp_async16(dA0 + off, Asrc0 + k0);
        cp_async16(dA1 + off, Asrc1 + k0);
        cp_async16(dB0 + off, Bsrc0 + k0);
        cp_async16(dB1 + off, Bsrc1 + k0);
        CP_COMMIT();
    }

    float acc[4][4][4] = {};
    const int gr = lane >> 2;
    const int tg = lane & 3;

    for (int kt = 0; kt < KT; kt++) {
        CP_WAIT1();
        __syncthreads();
        const uint32_t* As = smu + (kt % 3) * STAGE_H;
        const uint32_t* Bs = As + TILE_H;

        #pragma unroll
        for (int kc = 0; kc < 2; kc++) {       // two k16 chunks (b32 offset kc*8)
            uint32_t af[4][4], bf[4][2];
            #pragma unroll
            for (int mb = 0; mb < 4; mb++) {
                int r = wm * 64 + mb * 16 + gr;
                af[mb][0] = As[(r)     * 20 + kc * 8 + tg];
                af[mb][1] = As[(r + 8) * 20 + kc * 8 + tg];
                af[mb][2] = As[(r)     * 20 + kc * 8 + 4 + tg];
                af[mb][3] = As[(r + 8) * 20 + kc * 8 + 4 + tg];
            }
            #pragma unroll
            for (int nb = 0; nb < 4; nb++) {
                int c = wn * 32 + nb * 8 + gr;
                bf[nb][0] = Bs[c * 20 + kc * 8 + tg];
                bf[nb][1] = Bs[c * 20 + kc * 8 + 4 + tg];
            }
            #pragma unroll
            for (int mb = 0; mb < 4; mb++)
                #pragma unroll
                for (int nb = 0; nb < 4; nb++)
                    mma_bf16(acc[mb][nb], af[mb], bf[nb]);
        }

        if (kt + 2 < KT) {
            uint32_t off = ((kt + 2) % 3) * STAGE_H * 4;
            int k0 = (kt + 2) * BKS16;
            cp_async16(dA0 + off, Asrc0 + k0);
            cp_async16(dA1 + off, Asrc1 + k0);
            cp_async16(dB0 + off, Bsrc0 + k0);
            cp_async16(dB1 + off, Bsrc1 + k0);
        }
        CP_COMMIT();
        __syncthreads();
    }

    #pragma unroll
    for (int mb = 0; mb < 4; mb++) {
        int rlo = m0 + wm * 64 + mb * 16 + gr;
        #pragma unroll
        for (int nb = 0; nb < 4; nb++) {
            int col = n0 + wn * 32 + nb * 8 + tg * 2;
            float2 bi = *(const float2*)(bias + col);
            #pragma unroll
            for (int half = 0; half < 2; half++) {
                int row = rlo + half * 8;
                float v0 = acc[mb][nb][half * 2 + 0] + bi.x;
                float v1 = acc[mb][nb][half * 2 + 1] + bi.y;
                if (ACT) { v0 = gelu_exact(v0); v1 = gelu_exact(v1); }
                if (RES) {
                    float2 rv = *(const float2*)(resid + (size_t)row * N + col);
                    v0 += rv.x; v1 += rv.y;
                }
                if (OUT_BF16) {
                    __nv_bfloat162 o2;
                    o2.x = __float2bfloat16_rn(v0);
                    o2.y = __float2bfloat16_rn(v1);
                    *(__nv_bfloat162*)((__nv_bfloat16*)Cout + (size_t)row * N + col) = o2;
                } else {
                    float2 o2; o2.x = v0; o2.y = v1;
                    *(float2*)((float*)Cout + (size_t)row * N + col) = o2;
                }
            }
        }
    }
}

// ---------------- tensor-core flash attention (tf32, unchanged) ----------------
__global__ void __launch_bounds__(128) attn_kernel(
    const float* __restrict__ QKV, float* __restrict__ O)
{
    extern __shared__ float sma[];
    float* Ks = sma;
    float* Vs = sma + 2 * AT_TILE;
    float* Ps = sma + 4 * AT_TILE;

    const int qt = blockIdx.x;
    const int bh = blockIdx.y;
    const int b  = bh >> 4;
    const int h  = bh & 15;
    const int tid  = threadIdx.x;
    const int lane = tid & 31;
    const int w    = tid >> 5;
    const int gr   = lane >> 2;
    const int tg   = lane & 3;

    const float* Qb = QKV + (size_t)b * SEQ * QKV_LD + h * HDIMV;
    const float* Kb = Qb + 1024;
    const float* Vb = Qb + 2048;

    const uint32_t smb  = smem_u32(sma);
    const uint32_t KsB  = smb;
    const uint32_t VsB  = smb + 2 * AT_TILE * 4;

    #pragma unroll
    for (int j = 0; j < 8; j++) {
        int idx = j * 128 + tid;
        int r  = idx >> 4;
        int c4 = (idx & 15) * 4;
        float4 qv = *(const float4*)(Qb + (size_t)(qt * 64 + r) * QKV_LD + c4);
        Ps[r * AT_PAD + c4 + 0] = to_tf32(qv.x * 0.125f);
        Ps[r * AT_PAD + c4 + 1] = to_tf32(qv.y * 0.125f);
        Ps[r * AT_PAD + c4 + 2] = to_tf32(qv.z * 0.125f);
        Ps[r * AT_PAD + c4 + 3] = to_tf32(qv.w * 0.125f);
    }
    __syncthreads();
    uint32_t qf[8][4];
    {
        const int r = w * 16 + gr;
        #pragma unroll
        for (int kb = 0; kb < 8; kb++) {
            qf[kb][0] = __float_as_uint(Ps[(r)     * AT_PAD + kb * 8 + tg]);
            qf[kb][1] = __float_as_uint(Ps[(r + 8) * AT_PAD + kb * 8 + tg]);
            qf[kb][2] = __float_as_uint(Ps[(r)     * AT_PAD + kb * 8 + 4 + tg]);
            qf[kb][3] = __float_as_uint(Ps[(r + 8) * AT_PAD + kb * 8 + 4 + tg]);
        }
    }
    __syncthreads();

    #pragma unroll
    for (int j = 0; j < 8; j++) {
        int idx = j * 128 + tid;
        int r  = idx >> 4;
        int c4 = (idx & 15) * 4;
        uint32_t doff = (r * AT_PAD + c4) * 4;
        cp_async16(KsB + doff, Kb + (size_t)r * QKV_LD + c4);
        cp_async16(VsB + doff, Vb + (size_t)r * QKV_LD + c4);
    }
    CP_COMMIT();

    float oacc[8][4] = {};
    float rm[2] = { -3e38f, -3e38f };
    float rl[2] = { 0.f, 0.f };

    for (int kt = 0; kt <= qt; kt++) {
        const int buf = kt & 1;
        if (kt < qt) {
            const int nbuf = (kt + 1) & 1;
            const size_t krow0 = (size_t)(kt + 1) * 64;
            #pragma unroll
            for (int j = 0; j < 8; j++) {
                int idx = j * 128 + tid;
                int r  = idx >> 4;
                int c4 = (idx & 15) * 4;
                uint32_t doff = (nbuf * AT_TILE + r * AT_PAD + c4) * 4;
                cp_async16(KsB + doff, Kb + (krow0 + r) * QKV_LD + c4);
                cp_async16(VsB + doff, Vb + (krow0 + r) * QKV_LD + c4);
            }
            CP_COMMIT();
            CP_WAIT1();
        } else {
            CP_WAIT0();
        }
        __syncthreads();

        const float* Kt = Ks + buf * AT_TILE;
        const float* Vt = Vs + buf * AT_TILE;

        float s[8][4] = {};
        #pragma unroll
        for (int kb = 0; kb < 8; kb++) {
            uint32_t bf[8][2];
            #pragma unroll
            for (int nb = 0; nb < 8; nb++) {
                int t = nb * 8 + gr;
                bf[nb][0] = to_tf32_u(Kt[t * AT_PAD + kb * 8 + tg]);
                bf[nb][1] = to_tf32_u(Kt[t * AT_PAD + kb * 8 + 4 + tg]);
            }
            #pragma unroll
            for (int nb = 0; nb < 8; nb++)
                mma_tf32(s[nb], qf[kb], bf[nb]);
        }

        if (kt == qt) {
            #pragma unroll
            for (int nb = 0; nb < 8; nb++)
                #pragma unroll
                for (int e = 0; e < 4; e++) {
                    int row = w * 16 + gr + (e >> 1) * 8;
                    int col = nb * 8 + tg * 2 + (e & 1);
                    if (col > row) s[nb][e] = -3e38f;
                }
        }

        float alpha[2];
        #pragma unroll
        for (int hh = 0; hh < 2; hh++) {
            float mloc = -3e38f;
            #pragma unroll
            for (int nb = 0; nb < 8; nb++) {
                mloc = fmaxf(mloc, s[nb][hh * 2 + 0]);
                mloc = fmaxf(mloc, s[nb][hh * 2 + 1]);
            }
            mloc = fmaxf(mloc, __shfl_xor_sync(0xffffffffu, mloc, 1));
            mloc = fmaxf(mloc, __shfl_xor_sync(0xffffffffu, mloc, 2));
            float mnew = fmaxf(rm[hh], mloc);
            alpha[hh] = __expf(rm[hh] - mnew);
            float suml = 0.f;
            #pragma unroll
            for (int nb = 0; nb < 8; nb++) {
                float p0 = __expf(s[nb][hh * 2 + 0] - mnew);
                float p1 = __expf(s[nb][hh * 2 + 1] - mnew);
                s[nb][hh * 2 + 0] = p0;
                s[nb][hh * 2 + 1] = p1;
                suml += p0 + p1;
            }
            suml += __shfl_xor_sync(0xffffffffu, suml, 1);
            suml += __shfl_xor_sync(0xffffffffu, suml, 2);
            rl[hh] = rl[hh] * alpha[hh] + suml;
            rm[hh] = mnew;
        }

        #pragma unroll
        for (int nb = 0; nb < 8; nb++) {
            oacc[nb][0] *= alpha[0]; oacc[nb][1] *= alpha[0];
            oacc[nb][2] *= alpha[1]; oacc[nb][3] *= alpha[1];
        }

        {
            int r0s = w * 16 + gr;
            #pragma unroll
            for (int nb = 0; nb < 8; nb++) {
                Ps[(r0s)     * AT_PAD + nb * 8 + tg * 2 + 0] = to_tf32(s[nb][0]);
                Ps[(r0s)     * AT_PAD + nb * 8 + tg * 2 + 1] = to_tf32(s[nb][1]);
                Ps[(r0s + 8) * AT_PAD + nb * 8 + tg * 2 + 0] = to_tf32(s[nb][2]);
                Ps[(r0s + 8) * AT_PAD + nb * 8 + tg * 2 + 1] = to_tf32(s[nb][3]);
            }
        }
        __syncwarp();

        {
            const int r = w * 16 + gr;
            #pragma unroll
            for (int kb = 0; kb < 8; kb++) {
                uint32_t af[4];
                af[0] = __float_as_uint(Ps[(r)     * AT_PAD + kb * 8 + tg]);
                af[1] = __float_as_uint(Ps[(r + 8) * AT_PAD + kb * 8 + tg]);
                af[2] = __float_as_uint(Ps[(r)     * AT_PAD + kb * 8 + 4 + tg]);
                af[3] = __float_as_uint(Ps[(r + 8) * AT_PAD + kb * 8 + 4 + tg]);
                uint32_t bf[8][2];
                #pragma unroll
                for (int nb = 0; nb < 8; nb++) {
                    int d = nb * 8 + gr;
                    bf[nb][0] = to_tf32_u(Vt[(kb * 8 + tg)     * AT_PAD + d]);
                    bf[nb][1] = to_tf32_u(Vt[(kb * 8 + 4 + tg) * AT_PAD + d]);
                }
                #pragma unroll
                for (int nb = 0; nb < 8; nb++)
                    mma_tf32(oacc[nb], af, bf[nb]);
            }
        }
        __syncthreads();
    }

    float linv0 = 1.0f / rl[0];
    float linv1 = 1.0f / rl[1];
    #pragma unroll
    for (int hh = 0; hh < 2; hh++) {
        size_t row = (size_t)b * SEQ + (size_t)(qt * 64 + w * 16 + gr + hh * 8);
        float linv = hh ? linv1 : linv0;
        #pragma unroll
        for (int nb = 0; nb < 8; nb++) {
            float2 o2;
            o2.x = oacc[nb][hh * 2 + 0] * linv;
            o2.y = oacc[nb][hh * 2 + 1] * linv;
            *(float2*)(O + row * DIMV + h * HDIMV + nb * 8 + tg * 2) = o2;
        }
    }
}

extern "C" void kernel_launch(void* const* d_in, const int* in_sizes, int n_in,
                              void* d_out, int out_size)
{
    const float* x    = (const float*)d_in[0];
    const float* ln1g = (const float*)d_in[1];
    const float* ln1b = (const float*)d_in[2];
    const float* Wq   = (const float*)d_in[3];
    const float* bq   = (const float*)d_in[4];
    const float* Wk   = (const float*)d_in[5];
    const float* bk   = (const float*)d_in[6];
    const float* Wv   = (const float*)d_in[7];
    const float* bv   = (const float*)d_in[8];
    const float* ln2g = (const float*)d_in[9];
    const float* ln2b = (const float*)d_in[10];
    const float* fclg = (const float*)d_in[11];
    const float* fclb = (const float*)d_in[12];
    const float* W1   = (const float*)d_in[13];
    const float* b1   = (const float*)d_in[14];
    const float* W2   = (const float*)d_in[15];
    const float* b2   = (const float*)d_in[16];
    float* out = (float*)d_out;

    float *p_h, *p_qkv, *p_o, *p_x2, *p_wt, *p_bqkv;
    __nv_bfloat16 *p_h2, *p_mid, *p_w1t, *p_w2t;
    cudaGetSymbolAddress((void**)&p_h,    g_h);
    cudaGetSymbolAddress((void**)&p_qkv,  g_qkv);
    cudaGetSymbolAddress((void**)&p_o,    g_o);
    cudaGetSymbolAddress((void**)&p_x2,   g_x2);
    cudaGetSymbolAddress((void**)&p_h2,   g_h2);
    cudaGetSymbolAddress((void**)&p_mid,  g_mid);
    cudaGetSymbolAddress((void**)&p_wt,   g_wt);
    cudaGetSymbolAddress((void**)&p_w1t,  g_w1t);
    cudaGetSymbolAddress((void**)&p_w2t,  g_w2t);
    cudaGetSymbolAddress((void**)&p_bqkv, g_bqkv);

    cudaFuncSetAttribute(attn_kernel, cudaFuncAttributeMaxDynamicSharedMemorySize, ATTN_SMEM_B);
    cudaFuncSetAttribute(gemm_mma<0,0,0>, cudaFuncAttributeMaxDynamicSharedMemorySize, GEMM_SMEM_BYTES);
    cudaFuncSetAttribute(gemm_bf16<1,0,1>, cudaFuncAttributeMaxDynamicSharedMemorySize, GEMM_SMEM_BYTES);
    cudaFuncSetAttribute(gemm_bf16<1,1,0>, cudaFuncAttributeMaxDynamicSharedMemorySize, GEMM_SMEM_BYTES);

    transpose_qkv_kernel<<<dim3(2, 32, 48), dim3(32, 8)>>>(Wq, Wk, Wv, p_wt);
    transpose_kernel_b16<<<dim3(HIDV / 32, DIMV / 32), dim3(32, 8)>>>(W1, p_w1t, DIMV, HIDV);
    transpose_kernel_b16<<<dim3(DIMV / 32, HIDV / 32), dim3(32, 8)>>>(W2, p_w2t, HIDV, DIMV);
    pack_bias_kernel<<<QKV_LD / 256, 256>>>(bq, bk, bv, p_bqkv);
    ln_kernel<<<NTOK, 256>>>(x, ln1g, ln1b, p_h);
    gemm_mma<0,0,0><<<dim3(QKV_LD / BN, NTOK / BM), 256, GEMM_SMEM_BYTES>>>(
        p_h, p_wt, p_bqkv, nullptr, p_qkv, QKV_LD, DIMV);
    attn_kernel<<<dim3(SEQ / 64, 64), 128, ATTN_SMEM_B>>>(p_qkv, p_o);
    add_dln_kernel<<<NTOK, 256>>>(x, p_o, ln2g, ln2b, fclg, fclb, p_x2, p_h2);
    gemm_bf16<1,0,1><<<dim3(HIDV / BN, NTOK / BM), 256, GEMM_SMEM_BYTES>>>(
        p_h2, p_w1t, b1, nullptr, p_mid, HIDV, DIMV);
    gemm_bf16<1,1,0><<<dim3(DIMV / BN, NTOK / BM), 256, GEMM_SMEM_BYTES>>>(
        p_mid, p_w2t, b2, p_x2, out, DIMV, HIDV);
}

// round 7
// speedup vs baseline: 7.4878x; 1.1456x over previous
#include <cuda_runtime.h>
#include <cuda_fp16.h>
#include <cstdint>
#include <cstddef>

// Problem dims
#define DIMV   1024
#define HIDV   4096
#define SEQ    2048
#define NHEAD  16
#define HDIMV  64
#define NTOK   8192          // B * S
#define QKV_LD 3072          // fused QKV row stride

// GEMM tiling (fp16 mma m16n8k16): 128x128 tile, 32 K per stage
#define BM 128
#define BN 128
#define BKS16 32
#define TILE_H 2560          // 128 rows * 20 b32 (40 halves padded)
#define STAGE_H 5120
#define GEMM_SMEM_BYTES (3 * STAGE_H * 4)   // 61440

// attention smem
#define AT_PAD 68
#define AT_TILE (64 * AT_PAD)
#define ATTN_SMEM_B ((4 * AT_TILE + AT_TILE) * 4)  // 87040 B

// ---------------- static scratch ----------------
__device__ __half g_h  [(size_t)NTOK * DIMV];     // ln1(x) fp16
__device__ float  g_qkv[(size_t)NTOK * QKV_LD];   // fused Q|K|V fp32
__device__ float  g_o  [(size_t)NTOK * DIMV];
__device__ float  g_x2 [(size_t)NTOK * DIMV];
__device__ __half g_h2 [(size_t)NTOK * DIMV];
__device__ __half g_mid[(size_t)NTOK * HIDV];
__device__ __half g_wt [(size_t)QKV_LD * DIMV];   // QKV weights [3072][1024] fp16
__device__ __half g_w1t[(size_t)HIDV * DIMV];
__device__ __half g_w2t[(size_t)DIMV * HIDV];
__device__ float  g_bqkv[QKV_LD];

// ---------------- helpers ----------------
__device__ __forceinline__ uint32_t smem_u32(const void* p) {
    uint32_t a;
    asm("{ .reg .u64 t; cvta.to.shared.u64 t, %1; cvt.u32.u64 %0, t; }" : "=r"(a) : "l"(p));
    return a;
}

__device__ __forceinline__ float to_tf32(float x) {
    uint32_t r;
    asm("cvt.rna.tf32.f32 %0, %1;" : "=r"(r) : "f"(x));
    return __uint_as_float(r);
}

__device__ __forceinline__ uint32_t to_tf32_u(float x) {
    uint32_t r;
    asm("cvt.rna.tf32.f32 %0, %1;" : "=r"(r) : "f"(x));
    return r;
}

__device__ __forceinline__ float gelu_exact(float x) {
    return 0.5f * x * (1.0f + erff(x * 0.70710678118654752f));
}

__device__ __forceinline__ void cp_async16(uint32_t dst, const void* src) {
    asm volatile("cp.async.cg.shared.global [%0], [%1], 16;" :: "r"(dst), "l"(src));
}
#define CP_COMMIT() asm volatile("cp.async.commit_group;" ::: "memory")
#define CP_WAIT1()  asm volatile("cp.async.wait_group 1;" ::: "memory")
#define CP_WAIT0()  asm volatile("cp.async.wait_group 0;" ::: "memory")

__device__ __forceinline__ void mma_tf32(float* c, const uint32_t* a, const uint32_t* b) {
    asm volatile(
        "mma.sync.aligned.m16n8k8.row.col.f32.tf32.tf32.f32 "
        "{%0,%1,%2,%3}, {%4,%5,%6,%7}, {%8,%9}, {%0,%1,%2,%3};"
        : "+f"(c[0]), "+f"(c[1]), "+f"(c[2]), "+f"(c[3])
        : "r"(a[0]), "r"(a[1]), "r"(a[2]), "r"(a[3]), "r"(b[0]), "r"(b[1]));
}

__device__ __forceinline__ void mma_f16(float* c, const uint32_t* a, const uint32_t* b) {
    asm volatile(
        "mma.sync.aligned.m16n8k16.row.col.f32.f16.f16.f32 "
        "{%0,%1,%2,%3}, {%4,%5,%6,%7}, {%8,%9}, {%0,%1,%2,%3};"
        : "+f"(c[0]), "+f"(c[1]), "+f"(c[2]), "+f"(c[3])
        : "r"(a[0]), "r"(a[1]), "r"(a[2]), "r"(a[3]), "r"(b[0]), "r"(b[1]));
}

// ---------------- weight transposes (fp16 output) ----------------
__global__ void transpose_kernel_h16(const float* __restrict__ src, __half* __restrict__ dst,
                                     int R, int C)
{
    __shared__ float t[32][33];
    int c0 = blockIdx.x * 32, r0 = blockIdx.y * 32;
    int tx = threadIdx.x, ty = threadIdx.y;
    #pragma unroll
    for (int i = 0; i < 32; i += 8)
        t[ty + i][tx] = src[(size_t)(r0 + ty + i) * C + c0 + tx];
    __syncthreads();
    #pragma unroll
    for (int i = 0; i < 32; i += 8)
        dst[(size_t)(c0 + ty + i) * R + r0 + tx] = __float2half_rn(t[tx][ty + i]);
}

__global__ void transpose_qkv_kernel(const float* __restrict__ Wq, const float* __restrict__ Wk,
                                     const float* __restrict__ Wv, __half* __restrict__ dst)
{
    __shared__ float t[32][33];
    int s = blockIdx.z, w = s >> 4, h = s & 15;
    const float* W = ((w == 0) ? Wq : (w == 1) ? Wk : Wv) + (size_t)h * DIMV * HDIMV;
    __half* D = dst + (size_t)(w * 1024 + h * 64) * DIMV;
    int c0 = blockIdx.x * 32, r0 = blockIdx.y * 32;
    int tx = threadIdx.x, ty = threadIdx.y;
    #pragma unroll
    for (int i = 0; i < 32; i += 8)
        t[ty + i][tx] = W[(size_t)(r0 + ty + i) * HDIMV + c0 + tx];
    __syncthreads();
    #pragma unroll
    for (int i = 0; i < 32; i += 8)
        D[(size_t)(c0 + ty + i) * DIMV + r0 + tx] = __float2half_rn(t[tx][ty + i]);
}

__global__ void pack_bias_kernel(const float* __restrict__ bq, const float* __restrict__ bk,
                                 const float* __restrict__ bv, float* __restrict__ dst)
{
    int i = blockIdx.x * 256 + threadIdx.x;
    float v = (i < 1024) ? bq[i] : (i < 2048) ? bk[i - 1024] : bv[i - 2048];
    dst[i] = v;
}

// ---------------- LayerNorm (fp16 output) ----------------
__global__ void ln_kernel(const float* __restrict__ x, const float* __restrict__ g,
                          const float* __restrict__ b, __half* __restrict__ y)
{
    __shared__ float s_a[8], s_b[8];
    __shared__ float s_mu, s_rs;
    size_t row = blockIdx.x;
    int tid = threadIdx.x;
    float4 v = ((const float4*)(x + row * DIMV))[tid];
    float sum = v.x + v.y + v.z + v.w;
    float sq  = v.x*v.x + v.y*v.y + v.z*v.z + v.w*v.w;
    #pragma unroll
    for (int o = 16; o; o >>= 1) {
        sum += __shfl_xor_sync(0xffffffffu, sum, o);
        sq  += __shfl_xor_sync(0xffffffffu, sq,  o);
    }
    if ((tid & 31) == 0) { s_a[tid >> 5] = sum; s_b[tid >> 5] = sq; }
    __syncthreads();
    if (tid == 0) {
        float ts = 0.f, tq = 0.f;
        #pragma unroll
        for (int i = 0; i < 8; i++) { ts += s_a[i]; tq += s_b[i]; }
        float mu  = ts * (1.0f / DIMV);
        float var = tq * (1.0f / DIMV) - mu * mu;
        s_mu = mu; s_rs = rsqrtf(var + 1e-5f);
    }
    __syncthreads();
    float mu = s_mu, rs = s_rs;
    float4 gv = ((const float4*)g)[tid];
    float4 bv = ((const float4*)b)[tid];
    __half2 h0, h1;
    h0.x = __float2half_rn((v.x - mu) * rs * gv.x + bv.x);
    h0.y = __float2half_rn((v.y - mu) * rs * gv.y + bv.y);
    h1.x = __float2half_rn((v.z - mu) * rs * gv.z + bv.z);
    h1.y = __float2half_rn((v.w - mu) * rs * gv.w + bv.w);
    ((__half2*)(y + row * DIMV))[tid * 2 + 0] = h0;
    ((__half2*)(y + row * DIMV))[tid * 2 + 1] = h1;
}

// ---------------- residual add + LN(ln2) + LN(fcln), h2 out fp16 ----------------
__global__ void add_dln_kernel(const float* __restrict__ x, const float* __restrict__ oatt,
                               const float* __restrict__ g2, const float* __restrict__ b2,
                               const float* __restrict__ gf, const float* __restrict__ bf,
                               float* __restrict__ x2, __half* __restrict__ h2)
{
    __shared__ float s_a[8], s_b[8];
    __shared__ float s_mu, s_rs;
    size_t row = blockIdx.x;
    int tid = threadIdx.x;
    float4 v  = ((const float4*)(x    + row * DIMV))[tid];
    float4 ov = ((const float4*)(oatt + row * DIMV))[tid];
    v.x += ov.x; v.y += ov.y; v.z += ov.z; v.w += ov.w;
    ((float4*)(x2 + row * DIMV))[tid] = v;

    float sum = v.x + v.y + v.z + v.w;
    float sq  = v.x*v.x + v.y*v.y + v.z*v.z + v.w*v.w;
    #pragma unroll
    for (int o = 16; o; o >>= 1) {
        sum += __shfl_xor_sync(0xffffffffu, sum, o);
        sq  += __shfl_xor_sync(0xffffffffu, sq,  o);
    }
    if ((tid & 31) == 0) { s_a[tid >> 5] = sum; s_b[tid >> 5] = sq; }
    __syncthreads();
    if (tid == 0) {
        float ts = 0.f, tq = 0.f;
        #pragma unroll
        for (int i = 0; i < 8; i++) { ts += s_a[i]; tq += s_b[i]; }
        float mu  = ts * (1.0f / DIMV);
        float var = tq * (1.0f / DIMV) - mu * mu;
        s_mu = mu; s_rs = rsqrtf(var + 1e-5f);
    }
    __syncthreads();
    float mu1 = s_mu, rs1 = s_rs;
    float4 g2v = ((const float4*)g2)[tid];
    float4 b2v = ((const float4*)b2)[tid];
    float4 t;
    t.x = (v.x - mu1) * rs1 * g2v.x + b2v.x;
    t.y = (v.y - mu1) * rs1 * g2v.y + b2v.y;
    t.z = (v.z - mu1) * rs1 * g2v.z + b2v.z;
    t.w = (v.w - mu1) * rs1 * g2v.w + b2v.w;

    float sum2 = t.x + t.y + t.z + t.w;
    float sq2  = t.x*t.x + t.y*t.y + t.z*t.z + t.w*t.w;
    #pragma unroll
    for (int o = 16; o; o >>= 1) {
        sum2 += __shfl_xor_sync(0xffffffffu, sum2, o);
        sq2  += __shfl_xor_sync(0xffffffffu, sq2,  o);
    }
    if ((tid & 31) == 0) { s_a[tid >> 5] = sum2; s_b[tid >> 5] = sq2; }
    __syncthreads();
    if (tid == 0) {
        float ts = 0.f, tq = 0.f;
        #pragma unroll
        for (int i = 0; i < 8; i++) { ts += s_a[i]; tq += s_b[i]; }
        float mu  = ts * (1.0f / DIMV);
        float var = tq * (1.0f / DIMV) - mu * mu;
        s_mu = mu; s_rs = rsqrtf(var + 1e-5f);
    }
    __syncthreads();
    float mu2 = s_mu, rs2 = s_rs;
    float4 gfv = ((const float4*)gf)[tid];
    float4 bfv = ((const float4*)bf)[tid];
    __half2 h0, h1;
    h0.x = __float2half_rn((t.x - mu2) * rs2 * gfv.x + bfv.x);
    h0.y = __float2half_rn((t.y - mu2) * rs2 * gfv.y + bfv.y);
    h1.x = __float2half_rn((t.z - mu2) * rs2 * gfv.z + bfv.z);
    h1.y = __float2half_rn((t.w - mu2) * rs2 * gfv.w + bfv.w);
    ((__half2*)(h2 + row * DIMV))[tid * 2 + 0] = h0;
    ((__half2*)(h2 + row * DIMV))[tid * 2 + 1] = h1;
}

// ---------------- fp16 GEMM: C = act(A @ Bt^T + bias) (+res) ----------------
// A [M,K] fp16, Bt [N,K] fp16. 128x128 tile, 32 K per stage, 3-stage cp.async.
// OUT16: write __half, else fp32.
template<int ACT, int RES, int OUT16>
__global__ void __launch_bounds__(256) gemm_f16(
    const __half* __restrict__ A, const __half* __restrict__ Bt,
    const float* __restrict__ bias, const float* __restrict__ resid,
    void* __restrict__ Cout, int N, int K)
{
    extern __shared__ float sm[];
    uint32_t* smu = (uint32_t*)sm;
    const int tid  = threadIdx.x;
    const int lane = tid & 31;
    const int warp = tid >> 5;
    const int wm = warp >> 2;
    const int wn = warp & 3;
    const int m0 = blockIdx.y * BM;
    const int n0 = blockIdx.x * BN;
    const int KT = K / BKS16;

    const int lrow = tid >> 2;          // 0..63
    const int lk8  = (tid & 3) * 8;     // half offset
    const int lk4  = (tid & 3) * 4;     // b32 offset

    const __half* Asrc0 = A  + (size_t)(m0 + lrow)      * K + lk8;
    const __half* Asrc1 = A  + (size_t)(m0 + lrow + 64) * K + lk8;
    const __half* Bsrc0 = Bt + (size_t)(n0 + lrow)      * K + lk8;
    const __half* Bsrc1 = Bt + (size_t)(n0 + lrow + 64) * K + lk8;

    const uint32_t smb = smem_u32(sm);
    const uint32_t dA0 = smb + ((lrow)      * 20 + lk4) * 4;
    const uint32_t dA1 = smb + ((lrow + 64) * 20 + lk4) * 4;
    const uint32_t dB0 = dA0 + TILE_H * 4;
    const uint32_t dB1 = dA1 + TILE_H * 4;

    #pragma unroll
    for (int s = 0; s < 2; s++) {
        uint32_t off = s * STAGE_H * 4;
        int k0 = s * BKS16;
        cp_async16(dA0 + off, Asrc0 + k0);
        cp_async16(dA1 + off, Asrc1 + k0);
        cp_async16(dB0 + off, Bsrc0 + k0);
        cp_async16(dB1 + off, Bsrc1 + k0);
        CP_COMMIT();
    }

    float acc[4][4][4] = {};
    const int gr = lane >> 2;
    const int tg = lane & 3;

    for (int kt = 0; kt < KT; kt++) {
        CP_WAIT1();
        __syncthreads();
        const uint32_t* As = smu + (kt % 3) * STAGE_H;
        const uint32_t* Bs = As + TILE_H;

        #pragma unroll
        for (int kc = 0; kc < 2; kc++) {
            uint32_t af[4][4], bf[4][2];
            #pragma unroll
            for (int mb = 0; mb < 4; mb++) {
                int r = wm * 64 + mb * 16 + gr;
                af[mb][0] = As[(r)     * 20 + kc * 8 + tg];
                af[mb][1] = As[(r + 8) * 20 + kc * 8 + tg];
                af[mb][2] = As[(r)     * 20 + kc * 8 + 4 + tg];
                af[mb][3] = As[(r + 8) * 20 + kc * 8 + 4 + tg];
            }
            #pragma unroll
            for (int nb = 0; nb < 4; nb++) {
                int c = wn * 32 + nb * 8 + gr;
                bf[nb][0] = Bs[c * 20 + kc * 8 + tg];
                bf[nb][1] = Bs[c * 20 + kc * 8 + 4 + tg];
            }
            #pragma unroll
            for (int mb = 0; mb < 4; mb++)
                #pragma unroll
                for (int nb = 0; nb < 4; nb++)
                    mma_f16(acc[mb][nb], af[mb], bf[nb]);
        }

        if (kt + 2 < KT) {
            uint32_t off = ((kt + 2) % 3) * STAGE_H * 4;
            int k0 = (kt + 2) * BKS16;
            cp_async16(dA0 + off, Asrc0 + k0);
            cp_async16(dA1 + off, Asrc1 + k0);
            cp_async16(dB0 + off, Bsrc0 + k0);
            cp_async16(dB1 + off, Bsrc1 + k0);
        }
        CP_COMMIT();
        __syncthreads();
    }

    #pragma unroll
    for (int mb = 0; mb < 4; mb++) {
        int rlo = m0 + wm * 64 + mb * 16 + gr;
        #pragma unroll
        for (int nb = 0; nb < 4; nb++) {
            int col = n0 + wn * 32 + nb * 8 + tg * 2;
            float2 bi = *(const float2*)(bias + col);
            #pragma unroll
            for (int half_i = 0; half_i < 2; half_i++) {
                int row = rlo + half_i * 8;
                float v0 = acc[mb][nb][half_i * 2 + 0] + bi.x;
                float v1 = acc[mb][nb][half_i * 2 + 1] + bi.y;
                if (ACT) { v0 = gelu_exact(v0); v1 = gelu_exact(v1); }
                if (RES) {
                    float2 rv = *(const float2*)(resid + (size_t)row * N + col);
                    v0 += rv.x; v1 += rv.y;
                }
                if (OUT16) {
                    __half2 o2;
                    o2.x = __float2half_rn(v0);
                    o2.y = __float2half_rn(v1);
                    *(__half2*)((__half*)Cout + (size_t)row * N + col) = o2;
                } else {
                    float2 o2; o2.x = v0; o2.y = v1;
                    *(float2*)((float*)Cout + (size_t)row * N + col) = o2;
                }
            }
        }
    }
}

// ---------------- tensor-core flash attention (tf32, unchanged) ----------------
__global__ void __launch_bounds__(128) attn_kernel(
    const float* __restrict__ QKV, float* __restrict__ O)
{
    extern __shared__ float sma[];
    float* Ks = sma;
    float* Vs = sma + 2 * AT_TILE;
    float* Ps = sma + 4 * AT_TILE;

    const int qt = blockIdx.x;
    const int bh = blockIdx.y;
    const int b  = bh >> 4;
    const int h  = bh & 15;
    const int tid  = threadIdx.x;
    const int lane = tid & 31;
    const int w    = tid >> 5;
    const int gr   = lane >> 2;
    const int tg   = lane & 3;

    const float* Qb = QKV + (size_t)b * SEQ * QKV_LD + h * HDIMV;
    const float* Kb = Qb + 1024;
    const float* Vb = Qb + 2048;

    const uint32_t smb  = smem_u32(sma);
    const uint32_t KsB  = smb;
    const uint32_t VsB  = smb + 2 * AT_TILE * 4;

    #pragma unroll
    for (int j = 0; j < 8; j++) {
        int idx = j * 128 + tid;
        int r  = idx >> 4;
        int c4 = (idx & 15) * 4;
        float4 qv = *(const float4*)(Qb + (size_t)(qt * 64 + r) * QKV_LD + c4);
        Ps[r * AT_PAD + c4 + 0] = to_tf32(qv.x * 0.125f);
        Ps[r * AT_PAD + c4 + 1] = to_tf32(qv.y * 0.125f);
        Ps[r * AT_PAD + c4 + 2] = to_tf32(qv.z * 0.125f);
        Ps[r * AT_PAD + c4 + 3] = to_tf32(qv.w * 0.125f);
    }
    __syncthreads();
    uint32_t qf[8][4];
    {
        const int r = w * 16 + gr;
        #pragma unroll
        for (int kb = 0; kb < 8; kb++) {
            qf[kb][0] = __float_as_uint(Ps[(r)     * AT_PAD + kb * 8 + tg]);
            qf[kb][1] = __float_as_uint(Ps[(r + 8) * AT_PAD + kb * 8 + tg]);
            qf[kb][2] = __float_as_uint(Ps[(r)     * AT_PAD + kb * 8 + 4 + tg]);
            qf[kb][3] = __float_as_uint(Ps[(r + 8) * AT_PAD + kb * 8 + 4 + tg]);
        }
    }
    __syncthreads();

    #pragma unroll
    for (int j = 0; j < 8; j++) {
        int idx = j * 128 + tid;
        int r  = idx >> 4;
        int c4 = (idx & 15) * 4;
        uint32_t doff = (r * AT_PAD + c4) * 4;
        cp_async16(KsB + doff, Kb + (size_t)r * QKV_LD + c4);
        cp_async16(VsB + doff, Vb + (size_t)r * QKV_LD + c4);
    }
    CP_COMMIT();

    float oacc[8][4] = {};
    float rm[2] = { -3e38f, -3e38f };
    float rl[2] = { 0.f, 0.f };

    for (int kt = 0; kt <= qt; kt++) {
        const int buf = kt & 1;
        if (kt < qt) {
            const int nbuf = (kt + 1) & 1;
            const size_t krow0 = (size_t)(kt + 1) * 64;
            #pragma unroll
            for (int j = 0; j < 8; j++) {
                int idx = j * 128 + tid;
                int r  = idx >> 4;
                int c4 = (idx & 15) * 4;
                uint32_t doff = (nbuf * AT_TILE + r * AT_PAD + c4) * 4;
                cp_async16(KsB + doff, Kb + (krow0 + r) * QKV_LD + c4);
                cp_async16(VsB + doff, Vb + (krow0 + r) * QKV_LD + c4);
            }
            CP_COMMIT();
            CP_WAIT1();
        } else {
            CP_WAIT0();
        }
        __syncthreads();

        const float* Kt = Ks + buf * AT_TILE;
        const float* Vt = Vs + buf * AT_TILE;

        float s[8][4] = {};
        #pragma unroll
        for (int kb = 0; kb < 8; kb++) {
            uint32_t bf[8][2];
            #pragma unroll
            for (int nb = 0; nb < 8; nb++) {
                int t = nb * 8 + gr;
                bf[nb][0] = to_tf32_u(Kt[t * AT_PAD + kb * 8 + tg]);
                bf[nb][1] = to_tf32_u(Kt[t * AT_PAD + kb * 8 + 4 + tg]);
            }
            #pragma unroll
            for (int nb = 0; nb < 8; nb++)
                mma_tf32(s[nb], qf[kb], bf[nb]);
        }

        if (kt == qt) {
            #pragma unroll
            for (int nb = 0; nb < 8; nb++)
                #pragma unroll
                for (int e = 0; e < 4; e++) {
                    int row = w * 16 + gr + (e >> 1) * 8;
                    int col = nb * 8 + tg * 2 + (e & 1);
                    if (col > row) s[nb][e] = -3e38f;
                }
        }

        float alpha[2];
        #pragma unroll
        for (int hh = 0; hh < 2; hh++) {
            float mloc = -3e38f;
            #pragma unroll
            for (int nb = 0; nb < 8; nb++) {
                mloc = fmaxf(mloc, s[nb][hh * 2 + 0]);
                mloc = fmaxf(mloc, s[nb][hh * 2 + 1]);
            }
            mloc = fmaxf(mloc, __shfl_xor_sync(0xffffffffu, mloc, 1));
            mloc = fmaxf(mloc, __shfl_xor_sync(0xffffffffu, mloc, 2));
            float mnew = fmaxf(rm[hh], mloc);
            alpha[hh] = __expf(rm[hh] - mnew);
            float suml = 0.f;
            #pragma unroll
            for (int nb = 0; nb < 8; nb++) {
                float p0 = __expf(s[nb][hh * 2 + 0] - mnew);
                float p1 = __expf(s[nb][hh * 2 + 1] - mnew);
                s[nb][hh * 2 + 0] = p0;
                s[nb][hh * 2 + 1] = p1;
                suml += p0 + p1;
            }
            suml += __shfl_xor_sync(0xffffffffu, suml, 1);
            suml += __shfl_xor_sync(0xffffffffu, suml, 2);
            rl[hh] = rl[hh] * alpha[hh] + suml;
            rm[hh] = mnew;
        }

        #pragma unroll
        for (int nb = 0; nb < 8; nb++) {
            oacc[nb][0] *= alpha[0]; oacc[nb][1] *= alpha[0];
            oacc[nb][2] *= alpha[1]; oacc[nb][3] *= alpha[1];
        }

        {
            int r0s = w * 16 + gr;
            #pragma unroll
            for (int nb = 0; nb < 8; nb++) {
                Ps[(r0s)     * AT_PAD + nb * 8 + tg * 2 + 0] = to_tf32(s[nb][0]);
                Ps[(r0s)     * AT_PAD + nb * 8 + tg * 2 + 1] = to_tf32(s[nb][1]);
                Ps[(r0s + 8) * AT_PAD + nb * 8 + tg * 2 + 0] = to_tf32(s[nb][2]);
                Ps[(r0s + 8) * AT_PAD + nb * 8 + tg * 2 + 1] = to_tf32(s[nb][3]);
            }
        }
        __syncwarp();

        {
            const int r = w * 16 + gr;
            #pragma unroll
            for (int kb = 0; kb < 8; kb++) {
                uint32_t af[4];
                af[0] = __float_as_uint(Ps[(r)     * AT_PAD + kb * 8 + tg]);
                af[1] = __float_as_uint(Ps[(r + 8) * AT_PAD + kb * 8 + tg]);
                af[2] = __float_as_uint(Ps[(r)     * AT_PAD + kb * 8 + 4 + tg]);
                af[3] = __float_as_uint(Ps[(r + 8) * AT_PAD + kb * 8 + 4 + tg]);
                uint32_t bf[8][2];
                #pragma unroll
                for (int nb = 0; nb < 8; nb++) {
                    int d = nb * 8 + gr;
                    bf[nb][0] = to_tf32_u(Vt[(kb * 8 + tg)     * AT_PAD + d]);
                    bf[nb][1] = to_tf32_u(Vt[(kb * 8 + 4 + tg) * AT_PAD + d]);
                }
                #pragma unroll
                for (int nb = 0; nb < 8; nb++)
                    mma_tf32(oacc[nb], af, bf[nb]);
            }
        }
        __syncthreads();
    }

    float linv0 = 1.0f / rl[0];
    float linv1 = 1.0f / rl[1];
    #pragma unroll
    for (int hh = 0; hh < 2; hh++) {
        size_t row = (size_t)b * SEQ + (size_t)(qt * 64 + w * 16 + gr + hh * 8);
        float linv = hh ? linv1 : linv0;
        #pragma unroll
        for (int nb = 0; nb < 8; nb++) {
            float2 o2;
            o2.x = oacc[nb][hh * 2 + 0] * linv;
            o2.y = oacc[nb][hh * 2 + 1] * linv;
            *(float2*)(O + row * DIMV + h * HDIMV + nb * 8 + tg * 2) = o2;
        }
    }
}

extern "C" void kernel_launch(void* const* d_in, const int* in_sizes, int n_in,
                              void* d_out, int out_size)
{
    const float* x    = (const float*)d_in[0];
    const float* ln1g = (const float*)d_in[1];
    const float* ln1b = (const float*)d_in[2];
    const float* Wq   = (const float*)d_in[3];
    const float* bq   = (const float*)d_in[4];
    const float* Wk   = (const float*)d_in[5];
    const float* bk   = (const float*)d_in[6];
    const float* Wv   = (const float*)d_in[7];
    const float* bv   = (const float*)d_in[8];
    const float* ln2g = (const float*)d_in[9];
    const float* ln2b = (const float*)d_in[10];
    const float* fclg = (const float*)d_in[11];
    const float* fclb = (const float*)d_in[12];
    const float* W1   = (const float*)d_in[13];
    const float* b1   = (const float*)d_in[14];
    const float* W2   = (const float*)d_in[15];
    const float* b2   = (const float*)d_in[16];
    float* out = (float*)d_out;

    float *p_qkv, *p_o, *p_x2, *p_bqkv;
    __half *p_h, *p_h2, *p_mid, *p_wt, *p_w1t, *p_w2t;
    cudaGetSymbolAddress((void**)&p_h,    g_h);
    cudaGetSymbolAddress((void**)&p_qkv,  g_qkv);
    cudaGetSymbolAddress((void**)&p_o,    g_o);
    cudaGetSymbolAddress((void**)&p_x2,   g_x2);
    cudaGetSymbolAddress((void**)&p_h2,   g_h2);
    cudaGetSymbolAddress((void**)&p_mid,  g_mid);
    cudaGetSymbolAddress((void**)&p_wt,   g_wt);
    cudaGetSymbolAddress((void**)&p_w1t,  g_w1t);
    cudaGetSymbolAddress((void**)&p_w2t,  g_w2t);
    cudaGetSymbolAddress((void**)&p_bqkv, g_bqkv);

    cudaFuncSetAttribute(attn_kernel, cudaFuncAttributeMaxDynamicSharedMemorySize, ATTN_SMEM_B);
    cudaFuncSetAttribute(gemm_f16<0,0,0>, cudaFuncAttributeMaxDynamicSharedMemorySize, GEMM_SMEM_BYTES);
    cudaFuncSetAttribute(gemm_f16<1,0,1>, cudaFuncAttributeMaxDynamicSharedMemorySize, GEMM_SMEM_BYTES);
    cudaFuncSetAttribute(gemm_f16<1,1,0>, cudaFuncAttributeMaxDynamicSharedMemorySize, GEMM_SMEM_BYTES);

    transpose_qkv_kernel<<<dim3(2, 32, 48), dim3(32, 8)>>>(Wq, Wk, Wv, p_wt);
    transpose_kernel_h16<<<dim3(HIDV / 32, DIMV / 32), dim3(32, 8)>>>(W1, p_w1t, DIMV, HIDV);
    transpose_kernel_h16<<<dim3(DIMV / 32, HIDV / 32), dim3(32, 8)>>>(W2, p_w2t, HIDV, DIMV);
    pack_bias_kernel<<<QKV_LD / 256, 256>>>(bq, bk, bv, p_bqkv);
    ln_kernel<<<NTOK, 256>>>(x, ln1g, ln1b, p_h);
    // QKV projection (fp16): [8192,1024] @ [1024,3072] -> fp32
    gemm_f16<0,0,0><<<dim3(QKV_LD / BN, NTOK / BM), 256, GEMM_SMEM_BYTES>>>(
        p_h, p_wt, p_bqkv, nullptr, p_qkv, QKV_LD, DIMV);
    attn_kernel<<<dim3(SEQ / 64, 64), 128, ATTN_SMEM_B>>>(p_qkv, p_o);
    add_dln_kernel<<<NTOK, 256>>>(x, p_o, ln2g, ln2b, fclg, fclb, p_x2, p_h2);
    // MLP up + GELU (fp16 in/out)
    gemm_f16<1,0,1><<<dim3(HIDV / BN, NTOK / BM), 256, GEMM_SMEM_BYTES>>>(
        p_h2, p_w1t, b1, nullptr, p_mid, HIDV, DIMV);
    // MLP down + GELU + residual -> fp32 out
    gemm_f16<1,1,0><<<dim3(DIMV / BN, NTOK / BM), 256, GEMM_SMEM_BYTES>>>(
        p_mid, p_w2t, b2, p_x2, out, DIMV, HIDV);
}

// round 8
// speedup vs baseline: 8.9112x; 1.1901x over previous
#include <cuda_runtime.h>
#include <cuda_fp16.h>
#include <cstdint>
#include <cstddef>

// Problem dims
#define DIMV   1024
#define HIDV   4096
#define SEQ    2048
#define NHEAD  16
#define HDIMV  64
#define NTOK   8192          // B * S
#define QKV_LD 3072          // fused QKV row stride

// GEMM tiling (fp16 mma m16n8k16): 128x128 tile, 32 K per stage
#define BM 128
#define BN 128
#define BKS16 32
#define TILE_H 2560          // 128 rows * 20 b32 (40 halves padded)
#define STAGE_H 5120
#define GEMM_SMEM_BYTES (3 * STAGE_H * 4)   // 61440

// attention smem (fp16 tiles)
#define AT_PADH 72                         // halves per row (64 + 8 pad)
#define AT_TILEH (64 * AT_PADH)            // halves per tile
#define ATTN_SMEM_B (5 * AT_TILEH * 2)     // K[2]+V[2]+P = 46080 B

// ---------------- static scratch ----------------
__device__ __half g_h  [(size_t)NTOK * DIMV];     // ln1(x) fp16
__device__ __half g_qkv[(size_t)NTOK * QKV_LD];   // fused Q|K|V fp16
__device__ float  g_o  [(size_t)NTOK * DIMV];
__device__ float  g_x2 [(size_t)NTOK * DIMV];
__device__ __half g_h2 [(size_t)NTOK * DIMV];
__device__ __half g_mid[(size_t)NTOK * HIDV];
__device__ __half g_wt [(size_t)QKV_LD * DIMV];
__device__ __half g_w1t[(size_t)HIDV * DIMV];
__device__ __half g_w2t[(size_t)DIMV * HIDV];
__device__ float  g_bqkv[QKV_LD];

// ---------------- helpers ----------------
__device__ __forceinline__ uint32_t smem_u32(const void* p) {
    uint32_t a;
    asm("{ .reg .u64 t; cvta.to.shared.u64 t, %1; cvt.u32.u64 %0, t; }" : "=r"(a) : "l"(p));
    return a;
}

__device__ __forceinline__ float gelu_exact(float x) {
    return 0.5f * x * (1.0f + erff(x * 0.70710678118654752f));
}

__device__ __forceinline__ void cp_async16(uint32_t dst, const void* src) {
    asm volatile("cp.async.cg.shared.global [%0], [%1], 16;" :: "r"(dst), "l"(src));
}
#define CP_COMMIT() asm volatile("cp.async.commit_group;" ::: "memory")
#define CP_WAIT1()  asm volatile("cp.async.wait_group 1;" ::: "memory")
#define CP_WAIT0()  asm volatile("cp.async.wait_group 0;" ::: "memory")

__device__ __forceinline__ void mma_f16(float* c, const uint32_t* a, const uint32_t* b) {
    asm volatile(
        "mma.sync.aligned.m16n8k16.row.col.f32.f16.f16.f32 "
        "{%0,%1,%2,%3}, {%4,%5,%6,%7}, {%8,%9}, {%0,%1,%2,%3};"
        : "+f"(c[0]), "+f"(c[1]), "+f"(c[2]), "+f"(c[3])
        : "r"(a[0]), "r"(a[1]), "r"(a[2]), "r"(a[3]), "r"(b[0]), "r"(b[1]));
}

// ---------------- weight transposes (fp16 output) ----------------
__global__ void transpose_kernel_h16(const float* __restrict__ src, __half* __restrict__ dst,
                                     int R, int C)
{
    __shared__ float t[32][33];
    int c0 = blockIdx.x * 32, r0 = blockIdx.y * 32;
    int tx = threadIdx.x, ty = threadIdx.y;
    #pragma unroll
    for (int i = 0; i < 32; i += 8)
        t[ty + i][tx] = src[(size_t)(r0 + ty + i) * C + c0 + tx];
    __syncthreads();
    #pragma unroll
    for (int i = 0; i < 32; i += 8)
        dst[(size_t)(c0 + ty + i) * R + r0 + tx] = __float2half_rn(t[tx][ty + i]);
}

__global__ void transpose_qkv_kernel(const float* __restrict__ Wq, const float* __restrict__ Wk,
                                     const float* __restrict__ Wv, __half* __restrict__ dst)
{
    __shared__ float t[32][33];
    int s = blockIdx.z, w = s >> 4, h = s & 15;
    const float* W = ((w == 0) ? Wq : (w == 1) ? Wk : Wv) + (size_t)h * DIMV * HDIMV;
    __half* D = dst + (size_t)(w * 1024 + h * 64) * DIMV;
    int c0 = blockIdx.x * 32, r0 = blockIdx.y * 32;
    int tx = threadIdx.x, ty = threadIdx.y;
    #pragma unroll
    for (int i = 0; i < 32; i += 8)
        t[ty + i][tx] = W[(size_t)(r0 + ty + i) * HDIMV + c0 + tx];
    __syncthreads();
    #pragma unroll
    for (int i = 0; i < 32; i += 8)
        D[(size_t)(c0 + ty + i) * DIMV + r0 + tx] = __float2half_rn(t[tx][ty + i]);
}

__global__ void pack_bias_kernel(const float* __restrict__ bq, const float* __restrict__ bk,
                                 const float* __restrict__ bv, float* __restrict__ dst)
{
    int i = blockIdx.x * 256 + threadIdx.x;
    float v = (i < 1024) ? bq[i] : (i < 2048) ? bk[i - 1024] : bv[i - 2048];
    dst[i] = v;
}

// ---------------- LayerNorm (fp16 output) ----------------
__global__ void ln_kernel(const float* __restrict__ x, const float* __restrict__ g,
                          const float* __restrict__ b, __half* __restrict__ y)
{
    __shared__ float s_a[8], s_b[8];
    __shared__ float s_mu, s_rs;
    size_t row = blockIdx.x;
    int tid = threadIdx.x;
    float4 v = ((const float4*)(x + row * DIMV))[tid];
    float sum = v.x + v.y + v.z + v.w;
    float sq  = v.x*v.x + v.y*v.y + v.z*v.z + v.w*v.w;
    #pragma unroll
    for (int o = 16; o; o >>= 1) {
        sum += __shfl_xor_sync(0xffffffffu, sum, o);
        sq  += __shfl_xor_sync(0xffffffffu, sq,  o);
    }
    if ((tid & 31) == 0) { s_a[tid >> 5] = sum; s_b[tid >> 5] = sq; }
    __syncthreads();
    if (tid == 0) {
        float ts = 0.f, tq = 0.f;
        #pragma unroll
        for (int i = 0; i < 8; i++) { ts += s_a[i]; tq += s_b[i]; }
        float mu  = ts * (1.0f / DIMV);
        float var = tq * (1.0f / DIMV) - mu * mu;
        s_mu = mu; s_rs = rsqrtf(var + 1e-5f);
    }
    __syncthreads();
    float mu = s_mu, rs = s_rs;
    float4 gv = ((const float4*)g)[tid];
    float4 bv = ((const float4*)b)[tid];
    __half2 h0, h1;
    h0.x = __float2half_rn((v.x - mu) * rs * gv.x + bv.x);
    h0.y = __float2half_rn((v.y - mu) * rs * gv.y + bv.y);
    h1.x = __float2half_rn((v.z - mu) * rs * gv.z + bv.z);
    h1.y = __float2half_rn((v.w - mu) * rs * gv.w + bv.w);
    ((__half2*)(y + row * DIMV))[tid * 2 + 0] = h0;
    ((__half2*)(y + row * DIMV))[tid * 2 + 1] = h1;
}

// ---------------- residual add + LN(ln2) + LN(fcln), h2 out fp16 ----------------
__global__ void add_dln_kernel(const float* __restrict__ x, const float* __restrict__ oatt,
                               const float* __restrict__ g2, const float* __restrict__ b2,
                               const float* __restrict__ gf, const float* __restrict__ bf,
                               float* __restrict__ x2, __half* __restrict__ h2)
{
    __shared__ float s_a[8], s_b[8];
    __shared__ float s_mu, s_rs;
    size_t row = blockIdx.x;
    int tid = threadIdx.x;
    float4 v  = ((const float4*)(x    + row * DIMV))[tid];
    float4 ov = ((const float4*)(oatt + row * DIMV))[tid];
    v.x += ov.x; v.y += ov.y; v.z += ov.z; v.w += ov.w;
    ((float4*)(x2 + row * DIMV))[tid] = v;

    float sum = v.x + v.y + v.z + v.w;
    float sq  = v.x*v.x + v.y*v.y + v.z*v.z + v.w*v.w;
    #pragma unroll
    for (int o = 16; o; o >>= 1) {
        sum += __shfl_xor_sync(0xffffffffu, sum, o);
        sq  += __shfl_xor_sync(0xffffffffu, sq,  o);
    }
    if ((tid & 31) == 0) { s_a[tid >> 5] = sum; s_b[tid >> 5] = sq; }
    __syncthreads();
    if (tid == 0) {
        float ts = 0.f, tq = 0.f;
        #pragma unroll
        for (int i = 0; i < 8; i++) { ts += s_a[i]; tq += s_b[i]; }
        float mu  = ts * (1.0f / DIMV);
        float var = tq * (1.0f / DIMV) - mu * mu;
        s_mu = mu; s_rs = rsqrtf(var + 1e-5f);
    }
    __syncthreads();
    float mu1 = s_mu, rs1 = s_rs;
    float4 g2v = ((const float4*)g2)[tid];
    float4 b2v = ((const float4*)b2)[tid];
    float4 t;
    t.x = (v.x - mu1) * rs1 * g2v.x + b2v.x;
    t.y = (v.y - mu1) * rs1 * g2v.y + b2v.y;
    t.z = (v.z - mu1) * rs1 * g2v.z + b2v.z;
    t.w = (v.w - mu1) * rs1 * g2v.w + b2v.w;

    float sum2 = t.x + t.y + t.z + t.w;
    float sq2  = t.x*t.x + t.y*t.y + t.z*t.z + t.w*t.w;
    #pragma unroll
    for (int o = 16; o; o >>= 1) {
        sum2 += __shfl_xor_sync(0xffffffffu, sum2, o);
        sq2  += __shfl_xor_sync(0xffffffffu, sq2,  o);
    }
    if ((tid & 31) == 0) { s_a[tid >> 5] = sum2; s_b[tid >> 5] = sq2; }
    __syncthreads();
    if (tid == 0) {
        float ts = 0.f, tq = 0.f;
        #pragma unroll
        for (int i = 0; i < 8; i++) { ts += s_a[i]; tq += s_b[i]; }
        float mu  = ts * (1.0f / DIMV);
        float var = tq * (1.0f / DIMV) - mu * mu;
        s_mu = mu; s_rs = rsqrtf(var + 1e-5f);
    }
    __syncthreads();
    float mu2 = s_mu, rs2 = s_rs;
    float4 gfv = ((const float4*)gf)[tid];
    float4 bfv = ((const float4*)bf)[tid];
    __half2 h0, h1;
    h0.x = __float2half_rn((t.x - mu2) * rs2 * gfv.x + bfv.x);
    h0.y = __float2half_rn((t.y - mu2) * rs2 * gfv.y + bfv.y);
    h1.x = __float2half_rn((t.z - mu2) * rs2 * gfv.z + bfv.z);
    h1.y = __float2half_rn((t.w - mu2) * rs2 * gfv.w + bfv.w);
    ((__half2*)(h2 + row * DIMV))[tid * 2 + 0] = h0;
    ((__half2*)(h2 + row * DIMV))[tid * 2 + 1] = h1;
}

// ---------------- fp16 GEMM: C = act(A @ Bt^T + bias) (+res) ----------------
template<int ACT, int RES, int OUT16>
__global__ void __launch_bounds__(256) gemm_f16(
    const __half* __restrict__ A, const __half* __restrict__ Bt,
    const float* __restrict__ bias, const float* __restrict__ resid,
    void* __restrict__ Cout, int N, int K)
{
    extern __shared__ float sm[];
    uint32_t* smu = (uint32_t*)sm;
    const int tid  = threadIdx.x;
    const int lane = tid & 31;
    const int warp = tid >> 5;
    const int wm = warp >> 2;
    const int wn = warp & 3;
    const int m0 = blockIdx.y * BM;
    const int n0 = blockIdx.x * BN;
    const int KT = K / BKS16;

    const int lrow = tid >> 2;
    const int lk8  = (tid & 3) * 8;
    const int lk4  = (tid & 3) * 4;

    const __half* Asrc0 = A  + (size_t)(m0 + lrow)      * K + lk8;
    const __half* Asrc1 = A  + (size_t)(m0 + lrow + 64) * K + lk8;
    const __half* Bsrc0 = Bt + (size_t)(n0 + lrow)      * K + lk8;
    const __half* Bsrc1 = Bt + (size_t)(n0 + lrow + 64) * K + lk8;

    const uint32_t smb = smem_u32(sm);
    const uint32_t dA0 = smb + ((lrow)      * 20 + lk4) * 4;
    const uint32_t dA1 = smb + ((lrow + 64) * 20 + lk4) * 4;
    const uint32_t dB0 = dA0 + TILE_H * 4;
    const uint32_t dB1 = dA1 + TILE_H * 4;

    #pragma unroll
    for (int s = 0; s < 2; s++) {
        uint32_t off = s * STAGE_H * 4;
        int k0 = s * BKS16;
        cp_async16(dA0 + off, Asrc0 + k0);
        cp_async16(dA1 + off, Asrc1 + k0);
        cp_async16(dB0 + off, Bsrc0 + k0);
        cp_async16(dB1 + off, Bsrc1 + k0);
        CP_COMMIT();
    }

    float acc[4][4][4] = {};
    const int gr = lane >> 2;
    const int tg = lane & 3;

    for (int kt = 0; kt < KT; kt++) {
        CP_WAIT1();
        __syncthreads();
        const uint32_t* As = smu + (kt % 3) * STAGE_H;
        const uint32_t* Bs = As + TILE_H;

        #pragma unroll
        for (int kc = 0; kc < 2; kc++) {
            uint32_t af[4][4], bf[4][2];
            #pragma unroll
            for (int mb = 0; mb < 4; mb++) {
                int r = wm * 64 + mb * 16 + gr;
                af[mb][0] = As[(r)     * 20 + kc * 8 + tg];
                af[mb][1] = As[(r + 8) * 20 + kc * 8 + tg];
                af[mb][2] = As[(r)     * 20 + kc * 8 + 4 + tg];
                af[mb][3] = As[(r + 8) * 20 + kc * 8 + 4 + tg];
            }
            #pragma unroll
            for (int nb = 0; nb < 4; nb++) {
                int c = wn * 32 + nb * 8 + gr;
                bf[nb][0] = Bs[c * 20 + kc * 8 + tg];
                bf[nb][1] = Bs[c * 20 + kc * 8 + 4 + tg];
            }
            #pragma unroll
            for (int mb = 0; mb < 4; mb++)
                #pragma unroll
                for (int nb = 0; nb < 4; nb++)
                    mma_f16(acc[mb][nb], af[mb], bf[nb]);
        }

        if (kt + 2 < KT) {
            uint32_t off = ((kt + 2) % 3) * STAGE_H * 4;
            int k0 = (kt + 2) * BKS16;
            cp_async16(dA0 + off, Asrc0 + k0);
            cp_async16(dA1 + off, Asrc1 + k0);
            cp_async16(dB0 + off, Bsrc0 + k0);
            cp_async16(dB1 + off, Bsrc1 + k0);
        }
        CP_COMMIT();
        __syncthreads();
    }

    #pragma unroll
    for (int mb = 0; mb < 4; mb++) {
        int rlo = m0 + wm * 64 + mb * 16 + gr;
        #pragma unroll
        for (int nb = 0; nb < 4; nb++) {
            int col = n0 + wn * 32 + nb * 8 + tg * 2;
            float2 bi = *(const float2*)(bias + col);
            #pragma unroll
            for (int half_i = 0; half_i < 2; half_i++) {
                int row = rlo + half_i * 8;
                float v0 = acc[mb][nb][half_i * 2 + 0] + bi.x;
                float v1 = acc[mb][nb][half_i * 2 + 1] + bi.y;
                if (ACT) { v0 = gelu_exact(v0); v1 = gelu_exact(v1); }
                if (RES) {
                    float2 rv = *(const float2*)(resid + (size_t)row * N + col);
                    v0 += rv.x; v1 += rv.y;
                }
                if (OUT16) {
                    __half2 o2;
                    o2.x = __float2half_rn(v0);
                    o2.y = __float2half_rn(v1);
                    *(__half2*)((__half*)Cout + (size_t)row * N + col) = o2;
                } else {
                    float2 o2; o2.x = v0; o2.y = v1;
                    *(float2*)((float*)Cout + (size_t)row * N + col) = o2;
                }
            }
        }
    }
}

// ---------------- fp16 tensor-core flash attention ----------------
// 128 threads (4 warps), 64 q-rows per block, one (b,h). K/V fp16 tiles double-buffered.
__global__ void __launch_bounds__(128) attn_kernel(
    const __half* __restrict__ QKV, float* __restrict__ O)
{
    extern __shared__ __half smh[];
    __half* Ks = smh;                      // [2][64][AT_PADH]
    __half* Vs = smh + 2 * AT_TILEH;       // [2][64][AT_PADH]
    __half* Ps = smh + 4 * AT_TILEH;       // [64][AT_PADH]

    const int qt = blockIdx.x;
    const int bh = blockIdx.y;
    const int b  = bh >> 4;
    const int h  = bh & 15;
    const int tid  = threadIdx.x;
    const int lane = tid & 31;
    const int w    = tid >> 5;
    const int gr   = lane >> 2;
    const int tg   = lane & 3;

    const __half* Qb = QKV + (size_t)b * SEQ * QKV_LD + h * HDIMV;
    const __half* Kb = Qb + 1024;
    const __half* Vb = Qb + 2048;

    const uint32_t smb  = smem_u32(smh);
    const uint32_t KsB  = smb;
    const uint32_t VsB  = smb + 2 * AT_TILEH * 2;

    // ---- Q fragments straight from global (scaled by 1/8, exact in fp16) ----
    uint32_t qf[4][4];
    {
        const __half2 sc = __float2half2_rn(0.125f);
        const int r = qt * 64 + w * 16 + gr;
        #pragma unroll
        for (int kc = 0; kc < 4; kc++) {
            #pragma unroll
            for (int e = 0; e < 4; e++) {
                int rr = r + ((e & 1) ? 8 : 0);
                int dd = kc * 16 + ((e & 2) ? 8 : 0) + tg * 2;
                __half2 v = *(const __half2*)(Qb + (size_t)rr * QKV_LD + dd);
                v = __hmul2(v, sc);
                qf[kc][e] = *(uint32_t*)&v;
            }
        }
    }

    // ---- prologue: load K/V tile 0 (64 rows x 128 B each) ----
    #pragma unroll
    for (int j = 0; j < 4; j++) {
        int idx = j * 128 + tid;          // 0..511
        int r  = idx >> 3;
        int c8 = (idx & 7) * 8;           // half offset
        uint32_t doff = (r * AT_PADH + c8) * 2;
        cp_async16(KsB + doff, Kb + (size_t)r * QKV_LD + c8);
        cp_async16(VsB + doff, Vb + (size_t)r * QKV_LD + c8);
    }
    CP_COMMIT();

    float oacc[8][4] = {};
    float rm[2] = { -3e38f, -3e38f };
    float rl[2] = { 0.f, 0.f };

    for (int kt = 0; kt <= qt; kt++) {
        const int buf = kt & 1;
        if (kt < qt) {
            const int nbuf = (kt + 1) & 1;
            const size_t krow0 = (size_t)(kt + 1) * 64;
            #pragma unroll
            for (int j = 0; j < 4; j++) {
                int idx = j * 128 + tid;
                int r  = idx >> 3;
                int c8 = (idx & 7) * 8;
                uint32_t doff = (nbuf * AT_TILEH + r * AT_PADH + c8) * 2;
                cp_async16(KsB + doff, Kb + (krow0 + r) * QKV_LD + c8);
                cp_async16(VsB + doff, Vb + (krow0 + r) * QKV_LD + c8);
            }
            CP_COMMIT();
            CP_WAIT1();
        } else {
            CP_WAIT0();
        }
        __syncthreads();

        const __half* Kt = Ks + buf * AT_TILEH;
        const __half* Vt = Vs + buf * AT_TILEH;

        // ---- S = Q @ K^T (fp16 mma, 32 mmas) ----
        float s[8][4] = {};
        #pragma unroll
        for (int kc = 0; kc < 4; kc++) {
            uint32_t bf[8][2];
            #pragma unroll
            for (int nb = 0; nb < 8; nb++) {
                const __half* kp = Kt + (nb * 8 + gr) * AT_PADH + kc * 16 + tg * 2;
                bf[nb][0] = *(const uint32_t*)(kp);
                bf[nb][1] = *(const uint32_t*)(kp + 8);
            }
            #pragma unroll
            for (int nb = 0; nb < 8; nb++)
                mma_f16(s[nb], qf[kc], bf[nb]);
        }

        // ---- causal mask on diagonal tile ----
        if (kt == qt) {
            #pragma unroll
            for (int nb = 0; nb < 8; nb++)
                #pragma unroll
                for (int e = 0; e < 4; e++) {
                    int row = w * 16 + gr + (e >> 1) * 8;
                    int col = nb * 8 + tg * 2 + (e & 1);
                    if (col > row) s[nb][e] = -3e38f;
                }
        }

        // ---- online softmax (register stats, quad shuffle) ----
        float alpha[2];
        #pragma unroll
        for (int hh = 0; hh < 2; hh++) {
            float mloc = -3e38f;
            #pragma unroll
            for (int nb = 0; nb < 8; nb++) {
                mloc = fmaxf(mloc, s[nb][hh * 2 + 0]);
                mloc = fmaxf(mloc, s[nb][hh * 2 + 1]);
            }
            mloc = fmaxf(mloc, __shfl_xor_sync(0xffffffffu, mloc, 1));
            mloc = fmaxf(mloc, __shfl_xor_sync(0xffffffffu, mloc, 2));
            float mnew = fmaxf(rm[hh], mloc);
            alpha[hh] = __expf(rm[hh] - mnew);
            float suml = 0.f;
            #pragma unroll
            for (int nb = 0; nb < 8; nb++) {
                float p0 = __expf(s[nb][hh * 2 + 0] - mnew);
                float p1 = __expf(s[nb][hh * 2 + 1] - mnew);
                s[nb][hh * 2 + 0] = p0;
                s[nb][hh * 2 + 1] = p1;
                suml += p0 + p1;
            }
            suml += __shfl_xor_sync(0xffffffffu, suml, 1);
            suml += __shfl_xor_sync(0xffffffffu, suml, 2);
            rl[hh] = rl[hh] * alpha[hh] + suml;
            rm[hh] = mnew;
        }

        #pragma unroll
        for (int nb = 0; nb < 8; nb++) {
            oacc[nb][0] *= alpha[0]; oacc[nb][1] *= alpha[0];
            oacc[nb][2] *= alpha[1]; oacc[nb][3] *= alpha[1];
        }

        // ---- pack P (fp16) into smem strip ----
        {
            const int r0s = w * 16 + gr;
            #pragma unroll
            for (int nb = 0; nb < 8; nb++) {
                *(__half2*)(Ps + (r0s)     * AT_PADH + nb * 8 + tg * 2) =
                    __floats2half2_rn(s[nb][0], s[nb][1]);
                *(__half2*)(Ps + (r0s + 8) * AT_PADH + nb * 8 + tg * 2) =
                    __floats2half2_rn(s[nb][2], s[nb][3]);
            }
        }
        __syncwarp();

        // ---- O += P @ V (fp16 mma, 32 mmas) ----
        {
            const int r = w * 16 + gr;
            #pragma unroll
            for (int kc = 0; kc < 4; kc++) {
                uint32_t af[4];
                af[0] = *(const uint32_t*)(Ps + (r)     * AT_PADH + kc * 16 + tg * 2);
                af[1] = *(const uint32_t*)(Ps + (r + 8) * AT_PADH + kc * 16 + tg * 2);
                af[2] = *(const uint32_t*)(Ps + (r)     * AT_PADH + kc * 16 + 8 + tg * 2);
                af[3] = *(const uint32_t*)(Ps + (r + 8) * AT_PADH + kc * 16 + 8 + tg * 2);
                uint32_t bf[8][2];
                #pragma unroll
                for (int nb = 0; nb < 8; nb++) {
                    int d = nb * 8 + gr;
                    int t0 = kc * 16 + tg * 2;
                    __half2 b0 = __halves2half2(Vt[(t0)     * AT_PADH + d],
                                                Vt[(t0 + 1) * AT_PADH + d]);
                    __half2 b1 = __halves2half2(Vt[(t0 + 8) * AT_PADH + d],
                                                Vt[(t0 + 9) * AT_PADH + d]);
                    bf[nb][0] = *(uint32_t*)&b0;
                    bf[nb][1] = *(uint32_t*)&b1;
                }
                #pragma unroll
                for (int nb = 0; nb < 8; nb++)
                    mma_f16(oacc[nb], af, bf[nb]);
            }
        }
        __syncthreads();   // protect K/V/P buffers before next iteration's loads
    }

    // ---- normalize + write (concat-head layout) ----
    float linv0 = 1.0f / rl[0];
    float linv1 = 1.0f / rl[1];
    #pragma unroll
    for (int hh = 0; hh < 2; hh++) {
        size_t row = (size_t)b * SEQ + (size_t)(qt * 64 + w * 16 + gr + hh * 8);
        float linv = hh ? linv1 : linv0;
        #pragma unroll
        for (int nb = 0; nb < 8; nb++) {
            float2 o2;
            o2.x = oacc[nb][hh * 2 + 0] * linv;
            o2.y = oacc[nb][hh * 2 + 1] * linv;
            *(float2*)(O + row * DIMV + h * HDIMV + nb * 8 + tg * 2) = o2;
        }
    }
}

extern "C" void kernel_launch(void* const* d_in, const int* in_sizes, int n_in,
                              void* d_out, int out_size)
{
    const float* x    = (const float*)d_in[0];
    const float* ln1g = (const float*)d_in[1];
    const float* ln1b = (const float*)d_in[2];
    const float* Wq   = (const float*)d_in[3];
    const float* bq   = (const float*)d_in[4];
    const float* Wk   = (const float*)d_in[5];
    const float* bk   = (const float*)d_in[6];
    const float* Wv   = (const float*)d_in[7];
    const float* bv   = (const float*)d_in[8];
    const float* ln2g = (const float*)d_in[9];
    const float* ln2b = (const float*)d_in[10];
    const float* fclg = (const float*)d_in[11];
    const float* fclb = (const float*)d_in[12];
    const float* W1   = (const float*)d_in[13];
    const float* b1   = (const float*)d_in[14];
    const float* W2   = (const float*)d_in[15];
    const float* b2   = (const float*)d_in[16];
    float* out = (float*)d_out;

    float *p_o, *p_x2, *p_bqkv;
    __half *p_h, *p_qkv, *p_h2, *p_mid, *p_wt, *p_w1t, *p_w2t;
    cudaGetSymbolAddress((void**)&p_h,    g_h);
    cudaGetSymbolAddress((void**)&p_qkv,  g_qkv);
    cudaGetSymbolAddress((void**)&p_o,    g_o);
    cudaGetSymbolAddress((void**)&p_x2,   g_x2);
    cudaGetSymbolAddress((void**)&p_h2,   g_h2);
    cudaGetSymbolAddress((void**)&p_mid,  g_mid);
    cudaGetSymbolAddress((void**)&p_wt,   g_wt);
    cudaGetSymbolAddress((void**)&p_w1t,  g_w1t);
    cudaGetSymbolAddress((void**)&p_w2t,  g_w2t);
    cudaGetSymbolAddress((void**)&p_bqkv, g_bqkv);

    cudaFuncSetAttribute(attn_kernel, cudaFuncAttributeMaxDynamicSharedMemorySize, ATTN_SMEM_B);
    cudaFuncSetAttribute(gemm_f16<0,0,1>, cudaFuncAttributeMaxDynamicSharedMemorySize, GEMM_SMEM_BYTES);
    cudaFuncSetAttribute(gemm_f16<1,0,1>, cudaFuncAttributeMaxDynamicSharedMemorySize, GEMM_SMEM_BYTES);
    cudaFuncSetAttribute(gemm_f16<1,1,0>, cudaFuncAttributeMaxDynamicSharedMemorySize, GEMM_SMEM_BYTES);

    transpose_qkv_kernel<<<dim3(2, 32, 48), dim3(32, 8)>>>(Wq, Wk, Wv, p_wt);
    transpose_kernel_h16<<<dim3(HIDV / 32, DIMV / 32), dim3(32, 8)>>>(W1, p_w1t, DIMV, HIDV);
    transpose_kernel_h16<<<dim3(DIMV / 32, HIDV / 32), dim3(32, 8)>>>(W2, p_w2t, HIDV, DIMV);
    pack_bias_kernel<<<QKV_LD / 256, 256>>>(bq, bk, bv, p_bqkv);
    ln_kernel<<<NTOK, 256>>>(x, ln1g, ln1b, p_h);
    // QKV projection (fp16 in/out)
    gemm_f16<0,0,1><<<dim3(QKV_LD / BN, NTOK / BM), 256, GEMM_SMEM_BYTES>>>(
        p_h, p_wt, p_bqkv, nullptr, p_qkv, QKV_LD, DIMV);
    attn_kernel<<<dim3(SEQ / 64, 64), 128, ATTN_SMEM_B>>>(p_qkv, p_o);
    add_dln_kernel<<<NTOK, 256>>>(x, p_o, ln2g, ln2b, fclg, fclb, p_x2, p_h2);
    gemm_f16<1,0,1><<<dim3(HIDV / BN, NTOK / BM), 256, GEMM_SMEM_BYTES>>>(
        p_h2, p_w1t, b1, nullptr, p_mid, HIDV, DIMV);
    gemm_f16<1,1,0><<<dim3(DIMV / BN, NTOK / BM), 256, GEMM_SMEM_BYTES>>>(
        p_mid, p_w2t, b2, p_x2, out, DIMV, HIDV);
}

// round 9
// speedup vs baseline: 8.9673x; 1.0063x over previous
#include <cuda_runtime.h>
#include <cuda_fp16.h>
#include <cstdint>
#include <cstddef>

// Problem dims
#define DIMV   1024
#define HIDV   4096
#define SEQ    2048
#define NHEAD  16
#define HDIMV  64
#define NTOK   8192          // B * S
#define QKV_LD 3072          // fused QKV row stride

// GEMM tiling (fp16 mma m16n8k16): 128x128 tile, 32 K per stage
#define BM 128
#define BN 128
#define BKS16 32
#define TILE_H 2560          // 128 rows * 20 b32 (40 halves padded)
#define STAGE_H 5120
#define GEMM_SMEM_BYTES (3 * STAGE_H * 4)   // 61440

// attention smem (fp16 tiles)
#define AT_PADH 72                         // halves per row (64 + 8 pad)
#define AT_TILEH (64 * AT_PADH)            // halves per tile
#define ATTN_SMEM_B (5 * AT_TILEH * 2)     // K[2]+V[2]+P = 46080 B

// ---------------- static scratch ----------------
__device__ __half g_h  [(size_t)NTOK * DIMV];     // ln1(x) fp16
__device__ __half g_qkv[(size_t)NTOK * QKV_LD];   // fused Q|K|V fp16
__device__ float  g_o  [(size_t)NTOK * DIMV];
__device__ float  g_x2 [(size_t)NTOK * DIMV];
__device__ __half g_h2 [(size_t)NTOK * DIMV];
__device__ __half g_mid[(size_t)NTOK * HIDV];
__device__ __half g_wt [(size_t)QKV_LD * DIMV];
__device__ __half g_w1t[(size_t)HIDV * DIMV];
__device__ __half g_w2t[(size_t)DIMV * HIDV];
__device__ float  g_bqkv[QKV_LD];

// ---------------- helpers ----------------
__device__ __forceinline__ uint32_t smem_u32(const void* p) {
    uint32_t a;
    asm("{ .reg .u64 t; cvta.to.shared.u64 t, %1; cvt.u32.u64 %0, t; }" : "=r"(a) : "l"(p));
    return a;
}

__device__ __forceinline__ float gelu_exact(float x) {
    return 0.5f * x * (1.0f + erff(x * 0.70710678118654752f));
}

__device__ __forceinline__ void cp_async16(uint32_t dst, const void* src) {
    asm volatile("cp.async.cg.shared.global [%0], [%1], 16;" :: "r"(dst), "l"(src));
}
#define CP_COMMIT() asm volatile("cp.async.commit_group;" ::: "memory")
#define CP_WAIT1()  asm volatile("cp.async.wait_group 1;" ::: "memory")
#define CP_WAIT0()  asm volatile("cp.async.wait_group 0;" ::: "memory")

__device__ __forceinline__ void mma_f16(float* c, const uint32_t* a, const uint32_t* b) {
    asm volatile(
        "mma.sync.aligned.m16n8k16.row.col.f32.f16.f16.f32 "
        "{%0,%1,%2,%3}, {%4,%5,%6,%7}, {%8,%9}, {%0,%1,%2,%3};"
        : "+f"(c[0]), "+f"(c[1]), "+f"(c[2]), "+f"(c[3])
        : "r"(a[0]), "r"(a[1]), "r"(a[2]), "r"(a[3]), "r"(b[0]), "r"(b[1]));
}

// ---------------- weight transposes (fp16 output) ----------------
__global__ void transpose_kernel_h16(const float* __restrict__ src, __half* __restrict__ dst,
                                     int R, int C)
{
    __shared__ float t[32][33];
    int c0 = blockIdx.x * 32, r0 = blockIdx.y * 32;
    int tx = threadIdx.x, ty = threadIdx.y;
    #pragma unroll
    for (int i = 0; i < 32; i += 8)
        t[ty + i][tx] = src[(size_t)(r0 + ty + i) * C + c0 + tx];
    __syncthreads();
    #pragma unroll
    for (int i = 0; i < 32; i += 8)
        dst[(size_t)(c0 + ty + i) * R + r0 + tx] = __float2half_rn(t[tx][ty + i]);
}

__global__ void transpose_qkv_kernel(const float* __restrict__ Wq, const float* __restrict__ Wk,
                                     const float* __restrict__ Wv, __half* __restrict__ dst)
{
    __shared__ float t[32][33];
    int s = blockIdx.z, w = s >> 4, h = s & 15;
    const float* W = ((w == 0) ? Wq : (w == 1) ? Wk : Wv) + (size_t)h * DIMV * HDIMV;
    __half* D = dst + (size_t)(w * 1024 + h * 64) * DIMV;
    int c0 = blockIdx.x * 32, r0 = blockIdx.y * 32;
    int tx = threadIdx.x, ty = threadIdx.y;
    #pragma unroll
    for (int i = 0; i < 32; i += 8)
        t[ty + i][tx] = W[(size_t)(r0 + ty + i) * HDIMV + c0 + tx];
    __syncthreads();
    #pragma unroll
    for (int i = 0; i < 32; i += 8)
        D[(size_t)(c0 + ty + i) * DIMV + r0 + tx] = __float2half_rn(t[tx][ty + i]);
}

__global__ void pack_bias_kernel(const float* __restrict__ bq, const float* __restrict__ bk,
                                 const float* __restrict__ bv, float* __restrict__ dst)
{
    int i = blockIdx.x * 256 + threadIdx.x;
    float v = (i < 1024) ? bq[i] : (i < 2048) ? bk[i - 1024] : bv[i - 2048];
    dst[i] = v;
}

// ---------------- LayerNorm (fp16 output) ----------------
__global__ void ln_kernel(const float* __restrict__ x, const float* __restrict__ g,
                          const float* __restrict__ b, __half* __restrict__ y)
{
    __shared__ float s_a[8], s_b[8];
    __shared__ float s_mu, s_rs;
    size_t row = blockIdx.x;
    int tid = threadIdx.x;
    float4 v = ((const float4*)(x + row * DIMV))[tid];
    float sum = v.x + v.y + v.z + v.w;
    float sq  = v.x*v.x + v.y*v.y + v.z*v.z + v.w*v.w;
    #pragma unroll
    for (int o = 16; o; o >>= 1) {
        sum += __shfl_xor_sync(0xffffffffu, sum, o);
        sq  += __shfl_xor_sync(0xffffffffu, sq,  o);
    }
    if ((tid & 31) == 0) { s_a[tid >> 5] = sum; s_b[tid >> 5] = sq; }
    __syncthreads();
    if (tid == 0) {
        float ts = 0.f, tq = 0.f;
        #pragma unroll
        for (int i = 0; i < 8; i++) { ts += s_a[i]; tq += s_b[i]; }
        float mu  = ts * (1.0f / DIMV);
        float var = tq * (1.0f / DIMV) - mu * mu;
        s_mu = mu; s_rs = rsqrtf(var + 1e-5f);
    }
    __syncthreads();
    float mu = s_mu, rs = s_rs;
    float4 gv = ((const float4*)g)[tid];
    float4 bv = ((const float4*)b)[tid];
    __half2 h0, h1;
    h0.x = __float2half_rn((v.x - mu) * rs * gv.x + bv.x);
    h0.y = __float2half_rn((v.y - mu) * rs * gv.y + bv.y);
    h1.x = __float2half_rn((v.z - mu) * rs * gv.z + bv.z);
    h1.y = __float2half_rn((v.w - mu) * rs * gv.w + bv.w);
    ((__half2*)(y + row * DIMV))[tid * 2 + 0] = h0;
    ((__half2*)(y + row * DIMV))[tid * 2 + 1] = h1;
}

// ---------------- residual add + LN(ln2) + LN(fcln), h2 out fp16 ----------------
__global__ void add_dln_kernel(const float* __restrict__ x, const float* __restrict__ oatt,
                               const float* __restrict__ g2, const float* __restrict__ b2,
                               const float* __restrict__ gf, const float* __restrict__ bf,
                               float* __restrict__ x2, __half* __restrict__ h2)
{
    __shared__ float s_a[8], s_b[8];
    __shared__ float s_mu, s_rs;
    size_t row = blockIdx.x;
    int tid = threadIdx.x;
    float4 v  = ((const float4*)(x    + row * DIMV))[tid];
    float4 ov = ((const float4*)(oatt + row * DIMV))[tid];
    v.x += ov.x; v.y += ov.y; v.z += ov.z; v.w += ov.w;
    ((float4*)(x2 + row * DIMV))[tid] = v;

    float sum = v.x + v.y + v.z + v.w;
    float sq  = v.x*v.x + v.y*v.y + v.z*v.z + v.w*v.w;
    #pragma unroll
    for (int o = 16; o; o >>= 1) {
        sum += __shfl_xor_sync(0xffffffffu, sum, o);
        sq  += __shfl_xor_sync(0xffffffffu, sq,  o);
    }
    if ((tid & 31) == 0) { s_a[tid >> 5] = sum; s_b[tid >> 5] = sq; }
    __syncthreads();
    if (tid == 0) {
        float ts = 0.f, tq = 0.f;
        #pragma unroll
        for (int i = 0; i < 8; i++) { ts += s_a[i]; tq += s_b[i]; }
        float mu  = ts * (1.0f / DIMV);
        float var = tq * (1.0f / DIMV) - mu * mu;
        s_mu = mu; s_rs = rsqrtf(var + 1e-5f);
    }
    __syncthreads();
    float mu1 = s_mu, rs1 = s_rs;
    float4 g2v = ((const float4*)g2)[tid];
    float4 b2v = ((const float4*)b2)[tid];
    float4 t;
    t.x = (v.x - mu1) * rs1 * g2v.x + b2v.x;
    t.y = (v.y - mu1) * rs1 * g2v.y + b2v.y;
    t.z = (v.z - mu1) * rs1 * g2v.z + b2v.z;
    t.w = (v.w - mu1) * rs1 * g2v.w + b2v.w;

    float sum2 = t.x + t.y + t.z + t.w;
    float sq2  = t.x*t.x + t.y*t.y + t.z*t.z + t.w*t.w;
    #pragma unroll
    for (int o = 16; o; o >>= 1) {
        sum2 += __shfl_xor_sync(0xffffffffu, sum2, o);
        sq2  += __shfl_xor_sync(0xffffffffu, sq2,  o);
    }
    if ((tid & 31) == 0) { s_a[tid >> 5] = sum2; s_b[tid >> 5] = sq2; }
    __syncthreads();
    if (tid == 0) {
        float ts = 0.f, tq = 0.f;
        #pragma unroll
        for (int i = 0; i < 8; i++) { ts += s_a[i]; tq += s_b[i]; }
        float mu  = ts * (1.0f / DIMV);
        float var = tq * (1.0f / DIMV) - mu * mu;
        s_mu = mu; s_rs = rsqrtf(var + 1e-5f);
    }
    __syncthreads();
    float mu2 = s_mu, rs2 = s_rs;
    float4 gfv = ((const float4*)gf)[tid];
    float4 bfv = ((const float4*)bf)[tid];
    __half2 h0, h1;
    h0.x = __float2half_rn((t.x - mu2) * rs2 * gfv.x + bfv.x);
    h0.y = __float2half_rn((t.y - mu2) * rs2 * gfv.y + bfv.y);
    h1.x = __float2half_rn((t.z - mu2) * rs2 * gfv.z + bfv.z);
    h1.y = __float2half_rn((t.w - mu2) * rs2 * gfv.w + bfv.w);
    ((__half2*)(h2 + row * DIMV))[tid * 2 + 0] = h0;
    ((__half2*)(h2 + row * DIMV))[tid * 2 + 1] = h1;
}

// ---------------- fp16 GEMM: C = act(A @ Bt^T + bias) (+res) ----------------
template<int ACT, int RES, int OUT16>
__global__ void __launch_bounds__(256) gemm_f16(
    const __half* __restrict__ A, const __half* __restrict__ Bt,
    const float* __restrict__ bias, const float* __restrict__ resid,
    void* __restrict__ Cout, int N, int K)
{
    extern __shared__ float sm[];
    uint32_t* smu = (uint32_t*)sm;
    const int tid  = threadIdx.x;
    const int lane = tid & 31;
    const int warp = tid >> 5;
    const int wm = warp >> 2;
    const int wn = warp & 3;
    const int m0 = blockIdx.y * BM;
    const int n0 = blockIdx.x * BN;
    const int KT = K / BKS16;

    const int lrow = tid >> 2;
    const int lk8  = (tid & 3) * 8;
    const int lk4  = (tid & 3) * 4;

    const __half* Asrc0 = A  + (size_t)(m0 + lrow)      * K + lk8;
    const __half* Asrc1 = A  + (size_t)(m0 + lrow + 64) * K + lk8;
    const __half* Bsrc0 = Bt + (size_t)(n0 + lrow)      * K + lk8;
    const __half* Bsrc1 = Bt + (size_t)(n0 + lrow + 64) * K + lk8;

    const uint32_t smb = smem_u32(sm);
    const uint32_t dA0 = smb + ((lrow)      * 20 + lk4) * 4;
    const uint32_t dA1 = smb + ((lrow + 64) * 20 + lk4) * 4;
    const uint32_t dB0 = dA0 + TILE_H * 4;
    const uint32_t dB1 = dA1 + TILE_H * 4;

    #pragma unroll
    for (int s = 0; s < 2; s++) {
        uint32_t off = s * STAGE_H * 4;
        int k0 = s * BKS16;
        cp_async16(dA0 + off, Asrc0 + k0);
        cp_async16(dA1 + off, Asrc1 + k0);
        cp_async16(dB0 + off, Bsrc0 + k0);
        cp_async16(dB1 + off, Bsrc1 + k0);
        CP_COMMIT();
    }

    float acc[4][4][4] = {};
    const int gr = lane >> 2;
    const int tg = lane & 3;

    for (int kt = 0; kt < KT; kt++) {
        CP_WAIT1();
        __syncthreads();
        const uint32_t* As = smu + (kt % 3) * STAGE_H;
        const uint32_t* Bs = As + TILE_H;

        #pragma unroll
        for (int kc = 0; kc < 2; kc++) {
            uint32_t af[4][4], bf[4][2];
            #pragma unroll
            for (int mb = 0; mb < 4; mb++) {
                int r = wm * 64 + mb * 16 + gr;
                af[mb][0] = As[(r)     * 20 + kc * 8 + tg];
                af[mb][1] = As[(r + 8) * 20 + kc * 8 + tg];
                af[mb][2] = As[(r)     * 20 + kc * 8 + 4 + tg];
                af[mb][3] = As[(r + 8) * 20 + kc * 8 + 4 + tg];
            }
            #pragma unroll
            for (int nb = 0; nb < 4; nb++) {
                int c = wn * 32 + nb * 8 + gr;
                bf[nb][0] = Bs[c * 20 + kc * 8 + tg];
                bf[nb][1] = Bs[c * 20 + kc * 8 + 4 + tg];
            }
            #pragma unroll
            for (int mb = 0; mb < 4; mb++)
                #pragma unroll
                for (int nb = 0; nb < 4; nb++)
                    mma_f16(acc[mb][nb], af[mb], bf[nb]);
        }

        if (kt + 2 < KT) {
            uint32_t off = ((kt + 2) % 3) * STAGE_H * 4;
            int k0 = (kt + 2) * BKS16;
            cp_async16(dA0 + off, Asrc0 + k0);
            cp_async16(dA1 + off, Asrc1 + k0);
            cp_async16(dB0 + off, Bsrc0 + k0);
            cp_async16(dB1 + off, Bsrc1 + k0);
        }
        CP_COMMIT();
        __syncthreads();
    }

    #pragma unroll
    for (int mb = 0; mb < 4; mb++) {
        int rlo = m0 + wm * 64 + mb * 16 + gr;
        #pragma unroll
        for (int nb = 0; nb < 4; nb++) {
            int col = n0 + wn * 32 + nb * 8 + tg * 2;
            float2 bi = *(const float2*)(bias + col);
            #pragma unroll
            for (int half_i = 0; half_i < 2; half_i++) {
                int row = rlo + half_i * 8;
                float v0 = acc[mb][nb][half_i * 2 + 0] + bi.x;
                float v1 = acc[mb][nb][half_i * 2 + 1] + bi.y;
                if (ACT) { v0 = gelu_exact(v0); v1 = gelu_exact(v1); }
                if (RES) {
                    float2 rv = *(const float2*)(resid + (size_t)row * N + col);
                    v0 += rv.x; v1 += rv.y;
                }
                if (OUT16) {
                    __half2 o2;
                    o2.x = __float2half_rn(v0);
                    o2.y = __float2half_rn(v1);
                    *(__half2*)((__half*)Cout + (size_t)row * N + col) = o2;
                } else {
                    float2 o2; o2.x = v0; o2.y = v1;
                    *(float2*)((float*)Cout + (size_t)row * N + col) = o2;
                }
            }
        }
    }
}

// ---------------- fp16 tensor-core flash attention ----------------
// 128 threads (4 warps), 64 q-rows per block, one (b,h). K/V fp16 tiles double-buffered.
__global__ void __launch_bounds__(128) attn_kernel(
    const __half* __restrict__ QKV, float* __restrict__ O)
{
    extern __shared__ __half smh[];
    __half* Ks = smh;                      // [2][64][AT_PADH]
    __half* Vs = smh + 2 * AT_TILEH;       // [2][64][AT_PADH]
    __half* Ps = smh + 4 * AT_TILEH;       // [64][AT_PADH]

    const int qt = blockIdx.x;
    const int bh = blockIdx.y;
    const int b  = bh >> 4;
    const int h  = bh & 15;
    const int tid  = threadIdx.x;
    const int lane = tid & 31;
    const int w    = tid >> 5;
    const int gr   = lane >> 2;
    const int tg   = lane & 3;

    const __half* Qb = QKV + (size_t)b * SEQ * QKV_LD + h * HDIMV;
    const __half* Kb = Qb + 1024;
    const __half* Vb = Qb + 2048;

    const uint32_t smb  = smem_u32(smh);
    const uint32_t KsB  = smb;
    const uint32_t VsB  = smb + 2 * AT_TILEH * 2;

    // ---- Q fragments straight from global (scaled by 1/8, exact in fp16) ----
    uint32_t qf[4][4];
    {
        const __half2 sc = __float2half2_rn(0.125f);
        const int r = qt * 64 + w * 16 + gr;
        #pragma unroll
        for (int kc = 0; kc < 4; kc++) {
            #pragma unroll
            for (int e = 0; e < 4; e++) {
                int rr = r + ((e & 1) ? 8 : 0);
                int dd = kc * 16 + ((e & 2) ? 8 : 0) + tg * 2;
                __half2 v = *(const __half2*)(Qb + (size_t)rr * QKV_LD + dd);
                v = __hmul2(v, sc);
                qf[kc][e] = *(uint32_t*)&v;
            }
        }
    }

    // ---- prologue: load K/V tile 0 (64 rows x 128 B each) ----
    #pragma unroll
    for (int j = 0; j < 4; j++) {
        int idx = j * 128 + tid;          // 0..511
        int r  = idx >> 3;
        int c8 = (idx & 7) * 8;           // half offset
        uint32_t doff = (r * AT_PADH + c8) * 2;
        cp_async16(KsB + doff, Kb + (size_t)r * QKV_LD + c8);
        cp_async16(VsB + doff, Vb + (size_t)r * QKV_LD + c8);
    }
    CP_COMMIT();

    float oacc[8][4] = {};
    float rm[2] = { -3e38f, -3e38f };
    float rl[2] = { 0.f, 0.f };

    for (int kt = 0; kt <= qt; kt++) {
        const int buf = kt & 1;
        if (kt < qt) {
            const int nbuf = (kt + 1) & 1;
            const size_t krow0 = (size_t)(kt + 1) * 64;
            #pragma unroll
            for (int j = 0; j < 4; j++) {
                int idx = j * 128 + tid;
                int r  = idx >> 3;
                int c8 = (idx & 7) * 8;
                uint32_t doff = (nbuf * AT_TILEH + r * AT_PADH + c8) * 2;
                cp_async16(KsB + doff, Kb + (krow0 + r) * QKV_LD + c8);
                cp_async16(VsB + doff, Vb + (krow0 + r) * QKV_LD + c8);
            }
            CP_COMMIT();
            CP_WAIT1();
        } else {
            CP_WAIT0();
        }
        __syncthreads();

        const __half* Kt = Ks + buf * AT_TILEH;
        const __half* Vt = Vs + buf * AT_TILEH;

        // ---- S = Q @ K^T (fp16 mma, 32 mmas) ----
        float s[8][4] = {};
        #pragma unroll
        for (int kc = 0; kc < 4; kc++) {
            uint32_t bf[8][2];
            #pragma unroll
            for (int nb = 0; nb < 8; nb++) {
                const __half* kp = Kt + (nb * 8 + gr) * AT_PADH + kc * 16 + tg * 2;
                bf[nb][0] = *(const uint32_t*)(kp);
                bf[nb][1] = *(const uint32_t*)(kp + 8);
            }
            #pragma unroll
            for (int nb = 0; nb < 8; nb++)
                mma_f16(s[nb], qf[kc], bf[nb]);
        }

        // ---- causal mask on diagonal tile ----
        if (kt == qt) {
            #pragma unroll
            for (int nb = 0; nb < 8; nb++)
                #pragma unroll
                for (int e = 0; e < 4; e++) {
                    int row = w * 16 + gr + (e >> 1) * 8;
                    int col = nb * 8 + tg * 2 + (e & 1);
                    if (col > row) s[nb][e] = -3e38f;
                }
        }

        // ---- online softmax (register stats, quad shuffle) ----
        float alpha[2];
        #pragma unroll
        for (int hh = 0; hh < 2; hh++) {
            float mloc = -3e38f;
            #pragma unroll
            for (int nb = 0; nb < 8; nb++) {
                mloc = fmaxf(mloc, s[nb][hh * 2 + 0]);
                mloc = fmaxf(mloc, s[nb][hh * 2 + 1]);
            }
            mloc = fmaxf(mloc, __shfl_xor_sync(0xffffffffu, mloc, 1));
            mloc = fmaxf(mloc, __shfl_xor_sync(0xffffffffu, mloc, 2));
            float mnew = fmaxf(rm[hh], mloc);
            alpha[hh] = __expf(rm[hh] - mnew);
            float suml = 0.f;
            #pragma unroll
            for (int nb = 0; nb < 8; nb++) {
                float p0 = __expf(s[nb][hh * 2 + 0] - mnew);
                float p1 = __expf(s[nb][hh * 2 + 1] - mnew);
                s[nb][hh * 2 + 0] = p0;
                s[nb][hh * 2 + 1] = p1;
                suml += p0 + p1;
            }
            suml += __shfl_xor_sync(0xffffffffu, suml, 1);
            suml += __shfl_xor_sync(0xffffffffu, suml, 2);
            rl[hh] = rl[hh] * alpha[hh] + suml;
            rm[hh] = mnew;
        }

        #pragma unroll
        for (int nb = 0; nb < 8; nb++) {
            oacc[nb][0] *= alpha[0]; oacc[nb][1] *= alpha[0];
            oacc[nb][2] *= alpha[1]; oacc[nb][3] *= alpha[1];
        }

        // ---- pack P (fp16) into smem strip ----
        {
            const int r0s = w * 16 + gr;
            #pragma unroll
            for (int nb = 0; nb < 8; nb++) {
                *(__half2*)(Ps + (r0s)     * AT_PADH + nb * 8 + tg * 2) =
                    __floats2half2_rn(s[nb][0], s[nb][1]);
                *(__half2*)(Ps + (r0s + 8) * AT_PADH + nb * 8 + tg * 2) =
                    __floats2half2_rn(s[nb][2], s[nb][3]);
            }
        }
        __syncwarp();

        // ---- O += P @ V (fp16 mma, 32 mmas) ----
        {
            const int r = w * 16 + gr;
            #pragma unroll
            for (int kc = 0; kc < 4; kc++) {
                uint32_t af[4];
                af[0] = *(const uint32_t*)(Ps + (r)     * AT_PADH + kc * 16 + tg * 2);
                af[1] = *(const uint32_t*)(Ps + (r + 8) * AT_PADH + kc * 16 + tg * 2);
                af[2] = *(const uint32_t*)(Ps + (r)     * AT_PADH + kc * 16 + 8 + tg * 2);
                af[3] = *(const uint32_t*)(Ps + (r + 8) * AT_PADH + kc * 16 + 8 + tg * 2);
                uint32_t bf[8][2];
                #pragma unroll
                for (int nb = 0; nb < 8; nb++) {
                    int d = nb * 8 + gr;
                    int t0 = kc * 16 + tg * 2;
                    __half2 b0 = __halves2half2(Vt[(t0)     * AT_PADH + d],
                                                Vt[(t0 + 1) * AT_PADH + d]);
                    __half2 b1 = __halves2half2(Vt[(t0 + 8) * AT_PADH + d],
                                                Vt[(t0 + 9) * AT_PADH + d]);
                    bf[nb][0] = *(uint32_t*)&b0;
                    bf[nb][1] = *(uint32_t*)&b1;
                }
                #pragma unroll
                for (int nb = 0; nb < 8; nb++)
                    mma_f16(oacc[nb], af, bf[nb]);
            }
        }
        __syncthreads();   // protect K/V/P buffers before next iteration's loads
    }

    // ---- normalize + write (concat-head layout) ----
    float linv0 = 1.0f / rl[0];
    float linv1 = 1.0f / rl[1];
    #pragma unroll
    for (int hh = 0; hh < 2; hh++) {
        size_t row = (size_t)b * SEQ + (size_t)(qt * 64 + w * 16 + gr + hh * 8);
        float linv = hh ? linv1 : linv0;
        #pragma unroll
        for (int nb = 0; nb < 8; nb++) {
            float2 o2;
            o2.x = oacc[nb][hh * 2 + 0] * linv;
            o2.y = oacc[nb][hh * 2 + 1] * linv;
            *(float2*)(O + row * DIMV + h * HDIMV + nb * 8 + tg * 2) = o2;
        }
    }
}

extern "C" void kernel_launch(void* const* d_in, const int* in_sizes, int n_in,
                              void* d_out, int out_size)
{
    const float* x    = (const float*)d_in[0];
    const float* ln1g = (const float*)d_in[1];
    const float* ln1b = (const float*)d_in[2];
    const float* Wq   = (const float*)d_in[3];
    const float* bq   = (const float*)d_in[4];
    const float* Wk   = (const float*)d_in[5];
    const float* bk   = (const float*)d_in[6];
    const float* Wv   = (const float*)d_in[7];
    const float* bv   = (const float*)d_in[8];
    const float* ln2g = (const float*)d_in[9];
    const float* ln2b = (const float*)d_in[10];
    const float* fclg = (const float*)d_in[11];
    const float* fclb = (const float*)d_in[12];
    const float* W1   = (const float*)d_in[13];
    const float* b1   = (const float*)d_in[14];
    const float* W2   = (const float*)d_in[15];
    const float* b2   = (const float*)d_in[16];
    float* out = (float*)d_out;

    float *p_o, *p_x2, *p_bqkv;
    __half *p_h, *p_qkv, *p_h2, *p_mid, *p_wt, *p_w1t, *p_w2t;
    cudaGetSymbolAddress((void**)&p_h,    g_h);
    cudaGetSymbolAddress((void**)&p_qkv,  g_qkv);
    cudaGetSymbolAddress((void**)&p_o,    g_o);
    cudaGetSymbolAddress((void**)&p_x2,   g_x2);
    cudaGetSymbolAddress((void**)&p_h2,   g_h2);
    cudaGetSymbolAddress((void**)&p_mid,  g_mid);
    cudaGetSymbolAddress((void**)&p_wt,   g_wt);
    cudaGetSymbolAddress((void**)&p_w1t,  g_w1t);
    cudaGetSymbolAddress((void**)&p_w2t,  g_w2t);
    cudaGetSymbolAddress((void**)&p_bqkv, g_bqkv);

    cudaFuncSetAttribute(attn_kernel, cudaFuncAttributeMaxDynamicSharedMemorySize, ATTN_SMEM_B);
    cudaFuncSetAttribute(gemm_f16<0,0,1>, cudaFuncAttributeMaxDynamicSharedMemorySize, GEMM_SMEM_BYTES);
    cudaFuncSetAttribute(gemm_f16<1,0,1>, cudaFuncAttributeMaxDynamicSharedMemorySize, GEMM_SMEM_BYTES);
    cudaFuncSetAttribute(gemm_f16<1,1,0>, cudaFuncAttributeMaxDynamicSharedMemorySize, GEMM_SMEM_BYTES);

    transpose_qkv_kernel<<<dim3(2, 32, 48), dim3(32, 8)>>>(Wq, Wk, Wv, p_wt);
    transpose_kernel_h16<<<dim3(HIDV / 32, DIMV / 32), dim3(32, 8)>>>(W1, p_w1t, DIMV, HIDV);
    transpose_kernel_h16<<<dim3(DIMV / 32, HIDV / 32), dim3(32, 8)>>>(W2, p_w2t, HIDV, DIMV);
    pack_bias_kernel<<<QKV_LD / 256, 256>>>(bq, bk, bv, p_bqkv);
    ln_kernel<<<NTOK, 256>>>(x, ln1g, ln1b, p_h);
    // QKV projection (fp16 in/out)
    gemm_f16<0,0,1><<<dim3(QKV_LD / BN, NTOK / BM), 256, GEMM_SMEM_BYTES>>>(
        p_h, p_wt, p_bqkv, nullptr, p_qkv, QKV_LD, DIMV);
    attn_kernel<<<dim3(SEQ / 64, 64), 128, ATTN_SMEM_B>>>(p_qkv, p_o);
    add_dln_kernel<<<NTOK, 256>>>(x, p_o, ln2g, ln2b, fclg, fclb, p_x2, p_h2);
    gemm_f16<1,0,1><<<dim3(HIDV / BN, NTOK / BM), 256, GEMM_SMEM_BYTES>>>(
        p_h2, p_w1t, b1, nullptr, p_mid, HIDV, DIMV);
    gemm_f16<1,1,0><<<dim3(DIMV / BN, NTOK / BM), 256, GEMM_SMEM_BYTES>>>(
        p_mid, p_w2t, b2, p_x2, out, DIMV, HIDV);
}